// round 12
// baseline (speedup 1.0000x reference)
#include <cuda_runtime.h>
#include <math.h>

// Problem constants
#define BB 8
#define HH 256
#define WW 256
#define CC 64
#define NKY 8
#define NKX 16

typedef unsigned long long u64;

// ---------------- scratch (static device memory; no allocations) ------------
__device__ float g_h[BB*HH*CC*WW];        // h field, layout [b][u][c][v]  (128MB)
__device__ float g_Y[BB*NKY*HH*CC*2];     // stage-1 DFT  [b][ky][u][c][re,im]
__device__ float g_F[BB*NKY*NKX*CC*2];    // modes        [b][ky][s][c][re,im]
__device__ float g_OF[BB*NKY*NKX*CC*2];   // mixed modes  (same layout)
__device__ float g_G[BB*NKY*HH*CC*2];     // inverse stage [b][ky][u][o][re,im]
__device__ float g_Wl2[256*64];           // lift_w2 transposed [k][o]
__device__ float g_Wp1[64*128];           // proj_w1 transposed [k][o]
__device__ float g_Wfsk[4*64*64];         // fno skip, [l][i][o]
__device__ float g_Wf1[4*64*32];          // mlp w1,   [l][i][j]
__device__ float g_Wf2[4*32*64];          // mlp w2,   [l][j][o]

// ---- gelu via hardware tanh (1 MUFU op) ------------------------------------
__device__ __forceinline__ float gelu_f(float x){
    float x2 = x*x;
    float inner = fmaf(fmaf(0.0356774081f, x2, 0.7978845608f), x, 0.0f);
    float t;
    asm("tanh.approx.f32 %0,%1;" : "=f"(t) : "f"(inner));
    return 0.5f*x*(1.0f + t);
}

// ---- packed fp32x2 helpers --------------------------------------------------
__device__ __forceinline__ u64 pk2(float lo, float hi){
    u64 r; asm("mov.b64 %0,{%1,%2};" : "=l"(r) : "f"(lo), "f"(hi)); return r;
}
__device__ __forceinline__ void upk2(u64 v, float& lo, float& hi){
    asm("mov.b64 {%0,%1},%2;" : "=f"(lo), "=f"(hi) : "l"(v));
}
__device__ __forceinline__ u64 ffma2(u64 a, u64 b, u64 c){
    u64 r; asm("fma.rn.f32x2 %0,%1,%2,%3;" : "=l"(r) : "l"(a), "l"(b), "l"(c)); return r;
}

// ---------------- one-time (per launch) weight transposes --------------------
__global__ void k_reorder(const float* __restrict__ lw2, const float* __restrict__ pw1,
                          const float* __restrict__ skw, const float* __restrict__ mw1,
                          const float* __restrict__ mw2){
    int e = blockIdx.x*256 + threadIdx.x;
    if (e < 16384){ int k = e>>6, o = e&63;  g_Wl2[e] = lw2[o*256+k]; }
    else if (e < 24576){ int i = e-16384; int k = i>>7, o = i&127; g_Wp1[i] = pw1[o*64+k]; }
    else if (e < 40960){ int i = e-24576; int l = i>>12; int r = i&4095;
                         int ii = r>>6, o = r&63; g_Wfsk[i] = skw[l*4096 + o*64 + ii]; }
    else if (e < 49152){ int i = e-40960; int l = i>>11; int r = i&2047;
                         int ii = r>>5, j = r&31;  g_Wf1[i] = mw1[l*2048 + j*64 + ii]; }
    else if (e < 57344){ int i = e-49152; int l = i>>11; int r = i&2047;
                         int j = r>>6, o = r&63;   g_Wf2[i] = mw2[l*2048 + o*32 + j]; }
}

// ---------------- lifting: x(3) -> 256 -> gelu -> 64 ------------------------
__global__ __launch_bounds__(256,2) void k_lift(const float* __restrict__ x,
                       const float* __restrict__ w1, const float* __restrict__ b1,
                       const float* __restrict__ b2){
    extern __shared__ float sm[];
    float* t1  = sm;               // 128*130 = 16640
    float* w2h = t1 + 16640;       // 8192  [kk][o]
    float* w1s = w2h + 8192;       // 768
    float* b1s = w1s + 768;        // 256
    float* b2s = b1s + 256;        // 64
    float* xs  = b2s + 64;         // 3*128
    int tid = threadIdx.x;
    int blk = blockIdx.x;
    int q = blk & 1, u = (blk>>1) & 255, b = blk >> 9;

    for (int i = tid; i < 768; i += 256) w1s[i] = w1[i];
    if (tid < 256) b1s[tid] = b1[tid];
    if (tid < 64)  b2s[tid] = b2[tid];
    for (int i = tid; i < 3*128; i += 256){
        int c = i>>7, v = i&127;
        xs[i] = x[((b*3+c)*256+u)*256 + q*128 + v];
    }
    __syncthreads();

    int pxg = tid & 63, chg = tid >> 6;
    int o0 = chg*16;
    u64 acc[8][2];
    #pragma unroll
    for (int o2 = 0; o2 < 8; o2++){
        u64 ini = pk2(b2s[o0+2*o2], b2s[o0+2*o2+1]);
        acc[o2][0] = ini; acc[o2][1] = ini;
    }

    for (int p = 0; p < 2; p++){
        for (int i = tid; i < 2048; i += 256)
            ((float4*)w2h)[i] = ((const float4*)(g_Wl2 + p*8192))[i];
        for (int it = tid; it < 16384; it += 256){
            int kk = it >> 7, vx = it & 127;
            int c = p*128 + kk;
            float s = fmaf(w1s[c*3+0], xs[vx],
                      fmaf(w1s[c*3+1], xs[128+vx],
                      fmaf(w1s[c*3+2], xs[256+vx], b1s[c])));
            t1[kk*130+vx] = gelu_f(s);
        }
        __syncthreads();
        #pragma unroll 4
        for (int kk = 0; kk < 128; kk++){
            float2 tv = *(const float2*)&t1[kk*130 + pxg*2];
            u64 t20 = pk2(tv.x, tv.x), t21 = pk2(tv.y, tv.y);
            const ulonglong2* wp = (const ulonglong2*)&w2h[kk*64 + o0];
            #pragma unroll
            for (int qq = 0; qq < 4; qq++){
                ulonglong2 w = wp[qq];
                acc[2*qq][0]   = ffma2(t20, w.x, acc[2*qq][0]);
                acc[2*qq][1]   = ffma2(t21, w.x, acc[2*qq][1]);
                acc[2*qq+1][0] = ffma2(t20, w.y, acc[2*qq+1][0]);
                acc[2*qq+1][1] = ffma2(t21, w.y, acc[2*qq+1][1]);
            }
        }
        __syncthreads();
    }
    float* outrow = g_h + (size_t)((b*256+u)*64)*256 + q*128;
    #pragma unroll
    for (int o2 = 0; o2 < 8; o2++){
        float e0, d0, e1, d1;
        upk2(acc[o2][0], e0, d0);
        upk2(acc[o2][1], e1, d1);
        *(float2*)&outrow[(o0+2*o2)*256   + pxg*2] = make_float2(e0, e1);
        *(float2*)&outrow[(o0+2*o2+1)*256 + pxg*2] = make_float2(d0, d1);
    }
}

// ---------------- DFT stage 1 (over v): runs ONCE after lift -----------------
__global__ __launch_bounds__(256) void k_dft1(){
    extern __shared__ float sm[];
    float* hs  = sm;            // 64*260 = 16640
    float* tw8 = hs + 16640;    // 4096 = 2048 u64: [ky][v] e^{+2pi i ky v/256}
    float* red = tw8 + 4096;    // 4096
    int tid = threadIdx.x;
    int u = blockIdx.x & 255, b = blockIdx.x >> 8;
    const float* row = g_h + (size_t)(b*256+u)*64*256;
    const float4* rw4 = (const float4*)row;
    for (int i = tid; i < 4096; i += 256){
        int c = i>>6, v4 = i&63;
        *(float4*)&hs[c*260 + v4*4] = rw4[i];
    }
    {   // row ky=1 is the base table
        float ss, sc;
        sincospif((float)tid*(1.0f/128.0f), &ss, &sc);
        tw8[(256+tid)*2] = sc; tw8[(256+tid)*2+1] = ss;
    }
    __syncthreads();
    {
        u64* t8u = (u64*)tw8;
        const u64* basew = (const u64*)tw8 + 256;
        #pragma unroll
        for (int r = 0; r < 8; r++){
            int e = tid + r*256;
            int ky = e >> 8, v = e & 255;
            if (ky != 1) t8u[e] = basew[(ky*v)&255];
        }
    }
    __syncthreads();
    int c = tid & 63, qd = tid >> 6;
    const u64* t8 = (const u64*)tw8;
    u64 a[8];
    #pragma unroll
    for (int k = 0; k < 8; k++) a[k] = pk2(0.f, 0.f);
    const float* hc = &hs[c*260 + qd*64];
    int vb = qd*64;
    for (int vv = 0; vv < 64; vv += 4){
        float4 xv = *(const float4*)&hc[vv];
        u64 x0 = pk2(xv.x,xv.x), x1 = pk2(xv.y,xv.y);
        u64 x2 = pk2(xv.z,xv.z), x3 = pk2(xv.w,xv.w);
        #pragma unroll
        for (int k = 0; k < 8; k++){
            const u64* tk = t8 + k*256 + vb + vv;
            a[k] = ffma2(x0, tk[0], a[k]);
            a[k] = ffma2(x1, tk[1], a[k]);
            a[k] = ffma2(x2, tk[2], a[k]);
            a[k] = ffma2(x3, tk[3], a[k]);
        }
    }
    #pragma unroll
    for (int k = 0; k < 8; k++){
        float sr, si; upk2(a[k], sr, si);
        *(float2*)&red[((qd*64+c)*8+k)*2] = make_float2(sr, si);
    }
    __syncthreads();
    const float scale = 1.0f/65536.0f;
    #pragma unroll
    for (int rep = 0; rep < 2; rep++){
        int idx = tid + rep*256;
        int ky = idx >> 6, cc = idx & 63;
        float sr = 0.f, si = 0.f;
        #pragma unroll
        for (int q2 = 0; q2 < 4; q2++){
            float2 t = *(const float2*)&red[((q2*64+cc)*8+ky)*2];
            sr += t.x; si += t.y;
        }
        float* o = g_Y + (size_t)(((b*8+ky)*256+u)*64 + cc)*2;
        o[0] = sr*scale; o[1] = -si*scale;   // conjugate: table is e^{+i}
    }
}

// ---------------- DFT stage 2 (over u): grid B*KY*KX = 1024 -----------------
__global__ __launch_bounds__(256) void k_dft2(){
    __shared__ float tc[256], tsp[256];
    __shared__ float red[4*64*2];
    int tid = threadIdx.x;
    int blk = blockIdx.x;
    int s = blk & 15, ky = (blk>>4) & 7, b = blk >> 7;
    int kxe = (s < 8) ? s : s - 16;
    {
        float ss, sc;
        sincospif((float)tid*(1.0f/128.0f), &ss, &sc);
        tc[tid] = sc; tsp[tid] = ss;
    }
    __syncthreads();
    int uc = tid >> 6, c = tid & 63;
    float sr = 0.f, si = 0.f;
    const float* Yb = g_Y + (size_t)((b*8+ky)*256)*128;
    int u0 = uc*64;
    int t = (kxe*u0) & 255;
    for (int uu = 0; uu < 64; uu++){
        float2 y = *(const float2*)(Yb + (u0+uu)*128 + c*2);
        float cc = tc[t], sv = tsp[t];
        t = (t + kxe) & 255;
        sr = fmaf(y.x, cc, fmaf( y.y, sv, sr));
        si = fmaf(y.y, cc, fmaf(-y.x, sv, si));
    }
    red[(uc*64+c)*2]   = sr;
    red[(uc*64+c)*2+1] = si;
    __syncthreads();
    if (tid < 64){
        float ar = red[tid*2]       + red[(64+tid)*2]
                 + red[(128+tid)*2] + red[(192+tid)*2];
        float ai = red[tid*2+1]       + red[(64+tid)*2+1]
                 + red[(128+tid)*2+1] + red[(192+tid)*2+1];
        float* o = g_F + (size_t)(((b*8+ky)*16+s)*64 + tid)*2;
        o[0] = ar; o[1] = ai;
    }
}

// ---------------- mode mixing: out[o] = sum_i F[i] * W[i][o] (complex) ------
__global__ __launch_bounds__(256) void k_mix(int l, const float* __restrict__ wr1,
                      const float* __restrict__ wi1, const float* __restrict__ wr2,
                      const float* __restrict__ wi2){
    __shared__ float Fs[8*64*2];
    __shared__ float Wm[64*64*2];
    int tid = threadIdx.x;
    int s = blockIdx.x >> 3, ky = blockIdx.x & 7;
    const float* wr = (s < 8) ? wr1 : wr2;
    const float* wi = (s < 8) ? wi1 : wi2;
    int kxh = s & 7;
    for (int i = tid; i < 8*64*2; i += 256){
        int b = i >> 7, r = i & 127;
        Fs[i] = g_F[(size_t)(((b*8+ky)*16+s)*64)*2 + r];
    }
    for (int i = tid; i < 4096; i += 256){
        int ii = i >> 6, o = i & 63;
        int src = (((l*64+ii)*64+o)*8 + kxh)*8 + ky;
        Wm[i*2]   = wr[src];
        Wm[i*2+1] = wi[src];
    }
    __syncthreads();
    #pragma unroll
    for (int p = 0; p < 2; p++){
        int gid = tid + p*256;
        int b = gid >> 6, o = gid & 63;
        float ar = 0.f, ai = 0.f;
        const float2* fp = (const float2*)&Fs[b*128];
        const float2* wp = (const float2*)Wm;
        #pragma unroll 4
        for (int i2 = 0; i2 < 64; i2++){
            float2 f = fp[i2];
            float2 w = wp[i2*64 + o];
            ar = fmaf(f.x, w.x, fmaf(-f.y, w.y, ar));
            ai = fmaf(f.x, w.y, fmaf( f.y, w.x, ai));
        }
        float* ot = g_OF + (size_t)(((b*8+ky)*16+s)*64 + o)*2;
        ot[0] = ar; ot[1] = ai;
    }
}

// ---------------- inverse over kx: grid B*KY*8 = 512 -------------------------
__global__ __launch_bounds__(256) void k_idft1(){
    __shared__ float OFs[16*64*2];
    int tid = threadIdx.x;
    int blk = blockIdx.x;
    int uq = blk & 7, ky = (blk>>3) & 7, b = blk >> 6;
    for (int i = tid; i < 2048; i += 256)
        OFs[i] = g_OF[(size_t)((b*8+ky)*16*64)*2 + i];
    __syncthreads();
    int u = uq*32 + (tid & 31);
    int og = tid >> 5, o0 = og*8;
    float ar[8], ai[8];
    #pragma unroll
    for (int j = 0; j < 8; j++){ ar[j] = 0.f; ai[j] = 0.f; }
    for (int s = 0; s < 16; s++){
        int kxe = (s < 8) ? s : s - 16;
        float ss, sc;
        sincospif((float)(kxe*u)*(1.0f/128.0f), &ss, &sc);
        const float2* op = (const float2*)&OFs[(s*64+o0)*2];
        #pragma unroll
        for (int j = 0; j < 8; j++){
            float2 f = op[j];
            ar[j] = fmaf(f.x, sc, fmaf(-f.y, ss, ar[j]));
            ai[j] = fmaf(f.x, ss, fmaf( f.y, sc, ai[j]));
        }
    }
    float* o = g_G + (size_t)(((b*8+ky)*256+u)*64 + o0)*2;
    #pragma unroll
    for (int j = 0; j < 8; j++){ o[j*2] = ar[j]; o[j*2+1] = ai[j]; }
}

// ---------------- fused per-row layer kernel --------------------------------
// 256 threads: thread = (4 px, 16 ch). Register-tiled GEMMs on f32x2.
__global__ __launch_bounds__(256,2) void k_fuse(int l, int do_dft,
        const float* __restrict__ gate_g, const float* __restrict__ specb_g,
        const float* __restrict__ b1_g, const float* __restrict__ b2_g){
    extern __shared__ float sm[];
    float* hs  = sm;              // 64*260 = 16640
    float* uni = hs + 16640;      // 5120: phase1 {wsk|Gr}, epilogue red
    float* w1  = uni + 5120;      // 2048 [i][j]   (epilogue: tw8 low half)
    float* w2  = w1 + 2048;       // 2048 [j][o]   (epilogue: tw8 high half)
    float* twi = w2 + 2048;       // 512 interleaved (cos,sin) of +2pi t/256
    float* gw  = twi + 512;       // 64
    float* sb  = gw + 64;         // 64
    float* b1s = sb + 64;         // 32
    float* b2s = b1s + 32;        // 64   -> total 26592 floats = 106368 B
    float* wsk = uni;             // phase-1 alias
    float* Grr = uni + 4096;      // 512 [ky][o] real
    float* Gri = uni + 4608;      // 512 [ky][o] imag
    float* red = uni;             // epilogue alias (4096)
    float* tw8 = w1;              // epilogue alias (4096 = 2048 u64)

    int tid = threadIdx.x;
    int u = blockIdx.x & 255, b = blockIdx.x >> 8;
    float* row = g_h + (size_t)(b*256+u)*64*256;

    {
        const float4* rw4 = (const float4*)row;
        for (int i = tid; i < 4096; i += 256){
            int c = i>>6, v4 = i&63;
            *(float4*)&hs[c*260 + v4*4] = rw4[i];
        }
    }
    for (int i = tid; i < 1024; i += 256) ((float4*)wsk)[i] = ((const float4*)(g_Wfsk + l*4096))[i];
    for (int i = tid; i < 512;  i += 256) ((float4*)w1)[i]  = ((const float4*)(g_Wf1  + l*2048))[i];
    for (int i = tid; i < 512;  i += 256) ((float4*)w2)[i]  = ((const float4*)(g_Wf2  + l*2048))[i];
    for (int i = tid; i < 512; i += 256){
        int ky = i>>6, o = i&63;
        float2 g = *(const float2*)&g_G[(size_t)(((b*8+ky)*256+u)*64 + o)*2];
        Grr[i] = g.x; Gri[i] = g.y;
    }
    {
        float ss, sc;
        sincospif((float)tid*(1.0f/128.0f), &ss, &sc);
        twi[tid*2] = sc; twi[tid*2+1] = ss;
    }
    if (tid < 64) gw[tid]  = gate_g[l*64+tid];
    if (tid < 64) sb[tid]  = specb_g[l*64+tid];
    if (tid < 32) b1s[tid] = b1_g[l*32+tid];
    if (tid < 64) b2s[tid] = b2_g[l*64+tid];
    __syncthreads();

    int pxg = tid & 63, chg = tid >> 6;
    int v0 = pxg*4, o0 = chg*16;

    // ---- phase 1: acc[8 ch-pairs][4 px] = spec_b + recomb + skip GEMM
    u64 acc[8][4];
    #pragma unroll
    for (int o2 = 0; o2 < 8; o2++){
        u64 ini = pk2(sb[o0+2*o2], sb[o0+2*o2+1]);
        #pragma unroll
        for (int p = 0; p < 4; p++) acc[o2][p] = ini;
    }
    #pragma unroll
    for (int ky = 0; ky < 8; ky++){
        float cw = (ky == 0) ? 1.0f : 2.0f;
        u64 cs2[4], nsn2[4];
        int idx = (ky*v0) & 255;
        #pragma unroll
        for (int p = 0; p < 4; p++){
            float cs = twi[idx*2]*cw, sn = twi[idx*2+1]*cw;
            cs2[p] = pk2(cs, cs); nsn2[p] = pk2(-sn, -sn);
            idx = (idx + ky) & 255;
        }
        const u64* rr = (const u64*)&Grr[ky*64 + o0];
        const u64* ri = (const u64*)&Gri[ky*64 + o0];
        #pragma unroll
        for (int o2 = 0; o2 < 8; o2++){
            u64 gr = rr[o2], gi = ri[o2];
            #pragma unroll
            for (int p = 0; p < 4; p++)
                acc[o2][p] = ffma2(gr, cs2[p], ffma2(gi, nsn2[p], acc[o2][p]));
        }
    }
    // gate contribution into registers while h_old is being read anyway
    u64 garr[8];
    #pragma unroll
    for (int o2 = 0; o2 < 8; o2++){
        float g0 = gw[o0+2*o2], g1 = gw[o0+2*o2+1];
        float B0 = b2s[o0+2*o2], B1 = b2s[o0+2*o2+1];
        // use first pixel later; compute per-pixel below instead
        garr[o2] = pk2(g0, g1); (void)B0; (void)B1;
    }
    u64 out[8][4];
    #pragma unroll
    for (int o2 = 0; o2 < 8; o2++){
        u64 ini = pk2(b2s[o0+2*o2], b2s[o0+2*o2+1]);
        #pragma unroll
        for (int p = 0; p < 4; p++) out[o2][p] = ini;
    }
    #pragma unroll 2
    for (int i = 0; i < 64; i++){
        float4 hv = *(const float4*)&hs[i*260 + v0];
        u64 h2[4] = {pk2(hv.x,hv.x), pk2(hv.y,hv.y), pk2(hv.z,hv.z), pk2(hv.w,hv.w)};
        const ulonglong2* wp = (const ulonglong2*)&wsk[i*64 + o0];
        #pragma unroll
        for (int qq = 0; qq < 4; qq++){
            ulonglong2 w = wp[qq];
            #pragma unroll
            for (int p = 0; p < 4; p++){
                acc[2*qq][p]   = ffma2(h2[p], w.x, acc[2*qq][p]);
                acc[2*qq+1][p] = ffma2(h2[p], w.y, acc[2*qq+1][p]);
            }
        }
    }
    // gate: out += gate * h_old  (h_old rows owned by this thread, from hs)
    #pragma unroll
    for (int o2 = 0; o2 < 8; o2++){
        float4 ha = *(const float4*)&hs[(o0+2*o2)*260   + v0];
        float4 hb = *(const float4*)&hs[(o0+2*o2+1)*260 + v0];
        out[o2][0] = ffma2(pk2(ha.x, hb.x), garr[o2], out[o2][0]);
        out[o2][1] = ffma2(pk2(ha.y, hb.y), garr[o2], out[o2][1]);
        out[o2][2] = ffma2(pk2(ha.z, hb.z), garr[o2], out[o2][2]);
        out[o2][3] = ffma2(pk2(ha.w, hb.w), garr[o2], out[o2][3]);
    }
    __syncthreads();   // all phase-1 reads of h_old (hs) done
    #pragma unroll
    for (int o2 = 0; o2 < 8; o2++){
        float lo[4], hi[4];
        #pragma unroll
        for (int p = 0; p < 4; p++) upk2(acc[o2][p], lo[p], hi[p]);
        float4 r0, r1;
        r0.x = gelu_f(lo[0]); r0.y = gelu_f(lo[1]); r0.z = gelu_f(lo[2]); r0.w = gelu_f(lo[3]);
        r1.x = gelu_f(hi[0]); r1.y = gelu_f(hi[1]); r1.z = gelu_f(hi[2]); r1.w = gelu_f(hi[3]);
        *(float4*)&hs[(o0+2*o2)*260   + v0] = r0;
        *(float4*)&hs[(o0+2*o2+1)*260 + v0] = r1;
    }
    __syncthreads();

    // ---- phase 2 (single pass): m-channels jb..jb+7 over one t-scan
    int jb = chg*8;
    u64 m2[4][4];
    #pragma unroll
    for (int qq = 0; qq < 4; qq++){
        u64 ini = pk2(b1s[jb+2*qq], b1s[jb+2*qq+1]);
        #pragma unroll
        for (int p = 0; p < 4; p++) m2[qq][p] = ini;
    }
    #pragma unroll 2
    for (int i = 0; i < 64; i++){
        float4 tv = *(const float4*)&hs[i*260 + v0];
        u64 t2[4] = {pk2(tv.x,tv.x), pk2(tv.y,tv.y), pk2(tv.z,tv.z), pk2(tv.w,tv.w)};
        const ulonglong2* wp = (const ulonglong2*)&w1[i*32 + jb];
        ulonglong2 wa = wp[0], wb = wp[1];
        #pragma unroll
        for (int p = 0; p < 4; p++){
            m2[0][p] = ffma2(t2[p], wa.x, m2[0][p]);
            m2[1][p] = ffma2(t2[p], wa.y, m2[1][p]);
            m2[2][p] = ffma2(t2[p], wb.x, m2[2][p]);
            m2[3][p] = ffma2(t2[p], wb.y, m2[3][p]);
        }
    }
    __syncthreads();   // all t-reads done; hs rows 0..31 now reusable for m
    #pragma unroll
    for (int qq = 0; qq < 4; qq++){
        float lo[4], hi[4];
        #pragma unroll
        for (int p = 0; p < 4; p++) upk2(m2[qq][p], lo[p], hi[p]);
        float4 r0, r1;
        r0.x = gelu_f(lo[0]); r0.y = gelu_f(lo[1]); r0.z = gelu_f(lo[2]); r0.w = gelu_f(lo[3]);
        r1.x = gelu_f(hi[0]); r1.y = gelu_f(hi[1]); r1.z = gelu_f(hi[2]); r1.w = gelu_f(hi[3]);
        *(float4*)&hs[(jb+2*qq)*260   + v0] = r0;
        *(float4*)&hs[(jb+2*qq+1)*260 + v0] = r1;
    }
    __syncthreads();

    // ---- phase 3: single 32-j pass reading m from hs rows 0..31
    #pragma unroll 2
    for (int j = 0; j < 32; j++){
        float4 mv = *(const float4*)&hs[j*260 + v0];
        u64 mvp[4] = {pk2(mv.x,mv.x), pk2(mv.y,mv.y), pk2(mv.z,mv.z), pk2(mv.w,mv.w)};
        const ulonglong2* wp = (const ulonglong2*)&w2[j*64 + o0];
        #pragma unroll
        for (int qq = 0; qq < 4; qq++){
            ulonglong2 w = wp[qq];
            #pragma unroll
            for (int p = 0; p < 4; p++){
                out[2*qq][p]   = ffma2(mvp[p], w.x, out[2*qq][p]);
                out[2*qq+1][p] = ffma2(mvp[p], w.y, out[2*qq+1][p]);
            }
        }
    }
    __syncthreads();   // all m-reads done; hs now reusable for h_new

    bool dog = (l < 3);
    #pragma unroll
    for (int o2 = 0; o2 < 8; o2++){
        float lo[4], hi[4];
        #pragma unroll
        for (int p = 0; p < 4; p++) upk2(out[o2][p], lo[p], hi[p]);
        if (dog){
            #pragma unroll
            for (int p = 0; p < 4; p++){ lo[p] = gelu_f(lo[p]); hi[p] = gelu_f(hi[p]); }
        }
        float4 r0, r1;
        r0.x = lo[0]; r0.y = lo[1]; r0.z = lo[2]; r0.w = lo[3];
        r1.x = hi[0]; r1.y = hi[1]; r1.z = hi[2]; r1.w = hi[3];
        *(float4*)&hs[(o0+2*o2)*260   + v0] = r0;
        *(float4*)&hs[(o0+2*o2+1)*260 + v0] = r1;
        *(float4*)&row[(o0+2*o2)*256   + v0] = r0;
        *(float4*)&row[(o0+2*o2+1)*256 + v0] = r1;
    }

    // ---- epilogue: stage-1 DFT of h_new; per-ky sequential twiddle tables
    if (do_dft){
        __syncthreads();   // hs complete everywhere; w1/w2 regions now dead
        {   // build tw8[ky][v] (u64) in the dead w1+w2 region from twi
            u64* t8u = (u64*)tw8;
            const u64* twb = (const u64*)twi;
            #pragma unroll
            for (int r = 0; r < 8; r++){
                int e = tid + r*256;
                int ky = e >> 8, v = e & 255;
                t8u[e] = twb[(ky*v)&255];
            }
        }
        __syncthreads();
        int c = tid & 63, qd = tid >> 6;
        const u64* t8 = (const u64*)tw8;
        u64 a[8];
        #pragma unroll
        for (int k = 0; k < 8; k++) a[k] = pk2(0.f, 0.f);
        const float* hc = &hs[c*260 + qd*64];
        int vb = qd*64;
        for (int vv = 0; vv < 64; vv += 4){
            float4 xv = *(const float4*)&hc[vv];
            u64 x0 = pk2(xv.x,xv.x), x1 = pk2(xv.y,xv.y);
            u64 x2 = pk2(xv.z,xv.z), x3 = pk2(xv.w,xv.w);
            #pragma unroll
            for (int k = 0; k < 8; k++){
                const u64* tk = t8 + k*256 + vb + vv;
                a[k] = ffma2(x0, tk[0], a[k]);
                a[k] = ffma2(x1, tk[1], a[k]);
                a[k] = ffma2(x2, tk[2], a[k]);
                a[k] = ffma2(x3, tk[3], a[k]);
            }
        }
        #pragma unroll
        for (int k = 0; k < 8; k++){
            float sr, si; upk2(a[k], sr, si);
            *(float2*)&red[((qd*64+c)*8+k)*2] = make_float2(sr, si);
        }
        __syncthreads();
        const float scale = 1.0f/65536.0f;
        #pragma unroll
        for (int rep = 0; rep < 2; rep++){
            int idx = tid + rep*256;
            int ky = idx >> 6, cc = idx & 63;
            float sr = 0.f, si = 0.f;
            #pragma unroll
            for (int q2 = 0; q2 < 4; q2++){
                float2 t = *(const float2*)&red[((q2*64+cc)*8+ky)*2];
                sr += t.x; si += t.y;
            }
            float* o = g_Y + (size_t)(((b*8+ky)*256+u)*64 + cc)*2;
            o[0] = sr*scale; o[1] = -si*scale;   // tw8 is e^{+i}, conjugate here
        }
    }
}

// ---------------- projection: 64 -> 128 -> gelu -> 3, + input residual ------
__global__ __launch_bounds__(256,2) void k_proj(const float* __restrict__ x,
                      const float* __restrict__ b1g, const float* __restrict__ w2g,
                      const float* __restrict__ b2g, float* __restrict__ out){
    extern __shared__ float sm[];
    float* hsp = sm;            // 64*68 = 4352
    float* t2p = hsp + 4352;    // 64*132 = 8448  pair-packed: [j2][px][2]
    float* w1s = t2p + 8448;    // 64*128 [k][o]
    float* b1s = w1s + 8192;    // 128
    int tid = threadIdx.x;
    int blk = blockIdx.x;
    int q = blk & 3, u = (blk>>2) & 255, b = blk >> 10;
    const float* row = g_h + (size_t)(b*256+u)*64*256 + q*64;
    for (int i = tid; i < 1024; i += 256){
        int c = i>>4, v4 = i&15;
        *(float4*)&hsp[c*68 + v4*4] = *(const float4*)&row[c*256 + v4*4];
    }
    for (int i = tid; i < 2048; i += 256) ((float4*)w1s)[i] = ((const float4*)g_Wp1)[i];
    if (tid < 128) b1s[tid] = b1g[tid];
    __syncthreads();
    {
        int pxg = tid & 31, chg = tid >> 5;
        int o0 = chg*16;
        u64 a[8][2];
        #pragma unroll
        for (int o2 = 0; o2 < 8; o2++){
            u64 ini = pk2(b1s[o0+2*o2], b1s[o0+2*o2+1]);
            a[o2][0] = ini; a[o2][1] = ini;
        }
        #pragma unroll 4
        for (int k = 0; k < 64; k++){
            float2 tv = *(const float2*)&hsp[k*68 + pxg*2];
            u64 t20 = pk2(tv.x, tv.x), t21 = pk2(tv.y, tv.y);
            const ulonglong2* wp = (const ulonglong2*)&w1s[k*128 + o0];
            #pragma unroll
            for (int qq = 0; qq < 4; qq++){
                ulonglong2 w = wp[qq];
                a[2*qq][0]   = ffma2(t20, w.x, a[2*qq][0]);
                a[2*qq][1]   = ffma2(t21, w.x, a[2*qq][1]);
                a[2*qq+1][0] = ffma2(t20, w.y, a[2*qq+1][0]);
                a[2*qq+1][1] = ffma2(t21, w.y, a[2*qq+1][1]);
            }
        }
        // pair-packed store: t2p[(o>>1)*132 + px*2 + (o&1)]
        #pragma unroll
        for (int o2 = 0; o2 < 8; o2++){
            float e0, d0, e1, d1;
            upk2(a[o2][0], e0, d0);
            upk2(a[o2][1], e1, d1);
            int j2 = (o0>>1) + o2;
            float* tp = &t2p[j2*132 + pxg*4];
            tp[0] = gelu_f(e0); tp[1] = gelu_f(d0);
            tp[2] = gelu_f(e1); tp[3] = gelu_f(d1);
        }
    }
    __syncthreads();
    if (tid < 192){
        int c = tid >> 6, vv = tid & 63;
        u64 a2 = pk2(0.f, 0.f);
        const u64* wg = (const u64*)(w2g + c*128);
        #pragma unroll 4
        for (int j2 = 0; j2 < 64; j2++){
            u64 tv = *(const u64*)&t2p[j2*132 + vv*2];
            a2 = ffma2(tv, wg[j2], a2);
        }
        float s0, s1; upk2(a2, s0, s1);
        size_t gi = (size_t)((b*3+c)*256+u)*256 + q*64 + vv;
        out[gi] = s0 + s1 + b2g[c] + x[gi];
    }
}

// ---------------- host launch ------------------------------------------------
extern "C" void kernel_launch(void* const* d_in, const int* in_sizes, int n_in,
                              void* d_out, int out_size){
    (void)in_sizes; (void)n_in; (void)out_size;
    const float* x       = (const float*)d_in[0];
    const float* lift_w1 = (const float*)d_in[1];
    const float* lift_b1 = (const float*)d_in[2];
    const float* lift_w2 = (const float*)d_in[3];
    const float* lift_b2 = (const float*)d_in[4];
    const float* swr1    = (const float*)d_in[5];
    const float* swi1    = (const float*)d_in[6];
    const float* swr2    = (const float*)d_in[7];
    const float* swi2    = (const float*)d_in[8];
    const float* spec_b  = (const float*)d_in[9];
    const float* skw     = (const float*)d_in[10];
    const float* gate    = (const float*)d_in[11];
    const float* mw1     = (const float*)d_in[12];
    const float* mb1     = (const float*)d_in[13];
    const float* mw2     = (const float*)d_in[14];
    const float* mb2     = (const float*)d_in[15];
    const float* pw1     = (const float*)d_in[16];
    const float* pb1     = (const float*)d_in[17];
    const float* pw2     = (const float*)d_in[18];
    const float* pb2     = (const float*)d_in[19];
    float* out = (float*)d_out;

    const int SM_LIFT = (16640 + 8192 + 768 + 256 + 64 + 384) * 4;   // 105216
    const int SM_DFT1 = (16640 + 4096 + 4096) * 4;                    // 99328
    const int SM_FUSE = 26592 * 4;                                    // 106368
    const int SM_PROJ = (4352 + 8448 + 8192 + 128) * 4;               // 84480

    cudaFuncSetAttribute(k_lift, cudaFuncAttributeMaxDynamicSharedMemorySize, SM_LIFT);
    cudaFuncSetAttribute(k_dft1, cudaFuncAttributeMaxDynamicSharedMemorySize, SM_DFT1);
    cudaFuncSetAttribute(k_fuse, cudaFuncAttributeMaxDynamicSharedMemorySize, SM_FUSE);
    cudaFuncSetAttribute(k_proj, cudaFuncAttributeMaxDynamicSharedMemorySize, SM_PROJ);

    k_reorder<<<224, 256>>>(lift_w2, pw1, skw, mw1, mw2);
    k_lift<<<BB*HH*2, 256, SM_LIFT>>>(x, lift_w1, lift_b1, lift_b2);
    k_dft1<<<BB*HH, 256, SM_DFT1>>>();           // once, after lift
    for (int l = 0; l < 4; l++){
        k_dft2 <<<BB*NKY*NKX, 256>>>();
        k_mix  <<<NKX*NKY, 256>>>(l, swr1, swi1, swr2, swi2);
        k_idft1<<<BB*NKY*8, 256>>>();
        k_fuse <<<BB*HH, 256, SM_FUSE>>>(l, (l < 3) ? 1 : 0,
                                         gate, spec_b, mb1, mb2);
    }
    k_proj<<<BB*HH*4, 256, SM_PROJ>>>(x, pb1, pw2, pb2, out);
}

// round 13
// speedup vs baseline: 1.0636x; 1.0636x over previous
#include <cuda_runtime.h>
#include <math.h>

// Problem constants
#define BB 8
#define HH 256
#define WW 256
#define CC 64
#define NKY 8
#define NKX 16

typedef unsigned long long u64;

// ---------------- scratch (static device memory; no allocations) ------------
__device__ float g_h[BB*HH*CC*WW];        // h field, layout [b][u][c][v]  (128MB)
__device__ float g_Y[BB*NKY*HH*CC*2];     // stage-1 DFT  [b][ky][u][c][re,im]
__device__ float g_F[BB*NKY*NKX*CC*2];    // modes        [b][ky][s][c][re,im]
__device__ float g_OF[BB*NKY*NKX*CC*2];   // mixed modes  (same layout)
__device__ float g_G[BB*NKY*HH*CC*2];     // inverse stage [b][ky][u][o][re,im]
__device__ float g_Wl2[256*64];           // lift_w2 transposed [k][o]
__device__ float g_Wp1[64*128];           // proj_w1 transposed [k][o]
__device__ float g_Wfsk[4*64*64];         // fno skip, [l][i][o]
__device__ float g_Wf1[4*64*32];          // mlp w1,   [l][i][j]
__device__ float g_Wf2[4*32*64];          // mlp w2,   [l][j][o]

// ---- gelu via hardware tanh (1 MUFU op) ------------------------------------
__device__ __forceinline__ float gelu_f(float x){
    float x2 = x*x;
    float inner = fmaf(fmaf(0.0356774081f, x2, 0.7978845608f), x, 0.0f);
    float t;
    asm("tanh.approx.f32 %0,%1;" : "=f"(t) : "f"(inner));
    return 0.5f*x*(1.0f + t);
}

// ---- packed fp32x2 helpers --------------------------------------------------
__device__ __forceinline__ u64 pk2(float lo, float hi){
    u64 r; asm("mov.b64 %0,{%1,%2};" : "=l"(r) : "f"(lo), "f"(hi)); return r;
}
__device__ __forceinline__ void upk2(u64 v, float& lo, float& hi){
    asm("mov.b64 {%0,%1},%2;" : "=f"(lo), "=f"(hi) : "l"(v));
}
__device__ __forceinline__ u64 ffma2(u64 a, u64 b, u64 c){
    u64 r; asm("fma.rn.f32x2 %0,%1,%2,%3;" : "=l"(r) : "l"(a), "l"(b), "l"(c)); return r;
}

// ---------------- one-time (per launch) weight transposes --------------------
__global__ void k_reorder(const float* __restrict__ lw2, const float* __restrict__ pw1,
                          const float* __restrict__ skw, const float* __restrict__ mw1,
                          const float* __restrict__ mw2){
    int e = blockIdx.x*256 + threadIdx.x;
    if (e < 16384){ int k = e>>6, o = e&63;  g_Wl2[e] = lw2[o*256+k]; }
    else if (e < 24576){ int i = e-16384; int k = i>>7, o = i&127; g_Wp1[i] = pw1[o*64+k]; }
    else if (e < 40960){ int i = e-24576; int l = i>>12; int r = i&4095;
                         int ii = r>>6, o = r&63; g_Wfsk[i] = skw[l*4096 + o*64 + ii]; }
    else if (e < 49152){ int i = e-40960; int l = i>>11; int r = i&2047;
                         int ii = r>>5, j = r&31;  g_Wf1[i] = mw1[l*2048 + j*64 + ii]; }
    else if (e < 57344){ int i = e-49152; int l = i>>11; int r = i&2047;
                         int j = r>>6, o = r&63;   g_Wf2[i] = mw2[l*2048 + o*32 + j]; }
}

// ---------------- lifting: x(3) -> 256 -> gelu -> 64 ------------------------
__global__ __launch_bounds__(256,2) void k_lift(const float* __restrict__ x,
                       const float* __restrict__ w1, const float* __restrict__ b1,
                       const float* __restrict__ b2){
    extern __shared__ float sm[];
    float* t1  = sm;               // 128*130 = 16640
    float* w2h = t1 + 16640;       // 8192  [kk][o]
    float* w1s = w2h + 8192;       // 768
    float* b1s = w1s + 768;        // 256
    float* b2s = b1s + 256;        // 64
    float* xs  = b2s + 64;         // 3*128
    int tid = threadIdx.x;
    int blk = blockIdx.x;
    int q = blk & 1, u = (blk>>1) & 255, b = blk >> 9;

    for (int i = tid; i < 768; i += 256) w1s[i] = w1[i];
    if (tid < 256) b1s[tid] = b1[tid];
    if (tid < 64)  b2s[tid] = b2[tid];
    for (int i = tid; i < 3*128; i += 256){
        int c = i>>7, v = i&127;
        xs[i] = x[((b*3+c)*256+u)*256 + q*128 + v];
    }
    __syncthreads();

    int pxg = tid & 63, chg = tid >> 6;
    int o0 = chg*16;
    u64 acc[8][2];
    #pragma unroll
    for (int o2 = 0; o2 < 8; o2++){
        u64 ini = pk2(b2s[o0+2*o2], b2s[o0+2*o2+1]);
        acc[o2][0] = ini; acc[o2][1] = ini;
    }

    for (int p = 0; p < 2; p++){
        for (int i = tid; i < 2048; i += 256)
            ((float4*)w2h)[i] = ((const float4*)(g_Wl2 + p*8192))[i];
        for (int it = tid; it < 16384; it += 256){
            int kk = it >> 7, vx = it & 127;
            int c = p*128 + kk;
            float s = fmaf(w1s[c*3+0], xs[vx],
                      fmaf(w1s[c*3+1], xs[128+vx],
                      fmaf(w1s[c*3+2], xs[256+vx], b1s[c])));
            t1[kk*130+vx] = gelu_f(s);
        }
        __syncthreads();
        for (int kk = 0; kk < 128; kk++){
            float2 tv = *(const float2*)&t1[kk*130 + pxg*2];
            u64 t20 = pk2(tv.x, tv.x), t21 = pk2(tv.y, tv.y);
            const ulonglong2* wp = (const ulonglong2*)&w2h[kk*64 + o0];
            #pragma unroll
            for (int qq = 0; qq < 4; qq++){
                ulonglong2 w = wp[qq];
                acc[2*qq][0]   = ffma2(t20, w.x, acc[2*qq][0]);
                acc[2*qq][1]   = ffma2(t21, w.x, acc[2*qq][1]);
                acc[2*qq+1][0] = ffma2(t20, w.y, acc[2*qq+1][0]);
                acc[2*qq+1][1] = ffma2(t21, w.y, acc[2*qq+1][1]);
            }
        }
        __syncthreads();
    }
    float* outrow = g_h + (size_t)((b*256+u)*64)*256 + q*128;
    #pragma unroll
    for (int o2 = 0; o2 < 8; o2++){
        float e0, d0, e1, d1;
        upk2(acc[o2][0], e0, d0);
        upk2(acc[o2][1], e1, d1);
        *(float2*)&outrow[(o0+2*o2)*256   + pxg*2] = make_float2(e0, e1);
        *(float2*)&outrow[(o0+2*o2+1)*256 + pxg*2] = make_float2(d0, d1);
    }
}

// ---------------- DFT stage 1 (over v): runs ONCE after lift -----------------
__global__ __launch_bounds__(256) void k_dft1(){
    extern __shared__ float sm[];
    float* hs  = sm;            // 64*260 = 16640
    float* tw8 = hs + 16640;    // 4096 = 2048 u64: [ky][v] e^{+2pi i ky v/256}
    float* red = tw8 + 4096;    // 4096
    int tid = threadIdx.x;
    int u = blockIdx.x & 255, b = blockIdx.x >> 8;
    const float* row = g_h + (size_t)(b*256+u)*64*256;
    const float4* rw4 = (const float4*)row;
    for (int i = tid; i < 4096; i += 256){
        int c = i>>6, v4 = i&63;
        *(float4*)&hs[c*260 + v4*4] = rw4[i];
    }
    {   // row ky=1 is the base table
        float ss, sc;
        sincospif((float)tid*(1.0f/128.0f), &ss, &sc);
        tw8[(256+tid)*2] = sc; tw8[(256+tid)*2+1] = ss;
    }
    __syncthreads();
    {
        u64* t8u = (u64*)tw8;
        const u64* basew = (const u64*)tw8 + 256;
        #pragma unroll
        for (int r = 0; r < 8; r++){
            int e = tid + r*256;
            int ky = e >> 8, v = e & 255;
            if (ky != 1) t8u[e] = basew[(ky*v)&255];
        }
    }
    __syncthreads();
    int c = tid & 63, qd = tid >> 6;
    const u64* t8 = (const u64*)tw8;
    u64 a[8];
    #pragma unroll
    for (int k = 0; k < 8; k++) a[k] = pk2(0.f, 0.f);
    const float* hc = &hs[c*260 + qd*64];
    int vb = qd*64;
    for (int vv = 0; vv < 64; vv += 4){
        float4 xv = *(const float4*)&hc[vv];
        u64 x0 = pk2(xv.x,xv.x), x1 = pk2(xv.y,xv.y);
        u64 x2 = pk2(xv.z,xv.z), x3 = pk2(xv.w,xv.w);
        #pragma unroll
        for (int k = 0; k < 8; k++){
            const u64* tk = t8 + k*256 + vb + vv;
            a[k] = ffma2(x0, tk[0], a[k]);
            a[k] = ffma2(x1, tk[1], a[k]);
            a[k] = ffma2(x2, tk[2], a[k]);
            a[k] = ffma2(x3, tk[3], a[k]);
        }
    }
    #pragma unroll
    for (int k = 0; k < 8; k++){
        float sr, si; upk2(a[k], sr, si);
        *(float2*)&red[((qd*64+c)*8+k)*2] = make_float2(sr, si);
    }
    __syncthreads();
    const float scale = 1.0f/65536.0f;
    #pragma unroll
    for (int rep = 0; rep < 2; rep++){
        int idx = tid + rep*256;
        int ky = idx >> 6, cc = idx & 63;
        float sr = 0.f, si = 0.f;
        #pragma unroll
        for (int q2 = 0; q2 < 4; q2++){
            float2 t = *(const float2*)&red[((q2*64+cc)*8+ky)*2];
            sr += t.x; si += t.y;
        }
        float* o = g_Y + (size_t)(((b*8+ky)*256+u)*64 + cc)*2;
        o[0] = sr*scale; o[1] = -si*scale;   // conjugate: table is e^{+i}
    }
}

// ---------------- DFT stage 2 (over u): grid B*KY*KX = 1024 -----------------
__global__ __launch_bounds__(256) void k_dft2(){
    __shared__ float tc[256], tsp[256];
    __shared__ float red[4*64*2];
    int tid = threadIdx.x;
    int blk = blockIdx.x;
    int s = blk & 15, ky = (blk>>4) & 7, b = blk >> 7;
    int kxe = (s < 8) ? s : s - 16;
    {
        float ss, sc;
        sincospif((float)tid*(1.0f/128.0f), &ss, &sc);
        tc[tid] = sc; tsp[tid] = ss;
    }
    __syncthreads();
    int uc = tid >> 6, c = tid & 63;
    float sr = 0.f, si = 0.f;
    const float* Yb = g_Y + (size_t)((b*8+ky)*256)*128;
    int u0 = uc*64;
    int t = (kxe*u0) & 255;
    for (int uu = 0; uu < 64; uu++){
        float2 y = *(const float2*)(Yb + (u0+uu)*128 + c*2);
        float cc = tc[t], sv = tsp[t];
        t = (t + kxe) & 255;
        sr = fmaf(y.x, cc, fmaf( y.y, sv, sr));
        si = fmaf(y.y, cc, fmaf(-y.x, sv, si));
    }
    red[(uc*64+c)*2]   = sr;
    red[(uc*64+c)*2+1] = si;
    __syncthreads();
    if (tid < 64){
        float ar = red[tid*2]       + red[(64+tid)*2]
                 + red[(128+tid)*2] + red[(192+tid)*2];
        float ai = red[tid*2+1]       + red[(64+tid)*2+1]
                 + red[(128+tid)*2+1] + red[(192+tid)*2+1];
        float* o = g_F + (size_t)(((b*8+ky)*16+s)*64 + tid)*2;
        o[0] = ar; o[1] = ai;
    }
}

// ---------------- mode mixing: out[o] = sum_i F[i] * W[i][o] (complex) ------
__global__ __launch_bounds__(256) void k_mix(int l, const float* __restrict__ wr1,
                      const float* __restrict__ wi1, const float* __restrict__ wr2,
                      const float* __restrict__ wi2){
    __shared__ float Fs[8*64*2];
    __shared__ float Wm[64*64*2];
    int tid = threadIdx.x;
    int s = blockIdx.x >> 3, ky = blockIdx.x & 7;
    const float* wr = (s < 8) ? wr1 : wr2;
    const float* wi = (s < 8) ? wi1 : wi2;
    int kxh = s & 7;
    for (int i = tid; i < 8*64*2; i += 256){
        int b = i >> 7, r = i & 127;
        Fs[i] = g_F[(size_t)(((b*8+ky)*16+s)*64)*2 + r];
    }
    for (int i = tid; i < 4096; i += 256){
        int ii = i >> 6, o = i & 63;
        int src = (((l*64+ii)*64+o)*8 + kxh)*8 + ky;
        Wm[i*2]   = wr[src];
        Wm[i*2+1] = wi[src];
    }
    __syncthreads();
    #pragma unroll
    for (int p = 0; p < 2; p++){
        int gid = tid + p*256;
        int b = gid >> 6, o = gid & 63;
        float ar = 0.f, ai = 0.f;
        const float2* fp = (const float2*)&Fs[b*128];
        const float2* wp = (const float2*)Wm;
        #pragma unroll 4
        for (int i2 = 0; i2 < 64; i2++){
            float2 f = fp[i2];
            float2 w = wp[i2*64 + o];
            ar = fmaf(f.x, w.x, fmaf(-f.y, w.y, ar));
            ai = fmaf(f.x, w.y, fmaf( f.y, w.x, ai));
        }
        float* ot = g_OF + (size_t)(((b*8+ky)*16+s)*64 + o)*2;
        ot[0] = ar; ot[1] = ai;
    }
}

// ---------------- inverse over kx: grid B*KY*8 = 512 -------------------------
__global__ __launch_bounds__(256) void k_idft1(){
    __shared__ float OFs[16*64*2];
    int tid = threadIdx.x;
    int blk = blockIdx.x;
    int uq = blk & 7, ky = (blk>>3) & 7, b = blk >> 6;
    for (int i = tid; i < 2048; i += 256)
        OFs[i] = g_OF[(size_t)((b*8+ky)*16*64)*2 + i];
    __syncthreads();
    int u = uq*32 + (tid & 31);
    int og = tid >> 5, o0 = og*8;
    float ar[8], ai[8];
    #pragma unroll
    for (int j = 0; j < 8; j++){ ar[j] = 0.f; ai[j] = 0.f; }
    for (int s = 0; s < 16; s++){
        int kxe = (s < 8) ? s : s - 16;
        float ss, sc;
        sincospif((float)(kxe*u)*(1.0f/128.0f), &ss, &sc);
        const float2* op = (const float2*)&OFs[(s*64+o0)*2];
        #pragma unroll
        for (int j = 0; j < 8; j++){
            float2 f = op[j];
            ar[j] = fmaf(f.x, sc, fmaf(-f.y, ss, ar[j]));
            ai[j] = fmaf(f.x, ss, fmaf( f.y, sc, ai[j]));
        }
    }
    float* o = g_G + (size_t)(((b*8+ky)*256+u)*64 + o0)*2;
    #pragma unroll
    for (int j = 0; j < 8; j++){ o[j*2] = ar[j]; o[j*2+1] = ai[j]; }
}

// ---------------- fused per-row layer kernel (R11 baseline, 2202us) ---------
// 256 threads: thread = (4 px, 16 ch). Register-tiled GEMMs on f32x2.
// Single-pass MLP: phase2 computes all 8 m-channels per thread in one t-scan;
// m is stored into hs rows 0..31 (dead t storage).
__global__ __launch_bounds__(256,2) void k_fuse(int l, int do_dft,
        const float* __restrict__ gate_g, const float* __restrict__ specb_g,
        const float* __restrict__ b1_g, const float* __restrict__ b2_g){
    extern __shared__ float sm[];
    float* hs  = sm;              // 64*260 = 16640
    float* uni = hs + 16640;      // 5120: phase1 {wsk|Gr}, epilogue red
    float* w1  = uni + 5120;      // 2048 [i][j]   (epilogue: tw8 low half)
    float* w2  = w1 + 2048;       // 2048 [j][o]   (epilogue: tw8 high half)
    float* twi = w2 + 2048;       // 512 interleaved (cos,sin) of +2pi t/256
    float* gw  = twi + 512;       // 64
    float* sb  = gw + 64;         // 64
    float* b1s = sb + 64;         // 32
    float* b2s = b1s + 32;        // 64   -> total 26592 floats = 106368 B
    float* wsk = uni;             // phase-1 alias
    float* Grr = uni + 4096;      // 512 [ky][o] real
    float* Gri = uni + 4608;      // 512 [ky][o] imag
    float* red = uni;             // epilogue alias (4096)
    float* tw8 = w1;              // epilogue alias (4096 = 2048 u64)

    int tid = threadIdx.x;
    int u = blockIdx.x & 255, b = blockIdx.x >> 8;
    float* row = g_h + (size_t)(b*256+u)*64*256;

    {
        const float4* rw4 = (const float4*)row;
        for (int i = tid; i < 4096; i += 256){
            int c = i>>6, v4 = i&63;
            *(float4*)&hs[c*260 + v4*4] = rw4[i];
        }
    }
    for (int i = tid; i < 1024; i += 256) ((float4*)wsk)[i] = ((const float4*)(g_Wfsk + l*4096))[i];
    for (int i = tid; i < 512;  i += 256) ((float4*)w1)[i]  = ((const float4*)(g_Wf1  + l*2048))[i];
    for (int i = tid; i < 512;  i += 256) ((float4*)w2)[i]  = ((const float4*)(g_Wf2  + l*2048))[i];
    for (int i = tid; i < 512; i += 256){
        int ky = i>>6, o = i&63;
        float2 g = *(const float2*)&g_G[(size_t)(((b*8+ky)*256+u)*64 + o)*2];
        Grr[i] = g.x; Gri[i] = g.y;
    }
    {
        float ss, sc;
        sincospif((float)tid*(1.0f/128.0f), &ss, &sc);
        twi[tid*2] = sc; twi[tid*2+1] = ss;
    }
    if (tid < 64) gw[tid]  = gate_g[l*64+tid];
    if (tid < 64) sb[tid]  = specb_g[l*64+tid];
    if (tid < 32) b1s[tid] = b1_g[l*32+tid];
    if (tid < 64) b2s[tid] = b2_g[l*64+tid];
    __syncthreads();

    int pxg = tid & 63, chg = tid >> 6;
    int v0 = pxg*4, o0 = chg*16;

    // ---- phase 1: acc[8 ch-pairs][4 px] = spec_b + recomb + skip GEMM
    u64 acc[8][4];
    #pragma unroll
    for (int o2 = 0; o2 < 8; o2++){
        u64 ini = pk2(sb[o0+2*o2], sb[o0+2*o2+1]);
        #pragma unroll
        for (int p = 0; p < 4; p++) acc[o2][p] = ini;
    }
    #pragma unroll
    for (int ky = 0; ky < 8; ky++){
        float cw = (ky == 0) ? 1.0f : 2.0f;
        u64 cs2[4], nsn2[4];
        int idx = (ky*v0) & 255;
        #pragma unroll
        for (int p = 0; p < 4; p++){
            float cs = twi[idx*2]*cw, sn = twi[idx*2+1]*cw;
            cs2[p] = pk2(cs, cs); nsn2[p] = pk2(-sn, -sn);
            idx = (idx + ky) & 255;
        }
        const u64* rr = (const u64*)&Grr[ky*64 + o0];
        const u64* ri = (const u64*)&Gri[ky*64 + o0];
        #pragma unroll
        for (int o2 = 0; o2 < 8; o2++){
            u64 gr = rr[o2], gi = ri[o2];
            #pragma unroll
            for (int p = 0; p < 4; p++)
                acc[o2][p] = ffma2(gr, cs2[p], ffma2(gi, nsn2[p], acc[o2][p]));
        }
    }
    for (int i = 0; i < 64; i++){
        float4 hv = *(const float4*)&hs[i*260 + v0];
        u64 h2[4] = {pk2(hv.x,hv.x), pk2(hv.y,hv.y), pk2(hv.z,hv.z), pk2(hv.w,hv.w)};
        const ulonglong2* wp = (const ulonglong2*)&wsk[i*64 + o0];
        #pragma unroll
        for (int qq = 0; qq < 4; qq++){
            ulonglong2 w = wp[qq];
            #pragma unroll
            for (int p = 0; p < 4; p++){
                acc[2*qq][p]   = ffma2(h2[p], w.x, acc[2*qq][p]);
                acc[2*qq+1][p] = ffma2(h2[p], w.y, acc[2*qq+1][p]);
            }
        }
    }
    __syncthreads();   // all phase-1 reads of h_old (hs) done
    #pragma unroll
    for (int o2 = 0; o2 < 8; o2++){
        float lo[4], hi[4];
        #pragma unroll
        for (int p = 0; p < 4; p++) upk2(acc[o2][p], lo[p], hi[p]);
        float4 r0, r1;
        r0.x = gelu_f(lo[0]); r0.y = gelu_f(lo[1]); r0.z = gelu_f(lo[2]); r0.w = gelu_f(lo[3]);
        r1.x = gelu_f(hi[0]); r1.y = gelu_f(hi[1]); r1.z = gelu_f(hi[2]); r1.w = gelu_f(hi[3]);
        *(float4*)&hs[(o0+2*o2)*260   + v0] = r0;
        *(float4*)&hs[(o0+2*o2+1)*260 + v0] = r1;
    }
    __syncthreads();

    // ---- phase 2 (single pass): m-channels jb..jb+7 over one t-scan
    int jb = chg*8;
    u64 m2[4][4];
    #pragma unroll
    for (int qq = 0; qq < 4; qq++){
        u64 ini = pk2(b1s[jb+2*qq], b1s[jb+2*qq+1]);
        #pragma unroll
        for (int p = 0; p < 4; p++) m2[qq][p] = ini;
    }
    for (int i = 0; i < 64; i++){
        float4 tv = *(const float4*)&hs[i*260 + v0];
        u64 t2[4] = {pk2(tv.x,tv.x), pk2(tv.y,tv.y), pk2(tv.z,tv.z), pk2(tv.w,tv.w)};
        const ulonglong2* wp = (const ulonglong2*)&w1[i*32 + jb];
        ulonglong2 wa = wp[0], wb = wp[1];
        #pragma unroll
        for (int p = 0; p < 4; p++){
            m2[0][p] = ffma2(t2[p], wa.x, m2[0][p]);
            m2[1][p] = ffma2(t2[p], wa.y, m2[1][p]);
            m2[2][p] = ffma2(t2[p], wb.x, m2[2][p]);
            m2[3][p] = ffma2(t2[p], wb.y, m2[3][p]);
        }
    }
    // init out with gate (row = h_old in gmem, L1-resident) + b2 while t-reads drain
    u64 out[8][4];
    #pragma unroll
    for (int o2 = 0; o2 < 8; o2++){
        float4 ha = *(const float4*)&row[(o0+2*o2)*256   + v0];
        float4 hb = *(const float4*)&row[(o0+2*o2+1)*256 + v0];
        float g0 = gw[o0+2*o2], g1 = gw[o0+2*o2+1];
        float B0 = b2s[o0+2*o2], B1 = b2s[o0+2*o2+1];
        out[o2][0] = pk2(fmaf(g0,ha.x,B0), fmaf(g1,hb.x,B1));
        out[o2][1] = pk2(fmaf(g0,ha.y,B0), fmaf(g1,hb.y,B1));
        out[o2][2] = pk2(fmaf(g0,ha.z,B0), fmaf(g1,hb.z,B1));
        out[o2][3] = pk2(fmaf(g0,ha.w,B0), fmaf(g1,hb.w,B1));
    }
    __syncthreads();   // all t-reads done; hs rows 0..31 now reusable for m
    #pragma unroll
    for (int qq = 0; qq < 4; qq++){
        float lo[4], hi[4];
        #pragma unroll
        for (int p = 0; p < 4; p++) upk2(m2[qq][p], lo[p], hi[p]);
        float4 r0, r1;
        r0.x = gelu_f(lo[0]); r0.y = gelu_f(lo[1]); r0.z = gelu_f(lo[2]); r0.w = gelu_f(lo[3]);
        r1.x = gelu_f(hi[0]); r1.y = gelu_f(hi[1]); r1.z = gelu_f(hi[2]); r1.w = gelu_f(hi[3]);
        *(float4*)&hs[(jb+2*qq)*260   + v0] = r0;
        *(float4*)&hs[(jb+2*qq+1)*260 + v0] = r1;
    }
    __syncthreads();

    // ---- phase 3: single 32-j pass reading m from hs rows 0..31
    for (int j = 0; j < 32; j++){
        float4 mv = *(const float4*)&hs[j*260 + v0];
        u64 mvp[4] = {pk2(mv.x,mv.x), pk2(mv.y,mv.y), pk2(mv.z,mv.z), pk2(mv.w,mv.w)};
        const ulonglong2* wp = (const ulonglong2*)&w2[j*64 + o0];
        #pragma unroll
        for (int qq = 0; qq < 4; qq++){
            ulonglong2 w = wp[qq];
            #pragma unroll
            for (int p = 0; p < 4; p++){
                out[2*qq][p]   = ffma2(mvp[p], w.x, out[2*qq][p]);
                out[2*qq+1][p] = ffma2(mvp[p], w.y, out[2*qq+1][p]);
            }
        }
    }
    __syncthreads();   // all m-reads done; hs now reusable for h_new

    bool dog = (l < 3);
    #pragma unroll
    for (int o2 = 0; o2 < 8; o2++){
        float lo[4], hi[4];
        #pragma unroll
        for (int p = 0; p < 4; p++) upk2(out[o2][p], lo[p], hi[p]);
        if (dog){
            #pragma unroll
            for (int p = 0; p < 4; p++){ lo[p] = gelu_f(lo[p]); hi[p] = gelu_f(hi[p]); }
        }
        float4 r0, r1;
        r0.x = lo[0]; r0.y = lo[1]; r0.z = lo[2]; r0.w = lo[3];
        r1.x = hi[0]; r1.y = hi[1]; r1.z = hi[2]; r1.w = hi[3];
        *(float4*)&hs[(o0+2*o2)*260   + v0] = r0;
        *(float4*)&hs[(o0+2*o2+1)*260 + v0] = r1;
        *(float4*)&row[(o0+2*o2)*256   + v0] = r0;
        *(float4*)&row[(o0+2*o2+1)*256 + v0] = r1;
    }

    // ---- epilogue: stage-1 DFT of h_new; per-ky sequential twiddle tables
    if (do_dft){
        __syncthreads();   // hs complete everywhere; w1/w2 regions now dead
        {   // build tw8[ky][v] (u64) in the dead w1+w2 region from twi
            u64* t8u = (u64*)tw8;
            const u64* twb = (const u64*)twi;
            #pragma unroll
            for (int r = 0; r < 8; r++){
                int e = tid + r*256;
                int ky = e >> 8, v = e & 255;
                t8u[e] = twb[(ky*v)&255];
            }
        }
        __syncthreads();
        int c = tid & 63, qd = tid >> 6;
        const u64* t8 = (const u64*)tw8;
        u64 a[8];
        #pragma unroll
        for (int k = 0; k < 8; k++) a[k] = pk2(0.f, 0.f);
        const float* hc = &hs[c*260 + qd*64];
        int vb = qd*64;
        for (int vv = 0; vv < 64; vv += 4){
            float4 xv = *(const float4*)&hc[vv];
            u64 x0 = pk2(xv.x,xv.x), x1 = pk2(xv.y,xv.y);
            u64 x2 = pk2(xv.z,xv.z), x3 = pk2(xv.w,xv.w);
            #pragma unroll
            for (int k = 0; k < 8; k++){
                const u64* tk = t8 + k*256 + vb + vv;
                a[k] = ffma2(x0, tk[0], a[k]);
                a[k] = ffma2(x1, tk[1], a[k]);
                a[k] = ffma2(x2, tk[2], a[k]);
                a[k] = ffma2(x3, tk[3], a[k]);
            }
        }
        #pragma unroll
        for (int k = 0; k < 8; k++){
            float sr, si; upk2(a[k], sr, si);
            *(float2*)&red[((qd*64+c)*8+k)*2] = make_float2(sr, si);
        }
        __syncthreads();
        const float scale = 1.0f/65536.0f;
        #pragma unroll
        for (int rep = 0; rep < 2; rep++){
            int idx = tid + rep*256;
            int ky = idx >> 6, cc = idx & 63;
            float sr = 0.f, si = 0.f;
            #pragma unroll
            for (int q2 = 0; q2 < 4; q2++){
                float2 t = *(const float2*)&red[((q2*64+cc)*8+ky)*2];
                sr += t.x; si += t.y;
            }
            float* o = g_Y + (size_t)(((b*8+ky)*256+u)*64 + cc)*2;
            o[0] = sr*scale; o[1] = -si*scale;   // tw8 is e^{+i}, conjugate here
        }
    }
}

// ---------------- projection: 64 -> 128 -> gelu -> 3, + input residual ------
// Pair-packed t2 so the final 3-channel GEMM runs on ffma2 + LDS.64.
__global__ __launch_bounds__(256,2) void k_proj(const float* __restrict__ x,
                      const float* __restrict__ b1g, const float* __restrict__ w2g,
                      const float* __restrict__ b2g, float* __restrict__ out){
    extern __shared__ float sm[];
    float* hsp = sm;            // 64*68 = 4352
    float* t2p = hsp + 4352;    // 64*132 = 8448  pair-packed: [j2][px*2 + half]
    float* w1s = t2p + 8448;    // 64*128 [k][o]
    float* b1s = w1s + 8192;    // 128
    int tid = threadIdx.x;
    int blk = blockIdx.x;
    int q = blk & 3, u = (blk>>2) & 255, b = blk >> 10;
    const float* row = g_h + (size_t)(b*256+u)*64*256 + q*64;
    for (int i = tid; i < 1024; i += 256){
        int c = i>>4, v4 = i&15;
        *(float4*)&hsp[c*68 + v4*4] = *(const float4*)&row[c*256 + v4*4];
    }
    for (int i = tid; i < 2048; i += 256) ((float4*)w1s)[i] = ((const float4*)g_Wp1)[i];
    if (tid < 128) b1s[tid] = b1g[tid];
    __syncthreads();
    {
        int pxg = tid & 31, chg = tid >> 5;   // 32 px-groups (2 px) x 8 ch-groups (16 ch)
        int o0 = chg*16;
        u64 a[8][2];
        #pragma unroll
        for (int o2 = 0; o2 < 8; o2++){
            u64 ini = pk2(b1s[o0+2*o2], b1s[o0+2*o2+1]);
            a[o2][0] = ini; a[o2][1] = ini;
        }
        #pragma unroll 4
        for (int k = 0; k < 64; k++){
            float2 tv = *(const float2*)&hsp[k*68 + pxg*2];
            u64 t20 = pk2(tv.x, tv.x), t21 = pk2(tv.y, tv.y);
            const ulonglong2* wp = (const ulonglong2*)&w1s[k*128 + o0];
            #pragma unroll
            for (int qq = 0; qq < 4; qq++){
                ulonglong2 w = wp[qq];
                a[2*qq][0]   = ffma2(t20, w.x, a[2*qq][0]);
                a[2*qq][1]   = ffma2(t21, w.x, a[2*qq][1]);
                a[2*qq+1][0] = ffma2(t20, w.y, a[2*qq+1][0]);
                a[2*qq+1][1] = ffma2(t21, w.y, a[2*qq+1][1]);
            }
        }
        // pair-packed store: t2p[j2*132 + px*2 + half], j2 = o>>1
        #pragma unroll
        for (int o2 = 0; o2 < 8; o2++){
            float e0, d0, e1, d1;
            upk2(a[o2][0], e0, d0);   // px0: channels (2j2, 2j2+1)
            upk2(a[o2][1], e1, d1);   // px1
            int j2 = (o0>>1) + o2;
            float* tp = &t2p[j2*132 + pxg*4];
            tp[0] = gelu_f(e0); tp[1] = gelu_f(d0);
            tp[2] = gelu_f(e1); tp[3] = gelu_f(d1);
        }
    }
    __syncthreads();
    if (tid < 192){
        int c = tid >> 6, vv = tid & 63;
        u64 a2 = pk2(0.f, 0.f);
        const u64* wg = (const u64*)(w2g + c*128);
        #pragma unroll 4
        for (int j2 = 0; j2 < 64; j2++){
            u64 tv = *(const u64*)&t2p[j2*132 + vv*2];
            a2 = ffma2(tv, wg[j2], a2);
        }
        float s0, s1; upk2(a2, s0, s1);
        size_t gi = (size_t)((b*3+c)*256+u)*256 + q*64 + vv;
        out[gi] = s0 + s1 + b2g[c] + x[gi];
    }
}

// ---------------- host launch ------------------------------------------------
extern "C" void kernel_launch(void* const* d_in, const int* in_sizes, int n_in,
                              void* d_out, int out_size){
    (void)in_sizes; (void)n_in; (void)out_size;
    const float* x       = (const float*)d_in[0];
    const float* lift_w1 = (const float*)d_in[1];
    const float* lift_b1 = (const float*)d_in[2];
    const float* lift_w2 = (const float*)d_in[3];
    const float* lift_b2 = (const float*)d_in[4];
    const float* swr1    = (const float*)d_in[5];
    const float* swi1    = (const float*)d_in[6];
    const float* swr2    = (const float*)d_in[7];
    const float* swi2    = (const float*)d_in[8];
    const float* spec_b  = (const float*)d_in[9];
    const float* skw     = (const float*)d_in[10];
    const float* gate    = (const float*)d_in[11];
    const float* mw1     = (const float*)d_in[12];
    const float* mb1     = (const float*)d_in[13];
    const float* mw2     = (const float*)d_in[14];
    const float* mb2     = (const float*)d_in[15];
    const float* pw1     = (const float*)d_in[16];
    const float* pb1     = (const float*)d_in[17];
    const float* pw2     = (const float*)d_in[18];
    const float* pb2     = (const float*)d_in[19];
    float* out = (float*)d_out;

    const int SM_LIFT = (16640 + 8192 + 768 + 256 + 64 + 384) * 4;   // 105216
    const int SM_DFT1 = (16640 + 4096 + 4096) * 4;                    // 99328
    const int SM_FUSE = 26592 * 4;                                    // 106368
    const int SM_PROJ = (4352 + 8448 + 8192 + 128) * 4;               // 84480

    cudaFuncSetAttribute(k_lift, cudaFuncAttributeMaxDynamicSharedMemorySize, SM_LIFT);
    cudaFuncSetAttribute(k_dft1, cudaFuncAttributeMaxDynamicSharedMemorySize, SM_DFT1);
    cudaFuncSetAttribute(k_fuse, cudaFuncAttributeMaxDynamicSharedMemorySize, SM_FUSE);
    cudaFuncSetAttribute(k_proj, cudaFuncAttributeMaxDynamicSharedMemorySize, SM_PROJ);

    k_reorder<<<224, 256>>>(lift_w2, pw1, skw, mw1, mw2);
    k_lift<<<BB*HH*2, 256, SM_LIFT>>>(x, lift_w1, lift_b1, lift_b2);
    k_dft1<<<BB*HH, 256, SM_DFT1>>>();           // once, after lift
    for (int l = 0; l < 4; l++){
        k_dft2 <<<BB*NKY*NKX, 256>>>();
        k_mix  <<<NKX*NKY, 256>>>(l, swr1, swi1, swr2, swi2);
        k_idft1<<<BB*NKY*8, 256>>>();
        k_fuse <<<BB*HH, 256, SM_FUSE>>>(l, (l < 3) ? 1 : 0,
                                         gate, spec_b, mb1, mb2);
    }
    k_proj<<<BB*HH*4, 256, SM_PROJ>>>(x, pb1, pw2, pb2, out);
}

// round 14
// speedup vs baseline: 1.1367x; 1.0687x over previous
#include <cuda_runtime.h>
#include <math.h>

// Problem constants
#define BB 8
#define HH 256
#define WW 256
#define CC 64
#define NKY 8
#define NKX 16

typedef unsigned long long u64;

// ---------------- scratch (static device memory; no allocations) ------------
__device__ float g_h[BB*HH*CC*WW];        // h field, layout [b][u][c][v]  (128MB)
__device__ float g_Y[BB*NKY*HH*CC*2];     // stage-1 DFT  [b][ky][u][c][re,im]
__device__ float g_F[BB*NKY*NKX*CC*2];    // modes        [b][ky][s][c][re,im]
__device__ float g_OF[BB*NKY*NKX*CC*2];   // mixed modes  (same layout)
__device__ float g_G[BB*NKY*HH*CC*2];     // inverse stage [b][ky][u][o][re,im]
__device__ float g_Wl2[256*64];           // lift_w2 transposed [k][o], tf32-rounded
__device__ float g_Wp1[64*128];           // proj_w1 transposed [k][o]
__device__ float g_Wfsk[4*64*64];         // fno skip, [l][i][o]
__device__ float g_Wf1[4*64*32];          // mlp w1,   [l][i][j]
__device__ float g_Wf2[4*32*64];          // mlp w2,   [l][j][o]

// ---- gelu via hardware tanh (1 MUFU op) ------------------------------------
__device__ __forceinline__ float gelu_f(float x){
    float x2 = x*x;
    float inner = fmaf(fmaf(0.0356774081f, x2, 0.7978845608f), x, 0.0f);
    float t;
    asm("tanh.approx.f32 %0,%1;" : "=f"(t) : "f"(inner));
    return 0.5f*x*(1.0f + t);
}

// ---- packed fp32x2 helpers --------------------------------------------------
__device__ __forceinline__ u64 pk2(float lo, float hi){
    u64 r; asm("mov.b64 %0,{%1,%2};" : "=l"(r) : "f"(lo), "f"(hi)); return r;
}
__device__ __forceinline__ void upk2(u64 v, float& lo, float& hi){
    asm("mov.b64 {%0,%1},%2;" : "=f"(lo), "=f"(hi) : "l"(v));
}
__device__ __forceinline__ u64 ffma2(u64 a, u64 b, u64 c){
    u64 r; asm("fma.rn.f32x2 %0,%1,%2,%3;" : "=l"(r) : "l"(a), "l"(b), "l"(c)); return r;
}
__device__ __forceinline__ unsigned tf32_rna(float x){
    unsigned r; asm("cvt.rna.tf32.f32 %0,%1;" : "=r"(r) : "f"(x)); return r;
}

// ---------------- one-time (per launch) weight transposes --------------------
__global__ void k_reorder(const float* __restrict__ lw2, const float* __restrict__ pw1,
                          const float* __restrict__ skw, const float* __restrict__ mw1,
                          const float* __restrict__ mw2){
    int e = blockIdx.x*256 + threadIdx.x;
    if (e < 16384){ int k = e>>6, o = e&63;
        ((unsigned*)g_Wl2)[e] = tf32_rna(lw2[o*256+k]); }       // tf32-rounded
    else if (e < 24576){ int i = e-16384; int k = i>>7, o = i&127; g_Wp1[i] = pw1[o*64+k]; }
    else if (e < 40960){ int i = e-24576; int l = i>>12; int r = i&4095;
                         int ii = r>>6, o = r&63; g_Wfsk[i] = skw[l*4096 + o*64 + ii]; }
    else if (e < 49152){ int i = e-40960; int l = i>>11; int r = i&2047;
                         int ii = r>>5, j = r&31;  g_Wf1[i] = mw1[l*2048 + j*64 + ii]; }
    else if (e < 57344){ int i = e-49152; int l = i>>11; int r = i&2047;
                         int j = r>>6, o = r&63;   g_Wf2[i] = mw2[l*2048 + o*32 + j]; }
}

// ---------------- lifting via tf32 MMA: x(3) -> 256 -> gelu -> 64 ------------
// grid: B*H*2 (128-px tiles), 256 threads, 2 blocks/SM.
// C[64 o x 128 px] = W2[64x256] * t1[256x128], K swept in two halves.
// warp = (m-block mb 0..3, n-half nh 0..1); 8 n8-tiles per warp.
// smem strides 72 / 136 (==8 mod 32) -> conflict-free fragment gathers.
__global__ __launch_bounds__(256,2) void k_lift(const float* __restrict__ x,
                       const float* __restrict__ w1, const float* __restrict__ b1,
                       const float* __restrict__ b2){
    extern __shared__ float sm[];
    float* t1  = sm;               // 128*136 = 17408 (tf32 bits)
    float* w2h = t1 + 17408;       // 128*72 = 9216   (tf32 bits)
    float* w1s = w2h + 9216;       // 768
    float* b1s = w1s + 768;        // 256
    float* b2s = b1s + 256;        // 64
    float* xs  = b2s + 64;         // 384   -> total 28096 floats = 112384 B
    int tid = threadIdx.x;
    int blk = blockIdx.x;
    int q = blk & 1, u = (blk>>1) & 255, b = blk >> 9;
    int lane = tid & 31, w = tid >> 5;
    int g = lane >> 2, t = lane & 3;
    int mb = w & 3, nh = w >> 2;

    for (int i = tid; i < 768; i += 256) w1s[i] = w1[i];
    if (tid < 256) b1s[tid] = b1[tid];
    if (tid < 64)  b2s[tid] = b2[tid];
    for (int i = tid; i < 384; i += 256){
        int c = i>>7, v = i&127;
        xs[i] = x[((b*3+c)*256+u)*256 + q*128 + v];
    }
    __syncthreads();

    float acc[8][4];
    {
        float bl = b2s[mb*16 + g], bh = b2s[mb*16 + 8 + g];
        #pragma unroll
        for (int nt = 0; nt < 8; nt++){
            acc[nt][0] = bl; acc[nt][1] = bl;
            acc[nt][2] = bh; acc[nt][3] = bh;
        }
    }

    for (int p = 0; p < 2; p++){
        // stage this K-half of w2 (already tf32-rounded): [kk][o] stride 72
        for (int i = tid; i < 8192; i += 256){
            int kk = i>>6, o = i&63;
            w2h[kk*72 + o] = g_Wl2[p*8192 + i];
        }
        // compute t1 = tf32(gelu(w1 x + b1)) for this K-half: [kk][px] stride 136
        for (int it = tid; it < 16384; it += 256){
            int kk = it >> 7, vx = it & 127;
            int c = p*128 + kk;
            float s = fmaf(w1s[c*3+0], xs[vx],
                      fmaf(w1s[c*3+1], xs[128+vx],
                      fmaf(w1s[c*3+2], xs[256+vx], b1s[c])));
            ((unsigned*)t1)[kk*136 + vx] = tf32_rna(gelu_f(s));
        }
        __syncthreads();

        const unsigned* t1u = (const unsigned*)t1;
        const unsigned* w2u = (const unsigned*)w2h;
        #pragma unroll 2
        for (int ks = 0; ks < 16; ks++){
            int k0 = ks*8;
            unsigned a0 = w2u[(k0+t)*72   + mb*16 + g];
            unsigned a1 = w2u[(k0+t)*72   + mb*16 + 8 + g];
            unsigned a2 = w2u[(k0+t+4)*72 + mb*16 + g];
            unsigned a3 = w2u[(k0+t+4)*72 + mb*16 + 8 + g];
            #pragma unroll
            for (int nt = 0; nt < 8; nt++){
                int n0 = nh*64 + nt*8;
                unsigned bb0 = t1u[(k0+t)*136   + n0 + g];
                unsigned bb1 = t1u[(k0+t+4)*136 + n0 + g];
                asm volatile(
                    "mma.sync.aligned.m16n8k8.row.col.f32.tf32.tf32.f32 "
                    "{%0,%1,%2,%3},{%4,%5,%6,%7},{%8,%9},{%0,%1,%2,%3};"
                    : "+f"(acc[nt][0]), "+f"(acc[nt][1]),
                      "+f"(acc[nt][2]), "+f"(acc[nt][3])
                    : "r"(a0), "r"(a1), "r"(a2), "r"(a3), "r"(bb0), "r"(bb1));
            }
        }
        __syncthreads();
    }

    float* outrow = g_h + (size_t)((b*256+u)*64)*256 + q*128;
    #pragma unroll
    for (int nt = 0; nt < 8; nt++){
        int pxl = nh*64 + nt*8 + 2*t;
        *(float2*)&outrow[(mb*16 + g)*256     + pxl] = make_float2(acc[nt][0], acc[nt][1]);
        *(float2*)&outrow[(mb*16 + 8 + g)*256 + pxl] = make_float2(acc[nt][2], acc[nt][3]);
    }
}

// ---------------- DFT stage 1 (over v): runs ONCE after lift -----------------
__global__ __launch_bounds__(256) void k_dft1(){
    extern __shared__ float sm[];
    float* hs  = sm;            // 64*260 = 16640
    float* tw8 = hs + 16640;    // 4096 = 2048 u64: [ky][v] e^{+2pi i ky v/256}
    float* red = tw8 + 4096;    // 4096
    int tid = threadIdx.x;
    int u = blockIdx.x & 255, b = blockIdx.x >> 8;
    const float* row = g_h + (size_t)(b*256+u)*64*256;
    const float4* rw4 = (const float4*)row;
    for (int i = tid; i < 4096; i += 256){
        int c = i>>6, v4 = i&63;
        *(float4*)&hs[c*260 + v4*4] = rw4[i];
    }
    {   // row ky=1 is the base table
        float ss, sc;
        sincospif((float)tid*(1.0f/128.0f), &ss, &sc);
        tw8[(256+tid)*2] = sc; tw8[(256+tid)*2+1] = ss;
    }
    __syncthreads();
    {
        u64* t8u = (u64*)tw8;
        const u64* basew = (const u64*)tw8 + 256;
        #pragma unroll
        for (int r = 0; r < 8; r++){
            int e = tid + r*256;
            int ky = e >> 8, v = e & 255;
            if (ky != 1) t8u[e] = basew[(ky*v)&255];
        }
    }
    __syncthreads();
    int c = tid & 63, qd = tid >> 6;
    const u64* t8 = (const u64*)tw8;
    u64 a[8];
    #pragma unroll
    for (int k = 0; k < 8; k++) a[k] = pk2(0.f, 0.f);
    const float* hc = &hs[c*260 + qd*64];
    int vb = qd*64;
    for (int vv = 0; vv < 64; vv += 4){
        float4 xv = *(const float4*)&hc[vv];
        u64 x0 = pk2(xv.x,xv.x), x1 = pk2(xv.y,xv.y);
        u64 x2 = pk2(xv.z,xv.z), x3 = pk2(xv.w,xv.w);
        #pragma unroll
        for (int k = 0; k < 8; k++){
            const u64* tk = t8 + k*256 + vb + vv;
            a[k] = ffma2(x0, tk[0], a[k]);
            a[k] = ffma2(x1, tk[1], a[k]);
            a[k] = ffma2(x2, tk[2], a[k]);
            a[k] = ffma2(x3, tk[3], a[k]);
        }
    }
    #pragma unroll
    for (int k = 0; k < 8; k++){
        float sr, si; upk2(a[k], sr, si);
        *(float2*)&red[((qd*64+c)*8+k)*2] = make_float2(sr, si);
    }
    __syncthreads();
    const float scale = 1.0f/65536.0f;
    #pragma unroll
    for (int rep = 0; rep < 2; rep++){
        int idx = tid + rep*256;
        int ky = idx >> 6, cc = idx & 63;
        float sr = 0.f, si = 0.f;
        #pragma unroll
        for (int q2 = 0; q2 < 4; q2++){
            float2 t = *(const float2*)&red[((q2*64+cc)*8+ky)*2];
            sr += t.x; si += t.y;
        }
        float* o = g_Y + (size_t)(((b*8+ky)*256+u)*64 + cc)*2;
        o[0] = sr*scale; o[1] = -si*scale;   // conjugate: table is e^{+i}
    }
}

// ---------------- DFT stage 2 (over u): grid B*KY*KX = 1024 -----------------
__global__ __launch_bounds__(256) void k_dft2(){
    __shared__ float tc[256], tsp[256];
    __shared__ float red[4*64*2];
    int tid = threadIdx.x;
    int blk = blockIdx.x;
    int s = blk & 15, ky = (blk>>4) & 7, b = blk >> 7;
    int kxe = (s < 8) ? s : s - 16;
    {
        float ss, sc;
        sincospif((float)tid*(1.0f/128.0f), &ss, &sc);
        tc[tid] = sc; tsp[tid] = ss;
    }
    __syncthreads();
    int uc = tid >> 6, c = tid & 63;
    float sr = 0.f, si = 0.f;
    const float* Yb = g_Y + (size_t)((b*8+ky)*256)*128;
    int u0 = uc*64;
    int t = (kxe*u0) & 255;
    for (int uu = 0; uu < 64; uu++){
        float2 y = *(const float2*)(Yb + (u0+uu)*128 + c*2);
        float cc = tc[t], sv = tsp[t];
        t = (t + kxe) & 255;
        sr = fmaf(y.x, cc, fmaf( y.y, sv, sr));
        si = fmaf(y.y, cc, fmaf(-y.x, sv, si));
    }
    red[(uc*64+c)*2]   = sr;
    red[(uc*64+c)*2+1] = si;
    __syncthreads();
    if (tid < 64){
        float ar = red[tid*2]       + red[(64+tid)*2]
                 + red[(128+tid)*2] + red[(192+tid)*2];
        float ai = red[tid*2+1]       + red[(64+tid)*2+1]
                 + red[(128+tid)*2+1] + red[(192+tid)*2+1];
        float* o = g_F + (size_t)(((b*8+ky)*16+s)*64 + tid)*2;
        o[0] = ar; o[1] = ai;
    }
}

// ---------------- mode mixing: out[o] = sum_i F[i] * W[i][o] (complex) ------
__global__ __launch_bounds__(256) void k_mix(int l, const float* __restrict__ wr1,
                      const float* __restrict__ wi1, const float* __restrict__ wr2,
                      const float* __restrict__ wi2){
    __shared__ float Fs[8*64*2];
    __shared__ float Wm[64*64*2];
    int tid = threadIdx.x;
    int s = blockIdx.x >> 3, ky = blockIdx.x & 7;
    const float* wr = (s < 8) ? wr1 : wr2;
    const float* wi = (s < 8) ? wi1 : wi2;
    int kxh = s & 7;
    for (int i = tid; i < 8*64*2; i += 256){
        int b = i >> 7, r = i & 127;
        Fs[i] = g_F[(size_t)(((b*8+ky)*16+s)*64)*2 + r];
    }
    for (int i = tid; i < 4096; i += 256){
        int ii = i >> 6, o = i & 63;
        int src = (((l*64+ii)*64+o)*8 + kxh)*8 + ky;
        Wm[i*2]   = wr[src];
        Wm[i*2+1] = wi[src];
    }
    __syncthreads();
    #pragma unroll
    for (int p = 0; p < 2; p++){
        int gid = tid + p*256;
        int b = gid >> 6, o = gid & 63;
        float ar = 0.f, ai = 0.f;
        const float2* fp = (const float2*)&Fs[b*128];
        const float2* wp = (const float2*)Wm;
        #pragma unroll 4
        for (int i2 = 0; i2 < 64; i2++){
            float2 f = fp[i2];
            float2 w = wp[i2*64 + o];
            ar = fmaf(f.x, w.x, fmaf(-f.y, w.y, ar));
            ai = fmaf(f.x, w.y, fmaf( f.y, w.x, ai));
        }
        float* ot = g_OF + (size_t)(((b*8+ky)*16+s)*64 + o)*2;
        ot[0] = ar; ot[1] = ai;
    }
}

// ---------------- inverse over kx: grid B*KY*8 = 512 -------------------------
__global__ __launch_bounds__(256) void k_idft1(){
    __shared__ float OFs[16*64*2];
    int tid = threadIdx.x;
    int blk = blockIdx.x;
    int uq = blk & 7, ky = (blk>>3) & 7, b = blk >> 6;
    for (int i = tid; i < 2048; i += 256)
        OFs[i] = g_OF[(size_t)((b*8+ky)*16*64)*2 + i];
    __syncthreads();
    int u = uq*32 + (tid & 31);
    int og = tid >> 5, o0 = og*8;
    float ar[8], ai[8];
    #pragma unroll
    for (int j = 0; j < 8; j++){ ar[j] = 0.f; ai[j] = 0.f; }
    for (int s = 0; s < 16; s++){
        int kxe = (s < 8) ? s : s - 16;
        float ss, sc;
        sincospif((float)(kxe*u)*(1.0f/128.0f), &ss, &sc);
        const float2* op = (const float2*)&OFs[(s*64+o0)*2];
        #pragma unroll
        for (int j = 0; j < 8; j++){
            float2 f = op[j];
            ar[j] = fmaf(f.x, sc, fmaf(-f.y, ss, ar[j]));
            ai[j] = fmaf(f.x, ss, fmaf( f.y, sc, ai[j]));
        }
    }
    float* o = g_G + (size_t)(((b*8+ky)*256+u)*64 + o0)*2;
    #pragma unroll
    for (int j = 0; j < 8; j++){ o[j*2] = ar[j]; o[j*2+1] = ai[j]; }
}

// ---------------- fused per-row layer kernel (R11 baseline) ------------------
__global__ __launch_bounds__(256,2) void k_fuse(int l, int do_dft,
        const float* __restrict__ gate_g, const float* __restrict__ specb_g,
        const float* __restrict__ b1_g, const float* __restrict__ b2_g){
    extern __shared__ float sm[];
    float* hs  = sm;              // 64*260 = 16640
    float* uni = hs + 16640;      // 5120: phase1 {wsk|Gr}, epilogue red
    float* w1  = uni + 5120;      // 2048 [i][j]   (epilogue: tw8 low half)
    float* w2  = w1 + 2048;       // 2048 [j][o]   (epilogue: tw8 high half)
    float* twi = w2 + 2048;       // 512 interleaved (cos,sin) of +2pi t/256
    float* gw  = twi + 512;       // 64
    float* sb  = gw + 64;         // 64
    float* b1s = sb + 64;         // 32
    float* b2s = b1s + 32;        // 64   -> total 26592 floats = 106368 B
    float* wsk = uni;             // phase-1 alias
    float* Grr = uni + 4096;      // 512 [ky][o] real
    float* Gri = uni + 4608;      // 512 [ky][o] imag
    float* red = uni;             // epilogue alias (4096)
    float* tw8 = w1;              // epilogue alias (4096 = 2048 u64)

    int tid = threadIdx.x;
    int u = blockIdx.x & 255, b = blockIdx.x >> 8;
    float* row = g_h + (size_t)(b*256+u)*64*256;

    {
        const float4* rw4 = (const float4*)row;
        for (int i = tid; i < 4096; i += 256){
            int c = i>>6, v4 = i&63;
            *(float4*)&hs[c*260 + v4*4] = rw4[i];
        }
    }
    for (int i = tid; i < 1024; i += 256) ((float4*)wsk)[i] = ((const float4*)(g_Wfsk + l*4096))[i];
    for (int i = tid; i < 512;  i += 256) ((float4*)w1)[i]  = ((const float4*)(g_Wf1  + l*2048))[i];
    for (int i = tid; i < 512;  i += 256) ((float4*)w2)[i]  = ((const float4*)(g_Wf2  + l*2048))[i];
    for (int i = tid; i < 512; i += 256){
        int ky = i>>6, o = i&63;
        float2 g = *(const float2*)&g_G[(size_t)(((b*8+ky)*256+u)*64 + o)*2];
        Grr[i] = g.x; Gri[i] = g.y;
    }
    {
        float ss, sc;
        sincospif((float)tid*(1.0f/128.0f), &ss, &sc);
        twi[tid*2] = sc; twi[tid*2+1] = ss;
    }
    if (tid < 64) gw[tid]  = gate_g[l*64+tid];
    if (tid < 64) sb[tid]  = specb_g[l*64+tid];
    if (tid < 32) b1s[tid] = b1_g[l*32+tid];
    if (tid < 64) b2s[tid] = b2_g[l*64+tid];
    __syncthreads();

    int pxg = tid & 63, chg = tid >> 6;
    int v0 = pxg*4, o0 = chg*16;

    // ---- phase 1: acc[8 ch-pairs][4 px] = spec_b + recomb + skip GEMM
    u64 acc[8][4];
    #pragma unroll
    for (int o2 = 0; o2 < 8; o2++){
        u64 ini = pk2(sb[o0+2*o2], sb[o0+2*o2+1]);
        #pragma unroll
        for (int p = 0; p < 4; p++) acc[o2][p] = ini;
    }
    #pragma unroll
    for (int ky = 0; ky < 8; ky++){
        float cw = (ky == 0) ? 1.0f : 2.0f;
        u64 cs2[4], nsn2[4];
        int idx = (ky*v0) & 255;
        #pragma unroll
        for (int p = 0; p < 4; p++){
            float cs = twi[idx*2]*cw, sn = twi[idx*2+1]*cw;
            cs2[p] = pk2(cs, cs); nsn2[p] = pk2(-sn, -sn);
            idx = (idx + ky) & 255;
        }
        const u64* rr = (const u64*)&Grr[ky*64 + o0];
        const u64* ri = (const u64*)&Gri[ky*64 + o0];
        #pragma unroll
        for (int o2 = 0; o2 < 8; o2++){
            u64 gr = rr[o2], gi = ri[o2];
            #pragma unroll
            for (int p = 0; p < 4; p++)
                acc[o2][p] = ffma2(gr, cs2[p], ffma2(gi, nsn2[p], acc[o2][p]));
        }
    }
    for (int i = 0; i < 64; i++){
        float4 hv = *(const float4*)&hs[i*260 + v0];
        u64 h2[4] = {pk2(hv.x,hv.x), pk2(hv.y,hv.y), pk2(hv.z,hv.z), pk2(hv.w,hv.w)};
        const ulonglong2* wp = (const ulonglong2*)&wsk[i*64 + o0];
        #pragma unroll
        for (int qq = 0; qq < 4; qq++){
            ulonglong2 w = wp[qq];
            #pragma unroll
            for (int p = 0; p < 4; p++){
                acc[2*qq][p]   = ffma2(h2[p], w.x, acc[2*qq][p]);
                acc[2*qq+1][p] = ffma2(h2[p], w.y, acc[2*qq+1][p]);
            }
        }
    }
    __syncthreads();   // all phase-1 reads of h_old (hs) done
    #pragma unroll
    for (int o2 = 0; o2 < 8; o2++){
        float lo[4], hi[4];
        #pragma unroll
        for (int p = 0; p < 4; p++) upk2(acc[o2][p], lo[p], hi[p]);
        float4 r0, r1;
        r0.x = gelu_f(lo[0]); r0.y = gelu_f(lo[1]); r0.z = gelu_f(lo[2]); r0.w = gelu_f(lo[3]);
        r1.x = gelu_f(hi[0]); r1.y = gelu_f(hi[1]); r1.z = gelu_f(hi[2]); r1.w = gelu_f(hi[3]);
        *(float4*)&hs[(o0+2*o2)*260   + v0] = r0;
        *(float4*)&hs[(o0+2*o2+1)*260 + v0] = r1;
    }
    __syncthreads();

    // ---- phase 2 (single pass): m-channels jb..jb+7 over one t-scan
    int jb = chg*8;
    u64 m2[4][4];
    #pragma unroll
    for (int qq = 0; qq < 4; qq++){
        u64 ini = pk2(b1s[jb+2*qq], b1s[jb+2*qq+1]);
        #pragma unroll
        for (int p = 0; p < 4; p++) m2[qq][p] = ini;
    }
    for (int i = 0; i < 64; i++){
        float4 tv = *(const float4*)&hs[i*260 + v0];
        u64 t2[4] = {pk2(tv.x,tv.x), pk2(tv.y,tv.y), pk2(tv.z,tv.z), pk2(tv.w,tv.w)};
        const ulonglong2* wp = (const ulonglong2*)&w1[i*32 + jb];
        ulonglong2 wa = wp[0], wb = wp[1];
        #pragma unroll
        for (int p = 0; p < 4; p++){
            m2[0][p] = ffma2(t2[p], wa.x, m2[0][p]);
            m2[1][p] = ffma2(t2[p], wa.y, m2[1][p]);
            m2[2][p] = ffma2(t2[p], wb.x, m2[2][p]);
            m2[3][p] = ffma2(t2[p], wb.y, m2[3][p]);
        }
    }
    // init out with gate (row = h_old in gmem, L1-resident) + b2 while t-reads drain
    u64 out[8][4];
    #pragma unroll
    for (int o2 = 0; o2 < 8; o2++){
        float4 ha = *(const float4*)&row[(o0+2*o2)*256   + v0];
        float4 hb = *(const float4*)&row[(o0+2*o2+1)*256 + v0];
        float g0 = gw[o0+2*o2], g1 = gw[o0+2*o2+1];
        float B0 = b2s[o0+2*o2], B1 = b2s[o0+2*o2+1];
        out[o2][0] = pk2(fmaf(g0,ha.x,B0), fmaf(g1,hb.x,B1));
        out[o2][1] = pk2(fmaf(g0,ha.y,B0), fmaf(g1,hb.y,B1));
        out[o2][2] = pk2(fmaf(g0,ha.z,B0), fmaf(g1,hb.z,B1));
        out[o2][3] = pk2(fmaf(g0,ha.w,B0), fmaf(g1,hb.w,B1));
    }
    __syncthreads();   // all t-reads done; hs rows 0..31 now reusable for m
    #pragma unroll
    for (int qq = 0; qq < 4; qq++){
        float lo[4], hi[4];
        #pragma unroll
        for (int p = 0; p < 4; p++) upk2(m2[qq][p], lo[p], hi[p]);
        float4 r0, r1;
        r0.x = gelu_f(lo[0]); r0.y = gelu_f(lo[1]); r0.z = gelu_f(lo[2]); r0.w = gelu_f(lo[3]);
        r1.x = gelu_f(hi[0]); r1.y = gelu_f(hi[1]); r1.z = gelu_f(hi[2]); r1.w = gelu_f(hi[3]);
        *(float4*)&hs[(jb+2*qq)*260   + v0] = r0;
        *(float4*)&hs[(jb+2*qq+1)*260 + v0] = r1;
    }
    __syncthreads();

    // ---- phase 3: single 32-j pass reading m from hs rows 0..31
    for (int j = 0; j < 32; j++){
        float4 mv = *(const float4*)&hs[j*260 + v0];
        u64 mvp[4] = {pk2(mv.x,mv.x), pk2(mv.y,mv.y), pk2(mv.z,mv.z), pk2(mv.w,mv.w)};
        const ulonglong2* wp = (const ulonglong2*)&w2[j*64 + o0];
        #pragma unroll
        for (int qq = 0; qq < 4; qq++){
            ulonglong2 w = wp[qq];
            #pragma unroll
            for (int p = 0; p < 4; p++){
                out[2*qq][p]   = ffma2(mvp[p], w.x, out[2*qq][p]);
                out[2*qq+1][p] = ffma2(mvp[p], w.y, out[2*qq+1][p]);
            }
        }
    }
    __syncthreads();   // all m-reads done; hs now reusable for h_new

    bool dog = (l < 3);
    #pragma unroll
    for (int o2 = 0; o2 < 8; o2++){
        float lo[4], hi[4];
        #pragma unroll
        for (int p = 0; p < 4; p++) upk2(out[o2][p], lo[p], hi[p]);
        if (dog){
            #pragma unroll
            for (int p = 0; p < 4; p++){ lo[p] = gelu_f(lo[p]); hi[p] = gelu_f(hi[p]); }
        }
        float4 r0, r1;
        r0.x = lo[0]; r0.y = lo[1]; r0.z = lo[2]; r0.w = lo[3];
        r1.x = hi[0]; r1.y = hi[1]; r1.z = hi[2]; r1.w = hi[3];
        *(float4*)&hs[(o0+2*o2)*260   + v0] = r0;
        *(float4*)&hs[(o0+2*o2+1)*260 + v0] = r1;
        *(float4*)&row[(o0+2*o2)*256   + v0] = r0;
        *(float4*)&row[(o0+2*o2+1)*256 + v0] = r1;
    }

    // ---- epilogue: stage-1 DFT of h_new; per-ky sequential twiddle tables
    if (do_dft){
        __syncthreads();   // hs complete everywhere; w1/w2 regions now dead
        {   // build tw8[ky][v] (u64) in the dead w1+w2 region from twi
            u64* t8u = (u64*)tw8;
            const u64* twb = (const u64*)twi;
            #pragma unroll
            for (int r = 0; r < 8; r++){
                int e = tid + r*256;
                int ky = e >> 8, v = e & 255;
                t8u[e] = twb[(ky*v)&255];
            }
        }
        __syncthreads();
        int c = tid & 63, qd = tid >> 6;
        const u64* t8 = (const u64*)tw8;
        u64 a[8];
        #pragma unroll
        for (int k = 0; k < 8; k++) a[k] = pk2(0.f, 0.f);
        const float* hc = &hs[c*260 + qd*64];
        int vb = qd*64;
        for (int vv = 0; vv < 64; vv += 4){
            float4 xv = *(const float4*)&hc[vv];
            u64 x0 = pk2(xv.x,xv.x), x1 = pk2(xv.y,xv.y);
            u64 x2 = pk2(xv.z,xv.z), x3 = pk2(xv.w,xv.w);
            #pragma unroll
            for (int k = 0; k < 8; k++){
                const u64* tk = t8 + k*256 + vb + vv;
                a[k] = ffma2(x0, tk[0], a[k]);
                a[k] = ffma2(x1, tk[1], a[k]);
                a[k] = ffma2(x2, tk[2], a[k]);
                a[k] = ffma2(x3, tk[3], a[k]);
            }
        }
        #pragma unroll
        for (int k = 0; k < 8; k++){
            float sr, si; upk2(a[k], sr, si);
            *(float2*)&red[((qd*64+c)*8+k)*2] = make_float2(sr, si);
        }
        __syncthreads();
        const float scale = 1.0f/65536.0f;
        #pragma unroll
        for (int rep = 0; rep < 2; rep++){
            int idx = tid + rep*256;
            int ky = idx >> 6, cc = idx & 63;
            float sr = 0.f, si = 0.f;
            #pragma unroll
            for (int q2 = 0; q2 < 4; q2++){
                float2 t = *(const float2*)&red[((q2*64+cc)*8+ky)*2];
                sr += t.x; si += t.y;
            }
            float* o = g_Y + (size_t)(((b*8+ky)*256+u)*64 + cc)*2;
            o[0] = sr*scale; o[1] = -si*scale;   // tw8 is e^{+i}, conjugate here
        }
    }
}

// ---------------- projection: 64 -> 128 -> gelu -> 3, + input residual ------
__global__ __launch_bounds__(256,2) void k_proj(const float* __restrict__ x,
                      const float* __restrict__ b1g, const float* __restrict__ w2g,
                      const float* __restrict__ b2g, float* __restrict__ out){
    extern __shared__ float sm[];
    float* hsp = sm;            // 64*68 = 4352
    float* t2p = hsp + 4352;    // 64*132 = 8448  pair-packed: [j2][px*2 + half]
    float* w1s = t2p + 8448;    // 64*128 [k][o]
    float* b1s = w1s + 8192;    // 128
    int tid = threadIdx.x;
    int blk = blockIdx.x;
    int q = blk & 3, u = (blk>>2) & 255, b = blk >> 10;
    const float* row = g_h + (size_t)(b*256+u)*64*256 + q*64;
    for (int i = tid; i < 1024; i += 256){
        int c = i>>4, v4 = i&15;
        *(float4*)&hsp[c*68 + v4*4] = *(const float4*)&row[c*256 + v4*4];
    }
    for (int i = tid; i < 2048; i += 256) ((float4*)w1s)[i] = ((const float4*)g_Wp1)[i];
    if (tid < 128) b1s[tid] = b1g[tid];
    __syncthreads();
    {
        int pxg = tid & 31, chg = tid >> 5;
        int o0 = chg*16;
        u64 a[8][2];
        #pragma unroll
        for (int o2 = 0; o2 < 8; o2++){
            u64 ini = pk2(b1s[o0+2*o2], b1s[o0+2*o2+1]);
            a[o2][0] = ini; a[o2][1] = ini;
        }
        #pragma unroll 4
        for (int k = 0; k < 64; k++){
            float2 tv = *(const float2*)&hsp[k*68 + pxg*2];
            u64 t20 = pk2(tv.x, tv.x), t21 = pk2(tv.y, tv.y);
            const ulonglong2* wp = (const ulonglong2*)&w1s[k*128 + o0];
            #pragma unroll
            for (int qq = 0; qq < 4; qq++){
                ulonglong2 w = wp[qq];
                a[2*qq][0]   = ffma2(t20, w.x, a[2*qq][0]);
                a[2*qq][1]   = ffma2(t21, w.x, a[2*qq][1]);
                a[2*qq+1][0] = ffma2(t20, w.y, a[2*qq+1][0]);
                a[2*qq+1][1] = ffma2(t21, w.y, a[2*qq+1][1]);
            }
        }
        #pragma unroll
        for (int o2 = 0; o2 < 8; o2++){
            float e0, d0, e1, d1;
            upk2(a[o2][0], e0, d0);
            upk2(a[o2][1], e1, d1);
            int j2 = (o0>>1) + o2;
            float* tp = &t2p[j2*132 + pxg*4];
            tp[0] = gelu_f(e0); tp[1] = gelu_f(d0);
            tp[2] = gelu_f(e1); tp[3] = gelu_f(d1);
        }
    }
    __syncthreads();
    if (tid < 192){
        int c = tid >> 6, vv = tid & 63;
        u64 a2 = pk2(0.f, 0.f);
        const u64* wg = (const u64*)(w2g + c*128);
        #pragma unroll 4
        for (int j2 = 0; j2 < 64; j2++){
            u64 tv = *(const u64*)&t2p[j2*132 + vv*2];
            a2 = ffma2(tv, wg[j2], a2);
        }
        float s0, s1; upk2(a2, s0, s1);
        size_t gi = (size_t)((b*3+c)*256+u)*256 + q*64 + vv;
        out[gi] = s0 + s1 + b2g[c] + x[gi];
    }
}

// ---------------- host launch ------------------------------------------------
extern "C" void kernel_launch(void* const* d_in, const int* in_sizes, int n_in,
                              void* d_out, int out_size){
    (void)in_sizes; (void)n_in; (void)out_size;
    const float* x       = (const float*)d_in[0];
    const float* lift_w1 = (const float*)d_in[1];
    const float* lift_b1 = (const float*)d_in[2];
    const float* lift_w2 = (const float*)d_in[3];
    const float* lift_b2 = (const float*)d_in[4];
    const float* swr1    = (const float*)d_in[5];
    const float* swi1    = (const float*)d_in[6];
    const float* swr2    = (const float*)d_in[7];
    const float* swi2    = (const float*)d_in[8];
    const float* spec_b  = (const float*)d_in[9];
    const float* skw     = (const float*)d_in[10];
    const float* gate    = (const float*)d_in[11];
    const float* mw1     = (const float*)d_in[12];
    const float* mb1     = (const float*)d_in[13];
    const float* mw2     = (const float*)d_in[14];
    const float* mb2     = (const float*)d_in[15];
    const float* pw1     = (const float*)d_in[16];
    const float* pb1     = (const float*)d_in[17];
    const float* pw2     = (const float*)d_in[18];
    const float* pb2     = (const float*)d_in[19];
    float* out = (float*)d_out;

    const int SM_LIFT = 28096 * 4;                                    // 112384
    const int SM_DFT1 = (16640 + 4096 + 4096) * 4;                    // 99328
    const int SM_FUSE = 26592 * 4;                                    // 106368
    const int SM_PROJ = (4352 + 8448 + 8192 + 128) * 4;               // 84480

    cudaFuncSetAttribute(k_lift, cudaFuncAttributeMaxDynamicSharedMemorySize, SM_LIFT);
    cudaFuncSetAttribute(k_dft1, cudaFuncAttributeMaxDynamicSharedMemorySize, SM_DFT1);
    cudaFuncSetAttribute(k_fuse, cudaFuncAttributeMaxDynamicSharedMemorySize, SM_FUSE);
    cudaFuncSetAttribute(k_proj, cudaFuncAttributeMaxDynamicSharedMemorySize, SM_PROJ);

    k_reorder<<<224, 256>>>(lift_w2, pw1, skw, mw1, mw2);
    k_lift<<<BB*HH*2, 256, SM_LIFT>>>(x, lift_w1, lift_b1, lift_b2);
    k_dft1<<<BB*HH, 256, SM_DFT1>>>();           // once, after lift
    for (int l = 0; l < 4; l++){
        k_dft2 <<<BB*NKY*NKX, 256>>>();
        k_mix  <<<NKX*NKY, 256>>>(l, swr1, swi1, swr2, swi2);
        k_idft1<<<BB*NKY*8, 256>>>();
        k_fuse <<<BB*HH, 256, SM_FUSE>>>(l, (l < 3) ? 1 : 0,
                                         gate, spec_b, mb1, mb2);
    }
    k_proj<<<BB*HH*4, 256, SM_PROJ>>>(x, pb1, pw2, pb2, out);
}

// round 15
// speedup vs baseline: 1.2253x; 1.0779x over previous
#include <cuda_runtime.h>
#include <math.h>

// Problem constants
#define BB 8
#define HH 256
#define WW 256
#define CC 64
#define NKY 8
#define NKX 16

typedef unsigned long long u64;

// ---------------- scratch (static device memory; no allocations) ------------
__device__ float g_h[BB*HH*CC*WW];        // h field, layout [b][u][c][v]  (128MB)
__device__ float g_Y[BB*NKY*HH*CC*2];     // stage-1 DFT  [b][ky][u][c][re,im]
__device__ float g_F[BB*NKY*NKX*CC*2];    // modes        [b][ky][s][c][re,im]
__device__ float g_OF[BB*NKY*NKX*CC*2];   // mixed modes  (same layout)
__device__ float g_G[BB*NKY*HH*CC*2];     // inverse stage [b][ky][u][o][re,im]
__device__ float g_Wl2[256*64];           // lift_w2 transposed [k][o], tf32-rounded
__device__ float g_Wp1[64*128];           // proj_w1 transposed [k][o]
__device__ float g_Wfsk[4*64*64];         // fno skip, [l][i][o], tf32-rounded
__device__ float g_Wf1[4*64*32];          // mlp w1,   [l][i][j], tf32-rounded
__device__ float g_Wf2[4*32*64];          // mlp w2,   [l][j][o], tf32-rounded

// ---- gelu via hardware tanh (1 MUFU op) ------------------------------------
__device__ __forceinline__ float gelu_f(float x){
    float x2 = x*x;
    float inner = fmaf(fmaf(0.0356774081f, x2, 0.7978845608f), x, 0.0f);
    float t;
    asm("tanh.approx.f32 %0,%1;" : "=f"(t) : "f"(inner));
    return 0.5f*x*(1.0f + t);
}

// ---- packed fp32x2 helpers --------------------------------------------------
__device__ __forceinline__ u64 pk2(float lo, float hi){
    u64 r; asm("mov.b64 %0,{%1,%2};" : "=l"(r) : "f"(lo), "f"(hi)); return r;
}
__device__ __forceinline__ void upk2(u64 v, float& lo, float& hi){
    asm("mov.b64 {%0,%1},%2;" : "=f"(lo), "=f"(hi) : "l"(v));
}
__device__ __forceinline__ u64 ffma2(u64 a, u64 b, u64 c){
    u64 r; asm("fma.rn.f32x2 %0,%1,%2,%3;" : "=l"(r) : "l"(a), "l"(b), "l"(c)); return r;
}
__device__ __forceinline__ unsigned tf32_rna(float x){
    unsigned r; asm("cvt.rna.tf32.f32 %0,%1;" : "=r"(r) : "f"(x)); return r;
}
#define MMA_TF32(accv, A0, A1, A2, A3, B0, B1) \
    asm volatile( \
        "mma.sync.aligned.m16n8k8.row.col.f32.tf32.tf32.f32 " \
        "{%0,%1,%2,%3},{%4,%5,%6,%7},{%8,%9},{%0,%1,%2,%3};" \
        : "+f"((accv)[0]), "+f"((accv)[1]), "+f"((accv)[2]), "+f"((accv)[3]) \
        : "r"(A0), "r"(A1), "r"(A2), "r"(A3), "r"(B0), "r"(B1))

// ---------------- one-time (per launch) weight transposes --------------------
__global__ void k_reorder(const float* __restrict__ lw2, const float* __restrict__ pw1,
                          const float* __restrict__ skw, const float* __restrict__ mw1,
                          const float* __restrict__ mw2){
    int e = blockIdx.x*256 + threadIdx.x;
    if (e < 16384){ int k = e>>6, o = e&63;
        ((unsigned*)g_Wl2)[e] = tf32_rna(lw2[o*256+k]); }
    else if (e < 24576){ int i = e-16384; int k = i>>7, o = i&127; g_Wp1[i] = pw1[o*64+k]; }
    else if (e < 40960){ int i = e-24576; int l = i>>12; int r = i&4095;
                         int ii = r>>6, o = r&63;
                         ((unsigned*)g_Wfsk)[i] = tf32_rna(skw[l*4096 + o*64 + ii]); }
    else if (e < 49152){ int i = e-40960; int l = i>>11; int r = i&2047;
                         int ii = r>>5, j = r&31;
                         ((unsigned*)g_Wf1)[i] = tf32_rna(mw1[l*2048 + j*64 + ii]); }
    else if (e < 57344){ int i = e-49152; int l = i>>11; int r = i&2047;
                         int j = r>>6, o = r&63;
                         ((unsigned*)g_Wf2)[i] = tf32_rna(mw2[l*2048 + o*32 + j]); }
}

// ---------------- lifting via tf32 MMA (unchanged from R14) ------------------
__global__ __launch_bounds__(256,2) void k_lift(const float* __restrict__ x,
                       const float* __restrict__ w1, const float* __restrict__ b1,
                       const float* __restrict__ b2){
    extern __shared__ float sm[];
    float* t1  = sm;               // 128*136 = 17408 (tf32 bits)
    float* w2h = t1 + 17408;       // 128*72 = 9216
    float* w1s = w2h + 9216;       // 768
    float* b1s = w1s + 768;        // 256
    float* b2s = b1s + 256;        // 64
    float* xs  = b2s + 64;         // 384
    int tid = threadIdx.x;
    int blk = blockIdx.x;
    int q = blk & 1, u = (blk>>1) & 255, b = blk >> 9;
    int lane = tid & 31, w = tid >> 5;
    int g = lane >> 2, t = lane & 3;
    int mb = w & 3, nh = w >> 2;

    for (int i = tid; i < 768; i += 256) w1s[i] = w1[i];
    if (tid < 256) b1s[tid] = b1[tid];
    if (tid < 64)  b2s[tid] = b2[tid];
    for (int i = tid; i < 384; i += 256){
        int c = i>>7, v = i&127;
        xs[i] = x[((b*3+c)*256+u)*256 + q*128 + v];
    }
    __syncthreads();

    float acc[8][4];
    {
        float bl = b2s[mb*16 + g], bh = b2s[mb*16 + 8 + g];
        #pragma unroll
        for (int nt = 0; nt < 8; nt++){
            acc[nt][0] = bl; acc[nt][1] = bl;
            acc[nt][2] = bh; acc[nt][3] = bh;
        }
    }

    for (int p = 0; p < 2; p++){
        for (int i = tid; i < 8192; i += 256){
            int kk = i>>6, o = i&63;
            w2h[kk*72 + o] = g_Wl2[p*8192 + i];
        }
        for (int it = tid; it < 16384; it += 256){
            int kk = it >> 7, vx = it & 127;
            int c = p*128 + kk;
            float s = fmaf(w1s[c*3+0], xs[vx],
                      fmaf(w1s[c*3+1], xs[128+vx],
                      fmaf(w1s[c*3+2], xs[256+vx], b1s[c])));
            ((unsigned*)t1)[kk*136 + vx] = tf32_rna(gelu_f(s));
        }
        __syncthreads();

        const unsigned* t1u = (const unsigned*)t1;
        const unsigned* w2u = (const unsigned*)w2h;
        #pragma unroll 2
        for (int ks = 0; ks < 16; ks++){
            int k0 = ks*8;
            unsigned a0 = w2u[(k0+t)*72   + mb*16 + g];
            unsigned a1 = w2u[(k0+t)*72   + mb*16 + 8 + g];
            unsigned a2 = w2u[(k0+t+4)*72 + mb*16 + g];
            unsigned a3 = w2u[(k0+t+4)*72 + mb*16 + 8 + g];
            #pragma unroll
            for (int nt = 0; nt < 8; nt++){
                int n0 = nh*64 + nt*8;
                unsigned bb0 = t1u[(k0+t)*136   + n0 + g];
                unsigned bb1 = t1u[(k0+t+4)*136 + n0 + g];
                MMA_TF32(acc[nt], a0, a1, a2, a3, bb0, bb1);
            }
        }
        __syncthreads();
    }

    float* outrow = g_h + (size_t)((b*256+u)*64)*256 + q*128;
    #pragma unroll
    for (int nt = 0; nt < 8; nt++){
        int pxl = nh*64 + nt*8 + 2*t;
        *(float2*)&outrow[(mb*16 + g)*256     + pxl] = make_float2(acc[nt][0], acc[nt][1]);
        *(float2*)&outrow[(mb*16 + 8 + g)*256 + pxl] = make_float2(acc[nt][2], acc[nt][3]);
    }
}

// ---------------- DFT stage 1 (over v): runs ONCE after lift -----------------
__global__ __launch_bounds__(256) void k_dft1(){
    extern __shared__ float sm[];
    float* hs  = sm;            // 64*260 = 16640
    float* tw8 = hs + 16640;    // 4096
    float* red = tw8 + 4096;    // 4096
    int tid = threadIdx.x;
    int u = blockIdx.x & 255, b = blockIdx.x >> 8;
    const float* row = g_h + (size_t)(b*256+u)*64*256;
    const float4* rw4 = (const float4*)row;
    for (int i = tid; i < 4096; i += 256){
        int c = i>>6, v4 = i&63;
        *(float4*)&hs[c*260 + v4*4] = rw4[i];
    }
    {
        float ss, sc;
        sincospif((float)tid*(1.0f/128.0f), &ss, &sc);
        tw8[(256+tid)*2] = sc; tw8[(256+tid)*2+1] = ss;
    }
    __syncthreads();
    {
        u64* t8u = (u64*)tw8;
        const u64* basew = (const u64*)tw8 + 256;
        #pragma unroll
        for (int r = 0; r < 8; r++){
            int e = tid + r*256;
            int ky = e >> 8, v = e & 255;
            if (ky != 1) t8u[e] = basew[(ky*v)&255];
        }
    }
    __syncthreads();
    int c = tid & 63, qd = tid >> 6;
    const u64* t8 = (const u64*)tw8;
    u64 a[8];
    #pragma unroll
    for (int k = 0; k < 8; k++) a[k] = pk2(0.f, 0.f);
    const float* hc = &hs[c*260 + qd*64];
    int vb = qd*64;
    for (int vv = 0; vv < 64; vv += 4){
        float4 xv = *(const float4*)&hc[vv];
        u64 x0 = pk2(xv.x,xv.x), x1 = pk2(xv.y,xv.y);
        u64 x2 = pk2(xv.z,xv.z), x3 = pk2(xv.w,xv.w);
        #pragma unroll
        for (int k = 0; k < 8; k++){
            const u64* tk = t8 + k*256 + vb + vv;
            a[k] = ffma2(x0, tk[0], a[k]);
            a[k] = ffma2(x1, tk[1], a[k]);
            a[k] = ffma2(x2, tk[2], a[k]);
            a[k] = ffma2(x3, tk[3], a[k]);
        }
    }
    #pragma unroll
    for (int k = 0; k < 8; k++){
        float sr, si; upk2(a[k], sr, si);
        *(float2*)&red[((qd*64+c)*8+k)*2] = make_float2(sr, si);
    }
    __syncthreads();
    const float scale = 1.0f/65536.0f;
    #pragma unroll
    for (int rep = 0; rep < 2; rep++){
        int idx = tid + rep*256;
        int ky = idx >> 6, cc = idx & 63;
        float sr = 0.f, si = 0.f;
        #pragma unroll
        for (int q2 = 0; q2 < 4; q2++){
            float2 t = *(const float2*)&red[((q2*64+cc)*8+ky)*2];
            sr += t.x; si += t.y;
        }
        float* o = g_Y + (size_t)(((b*8+ky)*256+u)*64 + cc)*2;
        o[0] = sr*scale; o[1] = -si*scale;
    }
}

// ---------------- DFT stage 2 (over u): grid B*KY*KX = 1024 -----------------
__global__ __launch_bounds__(256) void k_dft2(){
    __shared__ float tc[256], tsp[256];
    __shared__ float red[4*64*2];
    int tid = threadIdx.x;
    int blk = blockIdx.x;
    int s = blk & 15, ky = (blk>>4) & 7, b = blk >> 7;
    int kxe = (s < 8) ? s : s - 16;
    {
        float ss, sc;
        sincospif((float)tid*(1.0f/128.0f), &ss, &sc);
        tc[tid] = sc; tsp[tid] = ss;
    }
    __syncthreads();
    int uc = tid >> 6, c = tid & 63;
    float sr = 0.f, si = 0.f;
    const float* Yb = g_Y + (size_t)((b*8+ky)*256)*128;
    int u0 = uc*64;
    int t = (kxe*u0) & 255;
    for (int uu = 0; uu < 64; uu++){
        float2 y = *(const float2*)(Yb + (u0+uu)*128 + c*2);
        float cc = tc[t], sv = tsp[t];
        t = (t + kxe) & 255;
        sr = fmaf(y.x, cc, fmaf( y.y, sv, sr));
        si = fmaf(y.y, cc, fmaf(-y.x, sv, si));
    }
    red[(uc*64+c)*2]   = sr;
    red[(uc*64+c)*2+1] = si;
    __syncthreads();
    if (tid < 64){
        float ar = red[tid*2]       + red[(64+tid)*2]
                 + red[(128+tid)*2] + red[(192+tid)*2];
        float ai = red[tid*2+1]       + red[(64+tid)*2+1]
                 + red[(128+tid)*2+1] + red[(192+tid)*2+1];
        float* o = g_F + (size_t)(((b*8+ky)*16+s)*64 + tid)*2;
        o[0] = ar; o[1] = ai;
    }
}

// ---------------- mode mixing ------------------------------------------------
__global__ __launch_bounds__(256) void k_mix(int l, const float* __restrict__ wr1,
                      const float* __restrict__ wi1, const float* __restrict__ wr2,
                      const float* __restrict__ wi2){
    __shared__ float Fs[8*64*2];
    __shared__ float Wm[64*64*2];
    int tid = threadIdx.x;
    int s = blockIdx.x >> 3, ky = blockIdx.x & 7;
    const float* wr = (s < 8) ? wr1 : wr2;
    const float* wi = (s < 8) ? wi1 : wi2;
    int kxh = s & 7;
    for (int i = tid; i < 8*64*2; i += 256){
        int b = i >> 7, r = i & 127;
        Fs[i] = g_F[(size_t)(((b*8+ky)*16+s)*64)*2 + r];
    }
    for (int i = tid; i < 4096; i += 256){
        int ii = i >> 6, o = i & 63;
        int src = (((l*64+ii)*64+o)*8 + kxh)*8 + ky;
        Wm[i*2]   = wr[src];
        Wm[i*2+1] = wi[src];
    }
    __syncthreads();
    #pragma unroll
    for (int p = 0; p < 2; p++){
        int gid = tid + p*256;
        int b = gid >> 6, o = gid & 63;
        float ar = 0.f, ai = 0.f;
        const float2* fp = (const float2*)&Fs[b*128];
        const float2* wp = (const float2*)Wm;
        #pragma unroll 4
        for (int i2 = 0; i2 < 64; i2++){
            float2 f = fp[i2];
            float2 w = wp[i2*64 + o];
            ar = fmaf(f.x, w.x, fmaf(-f.y, w.y, ar));
            ai = fmaf(f.x, w.y, fmaf( f.y, w.x, ai));
        }
        float* ot = g_OF + (size_t)(((b*8+ky)*16+s)*64 + o)*2;
        ot[0] = ar; ot[1] = ai;
    }
}

// ---------------- inverse over kx: grid B*KY*8 = 512 -------------------------
__global__ __launch_bounds__(256) void k_idft1(){
    __shared__ float OFs[16*64*2];
    int tid = threadIdx.x;
    int blk = blockIdx.x;
    int uq = blk & 7, ky = (blk>>3) & 7, b = blk >> 6;
    for (int i = tid; i < 2048; i += 256)
        OFs[i] = g_OF[(size_t)((b*8+ky)*16*64)*2 + i];
    __syncthreads();
    int u = uq*32 + (tid & 31);
    int og = tid >> 5, o0 = og*8;
    float ar[8], ai[8];
    #pragma unroll
    for (int j = 0; j < 8; j++){ ar[j] = 0.f; ai[j] = 0.f; }
    for (int s = 0; s < 16; s++){
        int kxe = (s < 8) ? s : s - 16;
        float ss, sc;
        sincospif((float)(kxe*u)*(1.0f/128.0f), &ss, &sc);
        const float2* op = (const float2*)&OFs[(s*64+o0)*2];
        #pragma unroll
        for (int j = 0; j < 8; j++){
            float2 f = op[j];
            ar[j] = fmaf(f.x, sc, fmaf(-f.y, ss, ar[j]));
            ai[j] = fmaf(f.x, ss, fmaf( f.y, sc, ai[j]));
        }
    }
    float* o = g_G + (size_t)(((b*8+ky)*256+u)*64 + o0)*2;
    #pragma unroll
    for (int j = 0; j < 8; j++){ o[j*2] = ar[j]; o[j*2+1] = ai[j]; }
}

// ---------------- fused per-row layer kernel: tf32 MMA everywhere ------------
// 256 threads, 2 blocks/SM. hs stride 264 (==8 mod 32).
// Phase 1: C[64x256] = [Wsk | Gext](K=80) x [h | twtab]  (+ spec_b)
// Phase 2: m[32x256] = W1 x t;  Phase 3: out = W2 x m + gate*h_old + b2.
__global__ __launch_bounds__(256,2) void k_fuse(int l, int do_dft,
        const float* __restrict__ gate_g, const float* __restrict__ specb_g,
        const float* __restrict__ b1_g, const float* __restrict__ b2_g){
    extern __shared__ float sm[];
    float* hs   = sm;               // 64*264 = 16896
    float* wsk  = hs + 16896;       // 64*72 = 4608   [k=i][o]
    float* Gext = wsk + 4608;       // 16*72 = 1152   [k][o]: rows 0-7 c*Grr, 8-15 -c*Gri
    float* w1   = Gext + 1152;      // 64*40 = 2560   [k=i][j]
    float* w2   = w1 + 2560;        // 32*72 = 2304   [k=j][o]
    float* twi  = w2 + 2304;        // 512 interleaved (cos,sin)
    float* gw   = twi + 512;        // 64
    float* sb   = gw + 64;          // 64
    float* b1s  = sb + 64;          // 32
    float* b2s  = b1s + 32;         // 64   -> total 28256 floats = 113024 B
    float* tw8  = wsk;              // epilogue alias (4096 <= 4608)
    float* red  = Gext;             // epilogue alias (4096 <= 1152+2560+2304)

    int tid = threadIdx.x;
    int u = blockIdx.x & 255, b = blockIdx.x >> 8;
    float* row = g_h + (size_t)(b*256+u)*64*256;
    int lane = tid & 31, w = tid >> 5;
    int g = lane >> 2, t = lane & 3;
    int mb = w & 3, nh = w >> 2;

    {
        const float4* rw4 = (const float4*)row;
        for (int i = tid; i < 4096; i += 256){
            int c = i>>6, v4 = i&63;
            *(float4*)&hs[c*264 + v4*4] = rw4[i];
        }
    }
    for (int i = tid; i < 4096; i += 256){ int ii = i>>6, o = i&63; wsk[ii*72+o] = g_Wfsk[l*4096+i]; }
    for (int i = tid; i < 2048; i += 256){ int ii = i>>5, j = i&31; w1[ii*40+j]  = g_Wf1[l*2048+i]; }
    for (int i = tid; i < 2048; i += 256){ int j = i>>6, o = i&63;  w2[j*72+o]   = g_Wf2[l*2048+i]; }
    for (int i = tid; i < 512; i += 256){
        int ky = i>>6, o = i&63;
        float2 gv = *(const float2*)&g_G[(size_t)(((b*8+ky)*256+u)*64 + o)*2];
        float ck = (ky == 0) ? 1.0f : 2.0f;
        Gext[ky*72 + o]     =  gv.x*ck;
        Gext[(8+ky)*72 + o] = -gv.y*ck;
    }
    {
        float ss, sc;
        sincospif((float)tid*(1.0f/128.0f), &ss, &sc);
        twi[tid*2] = sc; twi[tid*2+1] = ss;
    }
    if (tid < 64) gw[tid]  = gate_g[l*64+tid];
    if (tid < 64) sb[tid]  = specb_g[l*64+tid];
    if (tid < 32) b1s[tid] = b1_g[l*32+tid];
    if (tid < 64) b2s[tid] = b2_g[l*64+tid];
    __syncthreads();

    const unsigned* hsu  = (const unsigned*)hs;
    const unsigned* wsku = (const unsigned*)wsk;
    const unsigned* Gxu  = (const unsigned*)Gext;
    const unsigned* twu  = (const unsigned*)twi;
    const unsigned* w1u  = (const unsigned*)w1;
    const unsigned* w2u  = (const unsigned*)w2;

    // ---- phase 1: t = gelu(spec_b + recomb + Wsk h)  (K=64 + K=16 MMA)
    float acc[16][4];
    {
        float bl = sb[mb*16 + g], bh = sb[mb*16 + 8 + g];
        #pragma unroll
        for (int nt = 0; nt < 16; nt++){
            acc[nt][0] = bl; acc[nt][1] = bl;
            acc[nt][2] = bh; acc[nt][3] = bh;
        }
    }
    #pragma unroll 2
    for (int ks = 0; ks < 8; ks++){
        int k0 = ks*8;
        unsigned a0 = wsku[(k0+t)*72   + mb*16 + g];
        unsigned a1 = wsku[(k0+t)*72   + mb*16 + 8 + g];
        unsigned a2 = wsku[(k0+t+4)*72 + mb*16 + g];
        unsigned a3 = wsku[(k0+t+4)*72 + mb*16 + 8 + g];
        #pragma unroll
        for (int nt = 0; nt < 16; nt++){
            int n0 = nh*128 + nt*8;
            unsigned b0 = hsu[(k0+t)*264   + n0 + g];
            unsigned b1 = hsu[(k0+t+4)*264 + n0 + g];
            MMA_TF32(acc[nt], a0, a1, a2, a3, b0, b1);
        }
    }
    #pragma unroll
    for (int ks = 0; ks < 2; ks++){
        int k0 = ks*8;
        int kr = k0 + t, kr4 = k0 + t + 4;
        unsigned a0 = Gxu[kr*72  + mb*16 + g];
        unsigned a1 = Gxu[kr*72  + mb*16 + 8 + g];
        unsigned a2 = Gxu[kr4*72 + mb*16 + g];
        unsigned a3 = Gxu[kr4*72 + mb*16 + 8 + g];
        int ky0 = kr & 7,  p0 = kr >> 3;
        int ky4 = kr4 & 7, p4 = kr4 >> 3;
        int i0 = (ky0*(nh*128 + g)) & 255;
        int i4 = (ky4*(nh*128 + g)) & 255;
        int s0 = (ky0*8) & 255, s4 = (ky4*8) & 255;
        #pragma unroll
        for (int nt = 0; nt < 16; nt++){
            unsigned b0 = twu[i0*2 + p0];
            unsigned b1 = twu[i4*2 + p4];
            i0 = (i0 + s0) & 255; i4 = (i4 + s4) & 255;
            MMA_TF32(acc[nt], a0, a1, a2, a3, b0, b1);
        }
    }
    __syncthreads();   // all reads of h_old (hs) done
    #pragma unroll
    for (int nt = 0; nt < 16; nt++){
        int n0 = nh*128 + nt*8 + 2*t;
        *(float2*)&hs[(mb*16 + g)*264     + n0] = make_float2(gelu_f(acc[nt][0]), gelu_f(acc[nt][1]));
        *(float2*)&hs[(mb*16 + 8 + g)*264 + n0] = make_float2(gelu_f(acc[nt][2]), gelu_f(acc[nt][3]));
    }
    __syncthreads();

    // ---- phase 2: m = gelu(W1 t + b1), M=32 (warp = (mb2, nq))
    int mb2 = w & 1, nq = w >> 1;
    float am[8][4];
    {
        float bl = b1s[mb2*16 + g], bh = b1s[mb2*16 + 8 + g];
        #pragma unroll
        for (int nt = 0; nt < 8; nt++){
            am[nt][0] = bl; am[nt][1] = bl;
            am[nt][2] = bh; am[nt][3] = bh;
        }
    }
    #pragma unroll 2
    for (int ks = 0; ks < 8; ks++){
        int k0 = ks*8;
        unsigned a0 = w1u[(k0+t)*40   + mb2*16 + g];
        unsigned a1 = w1u[(k0+t)*40   + mb2*16 + 8 + g];
        unsigned a2 = w1u[(k0+t+4)*40 + mb2*16 + g];
        unsigned a3 = w1u[(k0+t+4)*40 + mb2*16 + 8 + g];
        #pragma unroll
        for (int nt = 0; nt < 8; nt++){
            int n0 = nq*64 + nt*8;
            unsigned b0 = hsu[(k0+t)*264   + n0 + g];
            unsigned b1 = hsu[(k0+t+4)*264 + n0 + g];
            MMA_TF32(am[nt], a0, a1, a2, a3, b0, b1);
        }
    }
    __syncthreads();   // all t reads done; rows 0..31 reusable for m
    #pragma unroll
    for (int nt = 0; nt < 8; nt++){
        int n0 = nq*64 + nt*8 + 2*t;
        *(float2*)&hs[(mb2*16 + g)*264     + n0] = make_float2(gelu_f(am[nt][0]), gelu_f(am[nt][1]));
        *(float2*)&hs[(mb2*16 + 8 + g)*264 + n0] = make_float2(gelu_f(am[nt][2]), gelu_f(am[nt][3]));
    }
    // gate + bias init for phase 3 (h_old from gmem row; overlaps m-store latency)
    float out[16][4];
    #pragma unroll
    for (int nt = 0; nt < 16; nt++){
        int n0 = nh*128 + nt*8 + 2*t;
        int r0 = mb*16 + g, r1 = r0 + 8;
        float2 ha = *(const float2*)&row[r0*256 + n0];
        float2 hb = *(const float2*)&row[r1*256 + n0];
        out[nt][0] = fmaf(gw[r0], ha.x, b2s[r0]);
        out[nt][1] = fmaf(gw[r0], ha.y, b2s[r0]);
        out[nt][2] = fmaf(gw[r1], hb.x, b2s[r1]);
        out[nt][3] = fmaf(gw[r1], hb.y, b2s[r1]);
    }
    __syncthreads();   // m stores visible

    // ---- phase 3: out += W2 m  (K=32)
    #pragma unroll
    for (int ks = 0; ks < 4; ks++){
        int k0 = ks*8;
        unsigned a0 = w2u[(k0+t)*72   + mb*16 + g];
        unsigned a1 = w2u[(k0+t)*72   + mb*16 + 8 + g];
        unsigned a2 = w2u[(k0+t+4)*72 + mb*16 + g];
        unsigned a3 = w2u[(k0+t+4)*72 + mb*16 + 8 + g];
        #pragma unroll
        for (int nt = 0; nt < 16; nt++){
            int n0 = nh*128 + nt*8;
            unsigned b0 = hsu[(k0+t)*264   + n0 + g];
            unsigned b1 = hsu[(k0+t+4)*264 + n0 + g];
            MMA_TF32(out[nt], a0, a1, a2, a3, b0, b1);
        }
    }
    __syncthreads();   // all m reads done; hs reusable for h_new

    bool dog = (l < 3);
    #pragma unroll
    for (int nt = 0; nt < 16; nt++){
        int n0 = nh*128 + nt*8 + 2*t;
        int r0 = mb*16 + g, r1 = r0 + 8;
        float v0a = out[nt][0], v1a = out[nt][1];
        float v0b = out[nt][2], v1b = out[nt][3];
        if (dog){
            v0a = gelu_f(v0a); v1a = gelu_f(v1a);
            v0b = gelu_f(v0b); v1b = gelu_f(v1b);
        }
        float2 ra = make_float2(v0a, v1a);
        float2 rb = make_float2(v0b, v1b);
        *(float2*)&hs[r0*264 + n0] = ra;
        *(float2*)&hs[r1*264 + n0] = rb;
        *(float2*)&row[r0*256 + n0] = ra;
        *(float2*)&row[r1*256 + n0] = rb;
    }

    // ---- epilogue: stage-1 DFT of h_new
    if (do_dft){
        __syncthreads();   // hs complete; wsk/Gext/w1/w2 regions now dead
        {
            u64* t8u = (u64*)tw8;
            const u64* twb = (const u64*)twi;
            #pragma unroll
            for (int r = 0; r < 8; r++){
                int e = tid + r*256;
                int ky = e >> 8, v = e & 255;
                t8u[e] = twb[(ky*v)&255];
            }
        }
        __syncthreads();
        int c = tid & 63, qd = tid >> 6;
        const u64* t8 = (const u64*)tw8;
        u64 a[8];
        #pragma unroll
        for (int k = 0; k < 8; k++) a[k] = pk2(0.f, 0.f);
        const float* hc = &hs[c*264 + qd*64];
        int vb = qd*64;
        for (int vv = 0; vv < 64; vv += 4){
            float4 xv = *(const float4*)&hc[vv];
            u64 x0 = pk2(xv.x,xv.x), x1 = pk2(xv.y,xv.y);
            u64 x2 = pk2(xv.z,xv.z), x3 = pk2(xv.w,xv.w);
            #pragma unroll
            for (int k = 0; k < 8; k++){
                const u64* tk = t8 + k*256 + vb + vv;
                a[k] = ffma2(x0, tk[0], a[k]);
                a[k] = ffma2(x1, tk[1], a[k]);
                a[k] = ffma2(x2, tk[2], a[k]);
                a[k] = ffma2(x3, tk[3], a[k]);
            }
        }
        #pragma unroll
        for (int k = 0; k < 8; k++){
            float sr, si; upk2(a[k], sr, si);
            *(float2*)&red[((qd*64+c)*8+k)*2] = make_float2(sr, si);
        }
        __syncthreads();
        const float scale = 1.0f/65536.0f;
        #pragma unroll
        for (int rep = 0; rep < 2; rep++){
            int idx = tid + rep*256;
            int ky = idx >> 6, cc = idx & 63;
            float sr = 0.f, si = 0.f;
            #pragma unroll
            for (int q2 = 0; q2 < 4; q2++){
                float2 t2 = *(const float2*)&red[((q2*64+cc)*8+ky)*2];
                sr += t2.x; si += t2.y;
            }
            float* o = g_Y + (size_t)(((b*8+ky)*256+u)*64 + cc)*2;
            o[0] = sr*scale; o[1] = -si*scale;
        }
    }
}

// ---------------- projection: 64 -> 128 -> gelu -> 3, + input residual ------
__global__ __launch_bounds__(256,2) void k_proj(const float* __restrict__ x,
                      const float* __restrict__ b1g, const float* __restrict__ w2g,
                      const float* __restrict__ b2g, float* __restrict__ out){
    extern __shared__ float sm[];
    float* hsp = sm;            // 64*68 = 4352
    float* t2p = hsp + 4352;    // 64*132 = 8448  pair-packed
    float* w1s = t2p + 8448;    // 64*128 [k][o]
    float* b1s = w1s + 8192;    // 128
    int tid = threadIdx.x;
    int blk = blockIdx.x;
    int q = blk & 3, u = (blk>>2) & 255, b = blk >> 10;
    const float* row = g_h + (size_t)(b*256+u)*64*256 + q*64;
    for (int i = tid; i < 1024; i += 256){
        int c = i>>4, v4 = i&15;
        *(float4*)&hsp[c*68 + v4*4] = *(const float4*)&row[c*256 + v4*4];
    }
    for (int i = tid; i < 2048; i += 256) ((float4*)w1s)[i] = ((const float4*)g_Wp1)[i];
    if (tid < 128) b1s[tid] = b1g[tid];
    __syncthreads();
    {
        int pxg = tid & 31, chg = tid >> 5;
        int o0 = chg*16;
        u64 a[8][2];
        #pragma unroll
        for (int o2 = 0; o2 < 8; o2++){
            u64 ini = pk2(b1s[o0+2*o2], b1s[o0+2*o2+1]);
            a[o2][0] = ini; a[o2][1] = ini;
        }
        #pragma unroll 4
        for (int k = 0; k < 64; k++){
            float2 tv = *(const float2*)&hsp[k*68 + pxg*2];
            u64 t20 = pk2(tv.x, tv.x), t21 = pk2(tv.y, tv.y);
            const ulonglong2* wp = (const ulonglong2*)&w1s[k*128 + o0];
            #pragma unroll
            for (int qq = 0; qq < 4; qq++){
                ulonglong2 w = wp[qq];
                a[2*qq][0]   = ffma2(t20, w.x, a[2*qq][0]);
                a[2*qq][1]   = ffma2(t21, w.x, a[2*qq][1]);
                a[2*qq+1][0] = ffma2(t20, w.y, a[2*qq+1][0]);
                a[2*qq+1][1] = ffma2(t21, w.y, a[2*qq+1][1]);
            }
        }
        #pragma unroll
        for (int o2 = 0; o2 < 8; o2++){
            float e0, d0, e1, d1;
            upk2(a[o2][0], e0, d0);
            upk2(a[o2][1], e1, d1);
            int j2 = (o0>>1) + o2;
            float* tp = &t2p[j2*132 + pxg*4];
            tp[0] = gelu_f(e0); tp[1] = gelu_f(d0);
            tp[2] = gelu_f(e1); tp[3] = gelu_f(d1);
        }
    }
    __syncthreads();
    if (tid < 192){
        int c = tid >> 6, vv = tid & 63;
        u64 a2 = pk2(0.f, 0.f);
        const u64* wg = (const u64*)(w2g + c*128);
        #pragma unroll 4
        for (int j2 = 0; j2 < 64; j2++){
            u64 tv = *(const u64*)&t2p[j2*132 + vv*2];
            a2 = ffma2(tv, wg[j2], a2);
        }
        float s0, s1; upk2(a2, s0, s1);
        size_t gi = (size_t)((b*3+c)*256+u)*256 + q*64 + vv;
        out[gi] = s0 + s1 + b2g[c] + x[gi];
    }
}

// ---------------- host launch ------------------------------------------------
extern "C" void kernel_launch(void* const* d_in, const int* in_sizes, int n_in,
                              void* d_out, int out_size){
    (void)in_sizes; (void)n_in; (void)out_size;
    const float* x       = (const float*)d_in[0];
    const float* lift_w1 = (const float*)d_in[1];
    const float* lift_b1 = (const float*)d_in[2];
    const float* lift_w2 = (const float*)d_in[3];
    const float* lift_b2 = (const float*)d_in[4];
    const float* swr1    = (const float*)d_in[5];
    const float* swi1    = (const float*)d_in[6];
    const float* swr2    = (const float*)d_in[7];
    const float* swi2    = (const float*)d_in[8];
    const float* spec_b  = (const float*)d_in[9];
    const float* skw     = (const float*)d_in[10];
    const float* gate    = (const float*)d_in[11];
    const float* mw1     = (const float*)d_in[12];
    const float* mb1     = (const float*)d_in[13];
    const float* mw2     = (const float*)d_in[14];
    const float* mb2     = (const float*)d_in[15];
    const float* pw1     = (const float*)d_in[16];
    const float* pb1     = (const float*)d_in[17];
    const float* pw2     = (const float*)d_in[18];
    const float* pb2     = (const float*)d_in[19];
    float* out = (float*)d_out;

    const int SM_LIFT = 28096 * 4;                                    // 112384
    const int SM_DFT1 = (16640 + 4096 + 4096) * 4;                    // 99328
    const int SM_FUSE = 28256 * 4;                                    // 113024
    const int SM_PROJ = (4352 + 8448 + 8192 + 128) * 4;               // 84480

    cudaFuncSetAttribute(k_lift, cudaFuncAttributeMaxDynamicSharedMemorySize, SM_LIFT);
    cudaFuncSetAttribute(k_dft1, cudaFuncAttributeMaxDynamicSharedMemorySize, SM_DFT1);
    cudaFuncSetAttribute(k_fuse, cudaFuncAttributeMaxDynamicSharedMemorySize, SM_FUSE);
    cudaFuncSetAttribute(k_proj, cudaFuncAttributeMaxDynamicSharedMemorySize, SM_PROJ);

    k_reorder<<<224, 256>>>(lift_w2, pw1, skw, mw1, mw2);
    k_lift<<<BB*HH*2, 256, SM_LIFT>>>(x, lift_w1, lift_b1, lift_b2);
    k_dft1<<<BB*HH, 256, SM_DFT1>>>();           // once, after lift
    for (int l = 0; l < 4; l++){
        k_dft2 <<<BB*NKY*NKX, 256>>>();
        k_mix  <<<NKX*NKY, 256>>>(l, swr1, swi1, swr2, swi2);
        k_idft1<<<BB*NKY*8, 256>>>();
        k_fuse <<<BB*HH, 256, SM_FUSE>>>(l, (l < 3) ? 1 : 0,
                                         gate, spec_b, mb1, mb2);
    }
    k_proj<<<BB*HH*4, 256, SM_PROJ>>>(x, pb1, pw2, pb2, out);
}

// round 16
// speedup vs baseline: 1.2492x; 1.0195x over previous
#include <cuda_runtime.h>
#include <math.h>

// Problem constants
#define BB 8
#define HH 256
#define WW 256
#define CC 64
#define NKY 8
#define NKX 16

typedef unsigned long long u64;

// ---------------- scratch (static device memory; no allocations) ------------
__device__ float g_h[BB*HH*CC*WW];        // h field, layout [b][u][c][v]  (128MB)
__device__ float g_Y[BB*NKY*HH*CC*2];     // stage-1 DFT  [b][ky][u][c][re,im]
__device__ float g_F[BB*NKY*NKX*CC*2];    // modes        [b][ky][s][c][re,im]
__device__ float g_OF[BB*NKY*NKX*CC*2];   // mixed modes  (same layout)
__device__ float g_G[BB*NKY*HH*CC*2];     // inverse stage [b][ky][u][o][re,im]
__device__ float g_Wl2[256*64];           // lift_w2 transposed [k][o], tf32-rounded
__device__ float g_Wp1[64*128];           // proj_w1 transposed [k][o], tf32-rounded
__device__ float g_Wfsk[4*64*64];         // fno skip, [l][i][o], tf32-rounded
__device__ float g_Wf1[4*64*32];          // mlp w1,   [l][i][j], tf32-rounded
__device__ float g_Wf2[4*32*64];          // mlp w2,   [l][j][o], tf32-rounded

// ---- gelu via hardware tanh (1 MUFU op) ------------------------------------
__device__ __forceinline__ float gelu_f(float x){
    float x2 = x*x;
    float inner = fmaf(fmaf(0.0356774081f, x2, 0.7978845608f), x, 0.0f);
    float t;
    asm("tanh.approx.f32 %0,%1;" : "=f"(t) : "f"(inner));
    return 0.5f*x*(1.0f + t);
}

// ---- packed fp32x2 helpers --------------------------------------------------
__device__ __forceinline__ u64 pk2(float lo, float hi){
    u64 r; asm("mov.b64 %0,{%1,%2};" : "=l"(r) : "f"(lo), "f"(hi)); return r;
}
__device__ __forceinline__ void upk2(u64 v, float& lo, float& hi){
    asm("mov.b64 {%0,%1},%2;" : "=f"(lo), "=f"(hi) : "l"(v));
}
__device__ __forceinline__ u64 ffma2(u64 a, u64 b, u64 c){
    u64 r; asm("fma.rn.f32x2 %0,%1,%2,%3;" : "=l"(r) : "l"(a), "l"(b), "l"(c)); return r;
}
__device__ __forceinline__ unsigned tf32_rna(float x){
    unsigned r; asm("cvt.rna.tf32.f32 %0,%1;" : "=r"(r) : "f"(x)); return r;
}
#define MMA_TF32(accv, A0, A1, A2, A3, B0, B1) \
    asm volatile( \
        "mma.sync.aligned.m16n8k8.row.col.f32.tf32.tf32.f32 " \
        "{%0,%1,%2,%3},{%4,%5,%6,%7},{%8,%9},{%0,%1,%2,%3};" \
        : "+f"((accv)[0]), "+f"((accv)[1]), "+f"((accv)[2]), "+f"((accv)[3]) \
        : "r"(A0), "r"(A1), "r"(A2), "r"(A3), "r"(B0), "r"(B1))

// ---------------- one-time (per launch) weight transposes --------------------
__global__ void k_reorder(const float* __restrict__ lw2, const float* __restrict__ pw1,
                          const float* __restrict__ skw, const float* __restrict__ mw1,
                          const float* __restrict__ mw2){
    int e = blockIdx.x*256 + threadIdx.x;
    if (e < 16384){ int k = e>>6, o = e&63;
        ((unsigned*)g_Wl2)[e] = tf32_rna(lw2[o*256+k]); }
    else if (e < 24576){ int i = e-16384; int k = i>>7, o = i&127;
        ((unsigned*)g_Wp1)[i] = tf32_rna(pw1[o*64+k]); }
    else if (e < 40960){ int i = e-24576; int l = i>>12; int r = i&4095;
                         int ii = r>>6, o = r&63;
                         ((unsigned*)g_Wfsk)[i] = tf32_rna(skw[l*4096 + o*64 + ii]); }
    else if (e < 49152){ int i = e-40960; int l = i>>11; int r = i&2047;
                         int ii = r>>5, j = r&31;
                         ((unsigned*)g_Wf1)[i] = tf32_rna(mw1[l*2048 + j*64 + ii]); }
    else if (e < 57344){ int i = e-49152; int l = i>>11; int r = i&2047;
                         int j = r>>6, o = r&63;
                         ((unsigned*)g_Wf2)[i] = tf32_rna(mw2[l*2048 + o*32 + j]); }
}

// ---------------- lifting via tf32 MMA (unchanged from R14/R15) --------------
__global__ __launch_bounds__(256,2) void k_lift(const float* __restrict__ x,
                       const float* __restrict__ w1, const float* __restrict__ b1,
                       const float* __restrict__ b2){
    extern __shared__ float sm[];
    float* t1  = sm;               // 128*136 = 17408 (tf32 bits)
    float* w2h = t1 + 17408;       // 128*72 = 9216
    float* w1s = w2h + 9216;       // 768
    float* b1s = w1s + 768;        // 256
    float* b2s = b1s + 256;        // 64
    float* xs  = b2s + 64;         // 384
    int tid = threadIdx.x;
    int blk = blockIdx.x;
    int q = blk & 1, u = (blk>>1) & 255, b = blk >> 9;
    int lane = tid & 31, w = tid >> 5;
    int g = lane >> 2, t = lane & 3;
    int mb = w & 3, nh = w >> 2;

    for (int i = tid; i < 768; i += 256) w1s[i] = w1[i];
    if (tid < 256) b1s[tid] = b1[tid];
    if (tid < 64)  b2s[tid] = b2[tid];
    for (int i = tid; i < 384; i += 256){
        int c = i>>7, v = i&127;
        xs[i] = x[((b*3+c)*256+u)*256 + q*128 + v];
    }
    __syncthreads();

    float acc[8][4];
    {
        float bl = b2s[mb*16 + g], bh = b2s[mb*16 + 8 + g];
        #pragma unroll
        for (int nt = 0; nt < 8; nt++){
            acc[nt][0] = bl; acc[nt][1] = bl;
            acc[nt][2] = bh; acc[nt][3] = bh;
        }
    }

    for (int p = 0; p < 2; p++){
        for (int i = tid; i < 8192; i += 256){
            int kk = i>>6, o = i&63;
            w2h[kk*72 + o] = g_Wl2[p*8192 + i];
        }
        for (int it = tid; it < 16384; it += 256){
            int kk = it >> 7, vx = it & 127;
            int c = p*128 + kk;
            float s = fmaf(w1s[c*3+0], xs[vx],
                      fmaf(w1s[c*3+1], xs[128+vx],
                      fmaf(w1s[c*3+2], xs[256+vx], b1s[c])));
            ((unsigned*)t1)[kk*136 + vx] = tf32_rna(gelu_f(s));
        }
        __syncthreads();

        const unsigned* t1u = (const unsigned*)t1;
        const unsigned* w2u = (const unsigned*)w2h;
        #pragma unroll 2
        for (int ks = 0; ks < 16; ks++){
            int k0 = ks*8;
            unsigned a0 = w2u[(k0+t)*72   + mb*16 + g];
            unsigned a1 = w2u[(k0+t)*72   + mb*16 + 8 + g];
            unsigned a2 = w2u[(k0+t+4)*72 + mb*16 + g];
            unsigned a3 = w2u[(k0+t+4)*72 + mb*16 + 8 + g];
            #pragma unroll
            for (int nt = 0; nt < 8; nt++){
                int n0 = nh*64 + nt*8;
                unsigned bb0 = t1u[(k0+t)*136   + n0 + g];
                unsigned bb1 = t1u[(k0+t+4)*136 + n0 + g];
                MMA_TF32(acc[nt], a0, a1, a2, a3, bb0, bb1);
            }
        }
        __syncthreads();
    }

    float* outrow = g_h + (size_t)((b*256+u)*64)*256 + q*128;
    #pragma unroll
    for (int nt = 0; nt < 8; nt++){
        int pxl = nh*64 + nt*8 + 2*t;
        *(float2*)&outrow[(mb*16 + g)*256     + pxl] = make_float2(acc[nt][0], acc[nt][1]);
        *(float2*)&outrow[(mb*16 + 8 + g)*256 + pxl] = make_float2(acc[nt][2], acc[nt][3]);
    }
}

// ---------------- DFT stage 1 (over v): runs ONCE after lift -----------------
__global__ __launch_bounds__(256) void k_dft1(){
    extern __shared__ float sm[];
    float* hs  = sm;            // 64*260 = 16640
    float* tw8 = hs + 16640;    // 4096
    float* red = tw8 + 4096;    // 4096
    int tid = threadIdx.x;
    int u = blockIdx.x & 255, b = blockIdx.x >> 8;
    const float* row = g_h + (size_t)(b*256+u)*64*256;
    const float4* rw4 = (const float4*)row;
    for (int i = tid; i < 4096; i += 256){
        int c = i>>6, v4 = i&63;
        *(float4*)&hs[c*260 + v4*4] = rw4[i];
    }
    {
        float ss, sc;
        sincospif((float)tid*(1.0f/128.0f), &ss, &sc);
        tw8[(256+tid)*2] = sc; tw8[(256+tid)*2+1] = ss;
    }
    __syncthreads();
    {
        u64* t8u = (u64*)tw8;
        const u64* basew = (const u64*)tw8 + 256;
        #pragma unroll
        for (int r = 0; r < 8; r++){
            int e = tid + r*256;
            int ky = e >> 8, v = e & 255;
            if (ky != 1) t8u[e] = basew[(ky*v)&255];
        }
    }
    __syncthreads();
    int c = tid & 63, qd = tid >> 6;
    const u64* t8 = (const u64*)tw8;
    u64 a[8];
    #pragma unroll
    for (int k = 0; k < 8; k++) a[k] = pk2(0.f, 0.f);
    const float* hc = &hs[c*260 + qd*64];
    int vb = qd*64;
    for (int vv = 0; vv < 64; vv += 4){
        float4 xv = *(const float4*)&hc[vv];
        u64 x0 = pk2(xv.x,xv.x), x1 = pk2(xv.y,xv.y);
        u64 x2 = pk2(xv.z,xv.z), x3 = pk2(xv.w,xv.w);
        #pragma unroll
        for (int k = 0; k < 8; k++){
            const ulonglong2* tk2 = (const ulonglong2*)(t8 + k*256 + vb + vv);
            ulonglong2 ta = tk2[0], tb = tk2[1];
            a[k] = ffma2(x0, ta.x, a[k]);
            a[k] = ffma2(x1, ta.y, a[k]);
            a[k] = ffma2(x2, tb.x, a[k]);
            a[k] = ffma2(x3, tb.y, a[k]);
        }
    }
    #pragma unroll
    for (int k = 0; k < 8; k++){
        float sr, si; upk2(a[k], sr, si);
        *(float2*)&red[((qd*64+c)*8+k)*2] = make_float2(sr, si);
    }
    __syncthreads();
    const float scale = 1.0f/65536.0f;
    #pragma unroll
    for (int rep = 0; rep < 2; rep++){
        int idx = tid + rep*256;
        int ky = idx >> 6, cc = idx & 63;
        float sr = 0.f, si = 0.f;
        #pragma unroll
        for (int q2 = 0; q2 < 4; q2++){
            float2 t = *(const float2*)&red[((q2*64+cc)*8+ky)*2];
            sr += t.x; si += t.y;
        }
        float* o = g_Y + (size_t)(((b*8+ky)*256+u)*64 + cc)*2;
        o[0] = sr*scale; o[1] = -si*scale;
    }
}

// ---------------- DFT stage 2 (over u): grid B*KY*KX = 1024 -----------------
__global__ __launch_bounds__(256) void k_dft2(){
    __shared__ float tc[256], tsp[256];
    __shared__ float red[4*64*2];
    int tid = threadIdx.x;
    int blk = blockIdx.x;
    int s = blk & 15, ky = (blk>>4) & 7, b = blk >> 7;
    int kxe = (s < 8) ? s : s - 16;
    {
        float ss, sc;
        sincospif((float)tid*(1.0f/128.0f), &ss, &sc);
        tc[tid] = sc; tsp[tid] = ss;
    }
    __syncthreads();
    int uc = tid >> 6, c = tid & 63;
    float sr = 0.f, si = 0.f;
    const float* Yb = g_Y + (size_t)((b*8+ky)*256)*128;
    int u0 = uc*64;
    int t = (kxe*u0) & 255;
    for (int uu = 0; uu < 64; uu++){
        float2 y = *(const float2*)(Yb + (u0+uu)*128 + c*2);
        float cc = tc[t], sv = tsp[t];
        t = (t + kxe) & 255;
        sr = fmaf(y.x, cc, fmaf( y.y, sv, sr));
        si = fmaf(y.y, cc, fmaf(-y.x, sv, si));
    }
    red[(uc*64+c)*2]   = sr;
    red[(uc*64+c)*2+1] = si;
    __syncthreads();
    if (tid < 64){
        float ar = red[tid*2]       + red[(64+tid)*2]
                 + red[(128+tid)*2] + red[(192+tid)*2];
        float ai = red[tid*2+1]       + red[(64+tid)*2+1]
                 + red[(128+tid)*2+1] + red[(192+tid)*2+1];
        float* o = g_F + (size_t)(((b*8+ky)*16+s)*64 + tid)*2;
        o[0] = ar; o[1] = ai;
    }
}

// ---------------- mode mixing ------------------------------------------------
__global__ __launch_bounds__(256) void k_mix(int l, const float* __restrict__ wr1,
                      const float* __restrict__ wi1, const float* __restrict__ wr2,
                      const float* __restrict__ wi2){
    __shared__ float Fs[8*64*2];
    __shared__ float Wm[64*64*2];
    int tid = threadIdx.x;
    int s = blockIdx.x >> 3, ky = blockIdx.x & 7;
    const float* wr = (s < 8) ? wr1 : wr2;
    const float* wi = (s < 8) ? wi1 : wi2;
    int kxh = s & 7;
    for (int i = tid; i < 8*64*2; i += 256){
        int b = i >> 7, r = i & 127;
        Fs[i] = g_F[(size_t)(((b*8+ky)*16+s)*64)*2 + r];
    }
    for (int i = tid; i < 4096; i += 256){
        int ii = i >> 6, o = i & 63;
        int src = (((l*64+ii)*64+o)*8 + kxh)*8 + ky;
        Wm[i*2]   = wr[src];
        Wm[i*2+1] = wi[src];
    }
    __syncthreads();
    #pragma unroll
    for (int p = 0; p < 2; p++){
        int gid = tid + p*256;
        int b = gid >> 6, o = gid & 63;
        float ar = 0.f, ai = 0.f;
        const float2* fp = (const float2*)&Fs[b*128];
        const float2* wp = (const float2*)Wm;
        #pragma unroll 4
        for (int i2 = 0; i2 < 64; i2++){
            float2 f = fp[i2];
            float2 w = wp[i2*64 + o];
            ar = fmaf(f.x, w.x, fmaf(-f.y, w.y, ar));
            ai = fmaf(f.x, w.y, fmaf( f.y, w.x, ai));
        }
        float* ot = g_OF + (size_t)(((b*8+ky)*16+s)*64 + o)*2;
        ot[0] = ar; ot[1] = ai;
    }
}

// ---------------- inverse over kx: grid B*KY*8 = 512 -------------------------
__global__ __launch_bounds__(256) void k_idft1(){
    __shared__ float OFs[16*64*2];
    int tid = threadIdx.x;
    int blk = blockIdx.x;
    int uq = blk & 7, ky = (blk>>3) & 7, b = blk >> 6;
    for (int i = tid; i < 2048; i += 256)
        OFs[i] = g_OF[(size_t)((b*8+ky)*16*64)*2 + i];
    __syncthreads();
    int u = uq*32 + (tid & 31);
    int og = tid >> 5, o0 = og*8;
    float ar[8], ai[8];
    #pragma unroll
    for (int j = 0; j < 8; j++){ ar[j] = 0.f; ai[j] = 0.f; }
    for (int s = 0; s < 16; s++){
        int kxe = (s < 8) ? s : s - 16;
        float ss, sc;
        sincospif((float)(kxe*u)*(1.0f/128.0f), &ss, &sc);
        const float2* op = (const float2*)&OFs[(s*64+o0)*2];
        #pragma unroll
        for (int j = 0; j < 8; j++){
            float2 f = op[j];
            ar[j] = fmaf(f.x, sc, fmaf(-f.y, ss, ar[j]));
            ai[j] = fmaf(f.x, ss, fmaf( f.y, sc, ai[j]));
        }
    }
    float* o = g_G + (size_t)(((b*8+ky)*256+u)*64 + o0)*2;
    #pragma unroll
    for (int j = 0; j < 8; j++){ o[j*2] = ar[j]; o[j*2+1] = ai[j]; }
}

// ---------------- fused per-row layer kernel: tf32 MMA (R15) -----------------
__global__ __launch_bounds__(256,2) void k_fuse(int l, int do_dft,
        const float* __restrict__ gate_g, const float* __restrict__ specb_g,
        const float* __restrict__ b1_g, const float* __restrict__ b2_g){
    extern __shared__ float sm[];
    float* hs   = sm;               // 64*264 = 16896
    float* wsk  = hs + 16896;       // 64*72 = 4608   [k=i][o]
    float* Gext = wsk + 4608;       // 16*72 = 1152
    float* w1   = Gext + 1152;      // 64*40 = 2560   [k=i][j]
    float* w2   = w1 + 2560;        // 32*72 = 2304   [k=j][o]
    float* twi  = w2 + 2304;        // 512 interleaved (cos,sin)
    float* gw   = twi + 512;        // 64
    float* sb   = gw + 64;          // 64
    float* b1s  = sb + 64;          // 32
    float* b2s  = b1s + 32;         // 64   -> total 28256 floats = 113024 B
    float* tw8  = wsk;              // epilogue alias
    float* red  = Gext;             // epilogue alias

    int tid = threadIdx.x;
    int u = blockIdx.x & 255, b = blockIdx.x >> 8;
    float* row = g_h + (size_t)(b*256+u)*64*256;
    int lane = tid & 31, w = tid >> 5;
    int g = lane >> 2, t = lane & 3;
    int mb = w & 3, nh = w >> 2;

    {
        const float4* rw4 = (const float4*)row;
        for (int i = tid; i < 4096; i += 256){
            int c = i>>6, v4 = i&63;
            *(float4*)&hs[c*264 + v4*4] = rw4[i];
        }
    }
    for (int i = tid; i < 4096; i += 256){ int ii = i>>6, o = i&63; wsk[ii*72+o] = g_Wfsk[l*4096+i]; }
    for (int i = tid; i < 2048; i += 256){ int ii = i>>5, j = i&31; w1[ii*40+j]  = g_Wf1[l*2048+i]; }
    for (int i = tid; i < 2048; i += 256){ int j = i>>6, o = i&63;  w2[j*72+o]   = g_Wf2[l*2048+i]; }
    for (int i = tid; i < 512; i += 256){
        int ky = i>>6, o = i&63;
        float2 gv = *(const float2*)&g_G[(size_t)(((b*8+ky)*256+u)*64 + o)*2];
        float ck = (ky == 0) ? 1.0f : 2.0f;
        Gext[ky*72 + o]     =  gv.x*ck;
        Gext[(8+ky)*72 + o] = -gv.y*ck;
    }
    {
        float ss, sc;
        sincospif((float)tid*(1.0f/128.0f), &ss, &sc);
        twi[tid*2] = sc; twi[tid*2+1] = ss;
    }
    if (tid < 64) gw[tid]  = gate_g[l*64+tid];
    if (tid < 64) sb[tid]  = specb_g[l*64+tid];
    if (tid < 32) b1s[tid] = b1_g[l*32+tid];
    if (tid < 64) b2s[tid] = b2_g[l*64+tid];
    __syncthreads();

    const unsigned* hsu  = (const unsigned*)hs;
    const unsigned* wsku = (const unsigned*)wsk;
    const unsigned* Gxu  = (const unsigned*)Gext;
    const unsigned* twu  = (const unsigned*)twi;
    const unsigned* w1u  = (const unsigned*)w1;
    const unsigned* w2u  = (const unsigned*)w2;

    // ---- phase 1: t = gelu(spec_b + recomb + Wsk h)
    float acc[16][4];
    {
        float bl = sb[mb*16 + g], bh = sb[mb*16 + 8 + g];
        #pragma unroll
        for (int nt = 0; nt < 16; nt++){
            acc[nt][0] = bl; acc[nt][1] = bl;
            acc[nt][2] = bh; acc[nt][3] = bh;
        }
    }
    #pragma unroll 2
    for (int ks = 0; ks < 8; ks++){
        int k0 = ks*8;
        unsigned a0 = wsku[(k0+t)*72   + mb*16 + g];
        unsigned a1 = wsku[(k0+t)*72   + mb*16 + 8 + g];
        unsigned a2 = wsku[(k0+t+4)*72 + mb*16 + g];
        unsigned a3 = wsku[(k0+t+4)*72 + mb*16 + 8 + g];
        #pragma unroll
        for (int nt = 0; nt < 16; nt++){
            int n0 = nh*128 + nt*8;
            unsigned b0 = hsu[(k0+t)*264   + n0 + g];
            unsigned b1 = hsu[(k0+t+4)*264 + n0 + g];
            MMA_TF32(acc[nt], a0, a1, a2, a3, b0, b1);
        }
    }
    #pragma unroll
    for (int ks = 0; ks < 2; ks++){
        int k0 = ks*8;
        int kr = k0 + t, kr4 = k0 + t + 4;
        unsigned a0 = Gxu[kr*72  + mb*16 + g];
        unsigned a1 = Gxu[kr*72  + mb*16 + 8 + g];
        unsigned a2 = Gxu[kr4*72 + mb*16 + g];
        unsigned a3 = Gxu[kr4*72 + mb*16 + 8 + g];
        int ky0 = kr & 7,  p0 = kr >> 3;
        int ky4 = kr4 & 7, p4 = kr4 >> 3;
        int i0 = (ky0*(nh*128 + g)) & 255;
        int i4 = (ky4*(nh*128 + g)) & 255;
        int s0 = (ky0*8) & 255, s4 = (ky4*8) & 255;
        #pragma unroll
        for (int nt = 0; nt < 16; nt++){
            unsigned b0 = twu[i0*2 + p0];
            unsigned b1 = twu[i4*2 + p4];
            i0 = (i0 + s0) & 255; i4 = (i4 + s4) & 255;
            MMA_TF32(acc[nt], a0, a1, a2, a3, b0, b1);
        }
    }
    __syncthreads();
    #pragma unroll
    for (int nt = 0; nt < 16; nt++){
        int n0 = nh*128 + nt*8 + 2*t;
        *(float2*)&hs[(mb*16 + g)*264     + n0] = make_float2(gelu_f(acc[nt][0]), gelu_f(acc[nt][1]));
        *(float2*)&hs[(mb*16 + 8 + g)*264 + n0] = make_float2(gelu_f(acc[nt][2]), gelu_f(acc[nt][3]));
    }
    __syncthreads();

    // ---- phase 2: m = gelu(W1 t + b1), M=32
    int mb2 = w & 1, nq = w >> 1;
    float am[8][4];
    {
        float bl = b1s[mb2*16 + g], bh = b1s[mb2*16 + 8 + g];
        #pragma unroll
        for (int nt = 0; nt < 8; nt++){
            am[nt][0] = bl; am[nt][1] = bl;
            am[nt][2] = bh; am[nt][3] = bh;
        }
    }
    #pragma unroll 2
    for (int ks = 0; ks < 8; ks++){
        int k0 = ks*8;
        unsigned a0 = w1u[(k0+t)*40   + mb2*16 + g];
        unsigned a1 = w1u[(k0+t)*40   + mb2*16 + 8 + g];
        unsigned a2 = w1u[(k0+t+4)*40 + mb2*16 + g];
        unsigned a3 = w1u[(k0+t+4)*40 + mb2*16 + 8 + g];
        #pragma unroll
        for (int nt = 0; nt < 8; nt++){
            int n0 = nq*64 + nt*8;
            unsigned b0 = hsu[(k0+t)*264   + n0 + g];
            unsigned b1 = hsu[(k0+t+4)*264 + n0 + g];
            MMA_TF32(am[nt], a0, a1, a2, a3, b0, b1);
        }
    }
    __syncthreads();
    #pragma unroll
    for (int nt = 0; nt < 8; nt++){
        int n0 = nq*64 + nt*8 + 2*t;
        *(float2*)&hs[(mb2*16 + g)*264     + n0] = make_float2(gelu_f(am[nt][0]), gelu_f(am[nt][1]));
        *(float2*)&hs[(mb2*16 + 8 + g)*264 + n0] = make_float2(gelu_f(am[nt][2]), gelu_f(am[nt][3]));
    }
    float out[16][4];
    #pragma unroll
    for (int nt = 0; nt < 16; nt++){
        int n0 = nh*128 + nt*8 + 2*t;
        int r0 = mb*16 + g, r1 = r0 + 8;
        float2 ha = *(const float2*)&row[r0*256 + n0];
        float2 hb = *(const float2*)&row[r1*256 + n0];
        out[nt][0] = fmaf(gw[r0], ha.x, b2s[r0]);
        out[nt][1] = fmaf(gw[r0], ha.y, b2s[r0]);
        out[nt][2] = fmaf(gw[r1], hb.x, b2s[r1]);
        out[nt][3] = fmaf(gw[r1], hb.y, b2s[r1]);
    }
    __syncthreads();

    // ---- phase 3: out += W2 m  (K=32)
    #pragma unroll
    for (int ks = 0; ks < 4; ks++){
        int k0 = ks*8;
        unsigned a0 = w2u[(k0+t)*72   + mb*16 + g];
        unsigned a1 = w2u[(k0+t)*72   + mb*16 + 8 + g];
        unsigned a2 = w2u[(k0+t+4)*72 + mb*16 + g];
        unsigned a3 = w2u[(k0+t+4)*72 + mb*16 + 8 + g];
        #pragma unroll
        for (int nt = 0; nt < 16; nt++){
            int n0 = nh*128 + nt*8;
            unsigned b0 = hsu[(k0+t)*264   + n0 + g];
            unsigned b1 = hsu[(k0+t+4)*264 + n0 + g];
            MMA_TF32(out[nt], a0, a1, a2, a3, b0, b1);
        }
    }
    __syncthreads();

    bool dog = (l < 3);
    #pragma unroll
    for (int nt = 0; nt < 16; nt++){
        int n0 = nh*128 + nt*8 + 2*t;
        int r0 = mb*16 + g, r1 = r0 + 8;
        float v0a = out[nt][0], v1a = out[nt][1];
        float v0b = out[nt][2], v1b = out[nt][3];
        if (dog){
            v0a = gelu_f(v0a); v1a = gelu_f(v1a);
            v0b = gelu_f(v0b); v1b = gelu_f(v1b);
        }
        float2 ra = make_float2(v0a, v1a);
        float2 rb = make_float2(v0b, v1b);
        *(float2*)&hs[r0*264 + n0] = ra;
        *(float2*)&hs[r1*264 + n0] = rb;
        *(float2*)&row[r0*256 + n0] = ra;
        *(float2*)&row[r1*256 + n0] = rb;
    }

    // ---- epilogue: stage-1 DFT of h_new (vectorized twiddle loads)
    if (do_dft){
        __syncthreads();
        {
            u64* t8u = (u64*)tw8;
            const u64* twb = (const u64*)twi;
            #pragma unroll
            for (int r = 0; r < 8; r++){
                int e = tid + r*256;
                int ky = e >> 8, v = e & 255;
                t8u[e] = twb[(ky*v)&255];
            }
        }
        __syncthreads();
        int c = tid & 63, qd = tid >> 6;
        const u64* t8 = (const u64*)tw8;
        u64 a[8];
        #pragma unroll
        for (int k = 0; k < 8; k++) a[k] = pk2(0.f, 0.f);
        const float* hc = &hs[c*264 + qd*64];
        int vb = qd*64;
        for (int vv = 0; vv < 64; vv += 4){
            float4 xv = *(const float4*)&hc[vv];
            u64 x0 = pk2(xv.x,xv.x), x1 = pk2(xv.y,xv.y);
            u64 x2 = pk2(xv.z,xv.z), x3 = pk2(xv.w,xv.w);
            #pragma unroll
            for (int k = 0; k < 8; k++){
                const ulonglong2* tk2 = (const ulonglong2*)(t8 + k*256 + vb + vv);
                ulonglong2 ta = tk2[0], tb = tk2[1];
                a[k] = ffma2(x0, ta.x, a[k]);
                a[k] = ffma2(x1, ta.y, a[k]);
                a[k] = ffma2(x2, tb.x, a[k]);
                a[k] = ffma2(x3, tb.y, a[k]);
            }
        }
        #pragma unroll
        for (int k = 0; k < 8; k++){
            float sr, si; upk2(a[k], sr, si);
            *(float2*)&red[((qd*64+c)*8+k)*2] = make_float2(sr, si);
        }
        __syncthreads();
        const float scale = 1.0f/65536.0f;
        #pragma unroll
        for (int rep = 0; rep < 2; rep++){
            int idx = tid + rep*256;
            int ky = idx >> 6, cc = idx & 63;
            float sr = 0.f, si = 0.f;
            #pragma unroll
            for (int q2 = 0; q2 < 4; q2++){
                float2 t2 = *(const float2*)&red[((q2*64+cc)*8+ky)*2];
                sr += t2.x; si += t2.y;
            }
            float* o = g_Y + (size_t)(((b*8+ky)*256+u)*64 + cc)*2;
            o[0] = sr*scale; o[1] = -si*scale;
        }
    }
}

// ---------------- projection via tf32 MMA: 64 -> 128 -> gelu -> 3 ------------
// grid: B*H*4 (64-px tiles), 256 threads = 8 warps (warp = m-block of 16 ch).
__global__ __launch_bounds__(256,2) void k_proj(const float* __restrict__ x,
                      const float* __restrict__ b1g, const float* __restrict__ w2g,
                      const float* __restrict__ b2g, float* __restrict__ out){
    extern __shared__ float sm[];
    float* hsp = sm;            // 64*72 = 4608  (tf32 bits, [k=c][px])
    float* w1s = hsp + 4608;    // 64*136 = 8704 (tf32 bits, [k][o])
    float* t2  = w1s + 8704;    // 128*66 = 8448
    float* b1s = t2 + 8448;     // 128   -> total 21888 floats = 87552 B
    int tid = threadIdx.x;
    int blk = blockIdx.x;
    int q = blk & 3, u = (blk>>2) & 255, b = blk >> 10;
    int lane = tid & 31, w = tid >> 5;
    int g = lane >> 2, t = lane & 3;
    int mb = w;   // 0..7

    const float* row = g_h + (size_t)(b*256+u)*64*256 + q*64;
    for (int i = tid; i < 1024; i += 256){
        int c = i>>4, v4 = i&15;
        float4 hv = *(const float4*)&row[c*256 + v4*4];
        uint4 hb;
        hb.x = tf32_rna(hv.x); hb.y = tf32_rna(hv.y);
        hb.z = tf32_rna(hv.z); hb.w = tf32_rna(hv.w);
        *(uint4*)&hsp[c*72 + v4*4] = hb;
    }
    for (int i = tid; i < 2048; i += 256){
        int k = i>>5, o4 = i&31;
        *(uint4*)&w1s[k*136 + o4*4] = ((const uint4*)g_Wp1)[i];
    }
    if (tid < 128) b1s[tid] = b1g[tid];
    __syncthreads();

    // MMA: M=128 (8 warps x m16), N=64 (8 n-tiles), K=64
    const unsigned* hu = (const unsigned*)hsp;
    const unsigned* wu = (const unsigned*)w1s;
    float acc[8][4];
    {
        float bl = b1s[mb*16 + g], bh = b1s[mb*16 + 8 + g];
        #pragma unroll
        for (int nt = 0; nt < 8; nt++){
            acc[nt][0] = bl; acc[nt][1] = bl;
            acc[nt][2] = bh; acc[nt][3] = bh;
        }
    }
    #pragma unroll 2
    for (int ks = 0; ks < 8; ks++){
        int k0 = ks*8;
        unsigned a0 = wu[(k0+t)*136   + mb*16 + g];
        unsigned a1 = wu[(k0+t)*136   + mb*16 + 8 + g];
        unsigned a2 = wu[(k0+t+4)*136 + mb*16 + g];
        unsigned a3 = wu[(k0+t+4)*136 + mb*16 + 8 + g];
        #pragma unroll
        for (int nt = 0; nt < 8; nt++){
            int n0 = nt*8;
            unsigned b0 = hu[(k0+t)*72   + n0 + g];
            unsigned b1 = hu[(k0+t+4)*72 + n0 + g];
            MMA_TF32(acc[nt], a0, a1, a2, a3, b0, b1);
        }
    }
    #pragma unroll
    for (int nt = 0; nt < 8; nt++){
        int n0 = nt*8 + 2*t;
        t2[(mb*16 + g)*66 + n0]       = gelu_f(acc[nt][0]);
        t2[(mb*16 + g)*66 + n0 + 1]   = gelu_f(acc[nt][1]);
        t2[(mb*16 + 8 + g)*66 + n0]     = gelu_f(acc[nt][2]);
        t2[(mb*16 + 8 + g)*66 + n0 + 1] = gelu_f(acc[nt][3]);
    }
    __syncthreads();
    if (tid < 192){
        int c = tid >> 6, vv = tid & 63;
        float a = b2g[c];
        #pragma unroll 4
        for (int j = 0; j < 128; j++)
            a = fmaf(t2[j*66+vv], w2g[c*128+j], a);
        size_t gi = (size_t)((b*3+c)*256+u)*256 + q*64 + vv;
        out[gi] = a + x[gi];
    }
}

// ---------------- host launch ------------------------------------------------
extern "C" void kernel_launch(void* const* d_in, const int* in_sizes, int n_in,
                              void* d_out, int out_size){
    (void)in_sizes; (void)n_in; (void)out_size;
    const float* x       = (const float*)d_in[0];
    const float* lift_w1 = (const float*)d_in[1];
    const float* lift_b1 = (const float*)d_in[2];
    const float* lift_w2 = (const float*)d_in[3];
    const float* lift_b2 = (const float*)d_in[4];
    const float* swr1    = (const float*)d_in[5];
    const float* swi1    = (const float*)d_in[6];
    const float* swr2    = (const float*)d_in[7];
    const float* swi2    = (const float*)d_in[8];
    const float* spec_b  = (const float*)d_in[9];
    const float* skw     = (const float*)d_in[10];
    const float* gate    = (const float*)d_in[11];
    const float* mw1     = (const float*)d_in[12];
    const float* mb1     = (const float*)d_in[13];
    const float* mw2     = (const float*)d_in[14];
    const float* mb2     = (const float*)d_in[15];
    const float* pw1     = (const float*)d_in[16];
    const float* pb1     = (const float*)d_in[17];
    const float* pw2     = (const float*)d_in[18];
    const float* pb2     = (const float*)d_in[19];
    float* out = (float*)d_out;

    const int SM_LIFT = 28096 * 4;                                    // 112384
    const int SM_DFT1 = (16640 + 4096 + 4096) * 4;                    // 99328
    const int SM_FUSE = 28256 * 4;                                    // 113024
    const int SM_PROJ = 21888 * 4;                                    // 87552

    cudaFuncSetAttribute(k_lift, cudaFuncAttributeMaxDynamicSharedMemorySize, SM_LIFT);
    cudaFuncSetAttribute(k_dft1, cudaFuncAttributeMaxDynamicSharedMemorySize, SM_DFT1);
    cudaFuncSetAttribute(k_fuse, cudaFuncAttributeMaxDynamicSharedMemorySize, SM_FUSE);
    cudaFuncSetAttribute(k_proj, cudaFuncAttributeMaxDynamicSharedMemorySize, SM_PROJ);

    k_reorder<<<224, 256>>>(lift_w2, pw1, skw, mw1, mw2);
    k_lift<<<BB*HH*2, 256, SM_LIFT>>>(x, lift_w1, lift_b1, lift_b2);
    k_dft1<<<BB*HH, 256, SM_DFT1>>>();           // once, after lift
    for (int l = 0; l < 4; l++){
        k_dft2 <<<BB*NKY*NKX, 256>>>();
        k_mix  <<<NKX*NKY, 256>>>(l, swr1, swi1, swr2, swi2);
        k_idft1<<<BB*NKY*8, 256>>>();
        k_fuse <<<BB*HH, 256, SM_FUSE>>>(l, (l < 3) ? 1 : 0,
                                         gate, spec_b, mb1, mb2);
    }
    k_proj<<<BB*HH*4, 256, SM_PROJ>>>(x, pb1, pw2, pb2, out);
}

// round 17
// speedup vs baseline: 1.3135x; 1.0515x over previous
#include <cuda_runtime.h>
#include <math.h>

// Problem constants
#define BB 8
#define HH 256
#define WW 256
#define CC 64
#define NKY 8
#define NKX 16

typedef unsigned long long u64;

// ---------------- scratch (static device memory; no allocations) ------------
__device__ float g_h[BB*HH*CC*WW];        // h field, layout [b][u][c][v]  (128MB)
__device__ float g_Y[BB*NKY*HH*CC*2];     // stage-1 DFT  [b][ky][u][c][re,im]
__device__ float g_F[BB*NKY*NKX*CC*2];    // modes        [b][ky][s][c][re,im]
__device__ float g_OF[BB*NKY*NKX*CC*2];   // mixed modes  (same layout)
__device__ float g_G[BB*NKY*HH*CC*2];     // inverse stage [b][ky][u][o][re,im]
__device__ float g_Wl2[256*64];           // lift_w2 transposed [k][o], tf32-rounded
__device__ float g_Wp1[64*128];           // proj_w1 transposed [k][o], tf32-rounded
__device__ float g_Wfsk[4*64*64];         // fno skip, [l][i][o], tf32-rounded
__device__ float g_Wf1[4*64*32];          // mlp w1,   [l][i][j], tf32-rounded
__device__ float g_Wf2[4*32*64];          // mlp w2,   [l][j][o], tf32-rounded

// ---- gelu via hardware tanh (1 MUFU op) ------------------------------------
__device__ __forceinline__ float gelu_f(float x){
    float x2 = x*x;
    float inner = fmaf(fmaf(0.0356774081f, x2, 0.7978845608f), x, 0.0f);
    float t;
    asm("tanh.approx.f32 %0,%1;" : "=f"(t) : "f"(inner));
    return 0.5f*x*(1.0f + t);
}

// ---- packed fp32x2 helpers --------------------------------------------------
__device__ __forceinline__ u64 pk2(float lo, float hi){
    u64 r; asm("mov.b64 %0,{%1,%2};" : "=l"(r) : "f"(lo), "f"(hi)); return r;
}
__device__ __forceinline__ void upk2(u64 v, float& lo, float& hi){
    asm("mov.b64 {%0,%1},%2;" : "=f"(lo), "=f"(hi) : "l"(v));
}
__device__ __forceinline__ u64 ffma2(u64 a, u64 b, u64 c){
    u64 r; asm("fma.rn.f32x2 %0,%1,%2,%3;" : "=l"(r) : "l"(a), "l"(b), "l"(c)); return r;
}
__device__ __forceinline__ unsigned tf32_rna(float x){
    unsigned r; asm("cvt.rna.tf32.f32 %0,%1;" : "=r"(r) : "f"(x)); return r;
}
#define MMA_TF32(accv, A0, A1, A2, A3, B0, B1) \
    asm volatile( \
        "mma.sync.aligned.m16n8k8.row.col.f32.tf32.tf32.f32 " \
        "{%0,%1,%2,%3},{%4,%5,%6,%7},{%8,%9},{%0,%1,%2,%3};" \
        : "+f"((accv)[0]), "+f"((accv)[1]), "+f"((accv)[2]), "+f"((accv)[3]) \
        : "r"(A0), "r"(A1), "r"(A2), "r"(A3), "r"(B0), "r"(B1))

// ---------------- one-time (per launch) weight transposes --------------------
__global__ void k_reorder(const float* __restrict__ lw2, const float* __restrict__ pw1,
                          const float* __restrict__ skw, const float* __restrict__ mw1,
                          const float* __restrict__ mw2){
    int e = blockIdx.x*256 + threadIdx.x;
    if (e < 16384){ int k = e>>6, o = e&63;
        ((unsigned*)g_Wl2)[e] = tf32_rna(lw2[o*256+k]); }
    else if (e < 24576){ int i = e-16384; int k = i>>7, o = i&127;
        ((unsigned*)g_Wp1)[i] = tf32_rna(pw1[o*64+k]); }
    else if (e < 40960){ int i = e-24576; int l = i>>12; int r = i&4095;
                         int ii = r>>6, o = r&63;
                         ((unsigned*)g_Wfsk)[i] = tf32_rna(skw[l*4096 + o*64 + ii]); }
    else if (e < 49152){ int i = e-40960; int l = i>>11; int r = i&2047;
                         int ii = r>>5, j = r&31;
                         ((unsigned*)g_Wf1)[i] = tf32_rna(mw1[l*2048 + j*64 + ii]); }
    else if (e < 57344){ int i = e-49152; int l = i>>11; int r = i&2047;
                         int j = r>>6, o = r&63;
                         ((unsigned*)g_Wf2)[i] = tf32_rna(mw2[l*2048 + o*32 + j]); }
}

// ---------------- lifting via tf32 MMA (unchanged) ---------------------------
__global__ __launch_bounds__(256,2) void k_lift(const float* __restrict__ x,
                       const float* __restrict__ w1, const float* __restrict__ b1,
                       const float* __restrict__ b2){
    extern __shared__ float sm[];
    float* t1  = sm;               // 128*136 = 17408 (tf32 bits)
    float* w2h = t1 + 17408;       // 128*72 = 9216
    float* w1s = w2h + 9216;       // 768
    float* b1s = w1s + 768;        // 256
    float* b2s = b1s + 256;        // 64
    float* xs  = b2s + 64;         // 384
    int tid = threadIdx.x;
    int blk = blockIdx.x;
    int q = blk & 1, u = (blk>>1) & 255, b = blk >> 9;
    int lane = tid & 31, w = tid >> 5;
    int g = lane >> 2, t = lane & 3;
    int mb = w & 3, nh = w >> 2;

    for (int i = tid; i < 768; i += 256) w1s[i] = w1[i];
    if (tid < 256) b1s[tid] = b1[tid];
    if (tid < 64)  b2s[tid] = b2[tid];
    for (int i = tid; i < 384; i += 256){
        int c = i>>7, v = i&127;
        xs[i] = x[((b*3+c)*256+u)*256 + q*128 + v];
    }
    __syncthreads();

    float acc[8][4];
    {
        float bl = b2s[mb*16 + g], bh = b2s[mb*16 + 8 + g];
        #pragma unroll
        for (int nt = 0; nt < 8; nt++){
            acc[nt][0] = bl; acc[nt][1] = bl;
            acc[nt][2] = bh; acc[nt][3] = bh;
        }
    }

    for (int p = 0; p < 2; p++){
        for (int i = tid; i < 8192; i += 256){
            int kk = i>>6, o = i&63;
            w2h[kk*72 + o] = g_Wl2[p*8192 + i];
        }
        for (int it = tid; it < 16384; it += 256){
            int kk = it >> 7, vx = it & 127;
            int c = p*128 + kk;
            float s = fmaf(w1s[c*3+0], xs[vx],
                      fmaf(w1s[c*3+1], xs[128+vx],
                      fmaf(w1s[c*3+2], xs[256+vx], b1s[c])));
            ((unsigned*)t1)[kk*136 + vx] = tf32_rna(gelu_f(s));
        }
        __syncthreads();

        const unsigned* t1u = (const unsigned*)t1;
        const unsigned* w2u = (const unsigned*)w2h;
        #pragma unroll 2
        for (int ks = 0; ks < 16; ks++){
            int k0 = ks*8;
            unsigned a0 = w2u[(k0+t)*72   + mb*16 + g];
            unsigned a1 = w2u[(k0+t)*72   + mb*16 + 8 + g];
            unsigned a2 = w2u[(k0+t+4)*72 + mb*16 + g];
            unsigned a3 = w2u[(k0+t+4)*72 + mb*16 + 8 + g];
            #pragma unroll
            for (int nt = 0; nt < 8; nt++){
                int n0 = nh*64 + nt*8;
                unsigned bb0 = t1u[(k0+t)*136   + n0 + g];
                unsigned bb1 = t1u[(k0+t+4)*136 + n0 + g];
                MMA_TF32(acc[nt], a0, a1, a2, a3, bb0, bb1);
            }
        }
        __syncthreads();
    }

    float* outrow = g_h + (size_t)((b*256+u)*64)*256 + q*128;
    #pragma unroll
    for (int nt = 0; nt < 8; nt++){
        int pxl = nh*64 + nt*8 + 2*t;
        *(float2*)&outrow[(mb*16 + g)*256     + pxl] = make_float2(acc[nt][0], acc[nt][1]);
        *(float2*)&outrow[(mb*16 + 8 + g)*256 + pxl] = make_float2(acc[nt][2], acc[nt][3]);
    }
}

// ---------------- DFT stage 1 via tf32 MMA: Y[c][16] = h[c][v] x twT[v][16] --
// M=64 (4 m-blocks), N=16 (2 n8-tiles), K=256 (32 k-steps); 8 warp-tiles.
__global__ __launch_bounds__(256) void k_dft1(){
    extern __shared__ float sm[];
    float* hs  = sm;            // 64*260 = 16640 (fp32; HW-truncates to tf32)
    float* twi = hs + 16640;    // 512 interleaved (cos,sin)
    float* twT = twi + 512;     // 256*24 = 6144  [v][slot]: 0-7 cos, 8-15 sin
    float* red = twT + 6144;    // 1024 [c][16]
    int tid = threadIdx.x;
    int u = blockIdx.x & 255, b = blockIdx.x >> 8;
    int lane = tid & 31, w = tid >> 5;
    int g = lane >> 2, t = lane & 3;
    int mb = w & 3, ns = w >> 2;
    const float* row = g_h + (size_t)(b*256+u)*64*256;
    const float4* rw4 = (const float4*)row;
    for (int i = tid; i < 4096; i += 256){
        int c = i>>6, v4 = i&63;
        *(float4*)&hs[c*260 + v4*4] = rw4[i];
    }
    {
        float ss, sc;
        sincospif((float)tid*(1.0f/128.0f), &ss, &sc);
        twi[tid*2] = sc; twi[tid*2+1] = ss;
    }
    __syncthreads();
    #pragma unroll
    for (int r = 0; r < 16; r++){
        int e = tid + r*256;
        int v = e >> 4, slot = e & 15;
        int ky = slot & 7;
        twT[v*24 + slot] = twi[((ky*v)&255)*2 + (slot>>3)];
    }
    __syncthreads();
    const unsigned* hsu = (const unsigned*)hs;
    const unsigned* twu = (const unsigned*)twT;
    float acc[4] = {0.f, 0.f, 0.f, 0.f};
    int m0 = mb*16, n0 = ns*8;
    #pragma unroll 4
    for (int ks = 0; ks < 32; ks++){
        int k0 = ks*8;
        unsigned a0 = hsu[(m0+g)*260   + k0+t];
        unsigned a1 = hsu[(m0+8+g)*260 + k0+t];
        unsigned a2 = hsu[(m0+g)*260   + k0+t+4];
        unsigned a3 = hsu[(m0+8+g)*260 + k0+t+4];
        unsigned b0 = twu[(k0+t)*24   + n0 + g];
        unsigned b1 = twu[(k0+t+4)*24 + n0 + g];
        MMA_TF32(acc, a0, a1, a2, a3, b0, b1);
    }
    red[(m0+g)*16   + n0 + 2*t]     = acc[0];
    red[(m0+g)*16   + n0 + 2*t + 1] = acc[1];
    red[(m0+8+g)*16 + n0 + 2*t]     = acc[2];
    red[(m0+8+g)*16 + n0 + 2*t + 1] = acc[3];
    __syncthreads();
    const float scale = 1.0f/65536.0f;
    #pragma unroll
    for (int rep = 0; rep < 2; rep++){
        int idx = tid + rep*256;
        int ky = idx >> 6, cc = idx & 63;
        float* o = g_Y + (size_t)(((b*8+ky)*256+u)*64 + cc)*2;
        o[0] =  red[cc*16 + ky]*scale;
        o[1] = -red[cc*16 + 8 + ky]*scale;   // e^{-i}: conjugate
    }
}

// ---------------- DFT stage 2 (over u): grid B*KY*KX = 1024 -----------------
__global__ __launch_bounds__(256) void k_dft2(){
    __shared__ float tc[256], tsp[256];
    __shared__ float red[4*64*2];
    int tid = threadIdx.x;
    int blk = blockIdx.x;
    int s = blk & 15, ky = (blk>>4) & 7, b = blk >> 7;
    int kxe = (s < 8) ? s : s - 16;
    {
        float ss, sc;
        sincospif((float)tid*(1.0f/128.0f), &ss, &sc);
        tc[tid] = sc; tsp[tid] = ss;
    }
    __syncthreads();
    int uc = tid >> 6, c = tid & 63;
    float sr = 0.f, si = 0.f;
    const float* Yb = g_Y + (size_t)((b*8+ky)*256)*128;
    int u0 = uc*64;
    int t = (kxe*u0) & 255;
    for (int uu = 0; uu < 64; uu++){
        float2 y = *(const float2*)(Yb + (u0+uu)*128 + c*2);
        float cc = tc[t], sv = tsp[t];
        t = (t + kxe) & 255;
        sr = fmaf(y.x, cc, fmaf( y.y, sv, sr));
        si = fmaf(y.y, cc, fmaf(-y.x, sv, si));
    }
    red[(uc*64+c)*2]   = sr;
    red[(uc*64+c)*2+1] = si;
    __syncthreads();
    if (tid < 64){
        float ar = red[tid*2]       + red[(64+tid)*2]
                 + red[(128+tid)*2] + red[(192+tid)*2];
        float ai = red[tid*2+1]       + red[(64+tid)*2+1]
                 + red[(128+tid)*2+1] + red[(192+tid)*2+1];
        float* o = g_F + (size_t)(((b*8+ky)*16+s)*64 + tid)*2;
        o[0] = ar; o[1] = ai;
    }
}

// ---------------- mode mixing ------------------------------------------------
__global__ __launch_bounds__(256) void k_mix(int l, const float* __restrict__ wr1,
                      const float* __restrict__ wi1, const float* __restrict__ wr2,
                      const float* __restrict__ wi2){
    __shared__ float Fs[8*64*2];
    __shared__ float Wm[64*64*2];
    int tid = threadIdx.x;
    int s = blockIdx.x >> 3, ky = blockIdx.x & 7;
    const float* wr = (s < 8) ? wr1 : wr2;
    const float* wi = (s < 8) ? wi1 : wi2;
    int kxh = s & 7;
    for (int i = tid; i < 8*64*2; i += 256){
        int b = i >> 7, r = i & 127;
        Fs[i] = g_F[(size_t)(((b*8+ky)*16+s)*64)*2 + r];
    }
    for (int i = tid; i < 4096; i += 256){
        int ii = i >> 6, o = i & 63;
        int src = (((l*64+ii)*64+o)*8 + kxh)*8 + ky;
        Wm[i*2]   = wr[src];
        Wm[i*2+1] = wi[src];
    }
    __syncthreads();
    #pragma unroll
    for (int p = 0; p < 2; p++){
        int gid = tid + p*256;
        int b = gid >> 6, o = gid & 63;
        float ar = 0.f, ai = 0.f;
        const float2* fp = (const float2*)&Fs[b*128];
        const float2* wp = (const float2*)Wm;
        #pragma unroll 4
        for (int i2 = 0; i2 < 64; i2++){
            float2 f = fp[i2];
            float2 w = wp[i2*64 + o];
            ar = fmaf(f.x, w.x, fmaf(-f.y, w.y, ar));
            ai = fmaf(f.x, w.y, fmaf( f.y, w.x, ai));
        }
        float* ot = g_OF + (size_t)(((b*8+ky)*16+s)*64 + o)*2;
        ot[0] = ar; ot[1] = ai;
    }
}

// ---------------- inverse over kx: grid B*KY*8 = 512 -------------------------
__global__ __launch_bounds__(256) void k_idft1(){
    __shared__ float OFs[16*64*2];
    int tid = threadIdx.x;
    int blk = blockIdx.x;
    int uq = blk & 7, ky = (blk>>3) & 7, b = blk >> 6;
    for (int i = tid; i < 2048; i += 256)
        OFs[i] = g_OF[(size_t)((b*8+ky)*16*64)*2 + i];
    __syncthreads();
    int u = uq*32 + (tid & 31);
    int og = tid >> 5, o0 = og*8;
    float ar[8], ai[8];
    #pragma unroll
    for (int j = 0; j < 8; j++){ ar[j] = 0.f; ai[j] = 0.f; }
    for (int s = 0; s < 16; s++){
        int kxe = (s < 8) ? s : s - 16;
        float ss, sc;
        sincospif((float)(kxe*u)*(1.0f/128.0f), &ss, &sc);
        const float2* op = (const float2*)&OFs[(s*64+o0)*2];
        #pragma unroll
        for (int j = 0; j < 8; j++){
            float2 f = op[j];
            ar[j] = fmaf(f.x, sc, fmaf(-f.y, ss, ar[j]));
            ai[j] = fmaf(f.x, ss, fmaf( f.y, sc, ai[j]));
        }
    }
    float* o = g_G + (size_t)(((b*8+ky)*256+u)*64 + o0)*2;
    #pragma unroll
    for (int j = 0; j < 8; j++){ o[j*2] = ar[j]; o[j*2+1] = ai[j]; }
}

// ---------------- fused per-row layer kernel: tf32 MMA everywhere ------------
__global__ __launch_bounds__(256,2) void k_fuse(int l, int do_dft,
        const float* __restrict__ gate_g, const float* __restrict__ specb_g,
        const float* __restrict__ b1_g, const float* __restrict__ b2_g){
    extern __shared__ float sm[];
    float* hs   = sm;               // 64*264 = 16896
    float* wsk  = hs + 16896;       // 64*72 = 4608   [k=i][o]
    float* Gext = wsk + 4608;       // 16*72 = 1152
    float* w1   = Gext + 1152;      // 64*40 = 2560   [k=i][j]
    float* w2   = w1 + 2560;        // 32*72 = 2304   [k=j][o]
    float* twi  = w2 + 2304;        // 512 interleaved (cos,sin)
    float* gw   = twi + 512;        // 64
    float* sb   = gw + 64;          // 64
    float* b1s  = sb + 64;          // 32
    float* b2s  = b1s + 32;         // 64   -> total 28256 floats = 113024 B
    float* twT  = wsk;              // epilogue alias: 6144 (spans wsk+Gext+w1 head)
    float* redd = wsk + 6144;       // epilogue alias: 1024 (inside w1 region)

    int tid = threadIdx.x;
    int u = blockIdx.x & 255, b = blockIdx.x >> 8;
    float* row = g_h + (size_t)(b*256+u)*64*256;
    int lane = tid & 31, w = tid >> 5;
    int g = lane >> 2, t = lane & 3;
    int mb = w & 3, nh = w >> 2;

    {
        const float4* rw4 = (const float4*)row;
        for (int i = tid; i < 4096; i += 256){
            int c = i>>6, v4 = i&63;
            *(float4*)&hs[c*264 + v4*4] = rw4[i];
        }
    }
    for (int i = tid; i < 4096; i += 256){ int ii = i>>6, o = i&63; wsk[ii*72+o] = g_Wfsk[l*4096+i]; }
    for (int i = tid; i < 2048; i += 256){ int ii = i>>5, j = i&31; w1[ii*40+j]  = g_Wf1[l*2048+i]; }
    for (int i = tid; i < 2048; i += 256){ int j = i>>6, o = i&63;  w2[j*72+o]   = g_Wf2[l*2048+i]; }
    for (int i = tid; i < 512; i += 256){
        int ky = i>>6, o = i&63;
        float2 gv = *(const float2*)&g_G[(size_t)(((b*8+ky)*256+u)*64 + o)*2];
        float ck = (ky == 0) ? 1.0f : 2.0f;
        Gext[ky*72 + o]     =  gv.x*ck;
        Gext[(8+ky)*72 + o] = -gv.y*ck;
    }
    {
        float ss, sc;
        sincospif((float)tid*(1.0f/128.0f), &ss, &sc);
        twi[tid*2] = sc; twi[tid*2+1] = ss;
    }
    if (tid < 64) gw[tid]  = gate_g[l*64+tid];
    if (tid < 64) sb[tid]  = specb_g[l*64+tid];
    if (tid < 32) b1s[tid] = b1_g[l*32+tid];
    if (tid < 64) b2s[tid] = b2_g[l*64+tid];
    __syncthreads();

    const unsigned* hsu  = (const unsigned*)hs;
    const unsigned* wsku = (const unsigned*)wsk;
    const unsigned* Gxu  = (const unsigned*)Gext;
    const unsigned* twu  = (const unsigned*)twi;
    const unsigned* w1u  = (const unsigned*)w1;
    const unsigned* w2u  = (const unsigned*)w2;

    // ---- phase 1: t = gelu(spec_b + recomb + Wsk h)
    float acc[16][4];
    {
        float bl = sb[mb*16 + g], bh = sb[mb*16 + 8 + g];
        #pragma unroll
        for (int nt = 0; nt < 16; nt++){
            acc[nt][0] = bl; acc[nt][1] = bl;
            acc[nt][2] = bh; acc[nt][3] = bh;
        }
    }
    #pragma unroll 2
    for (int ks = 0; ks < 8; ks++){
        int k0 = ks*8;
        unsigned a0 = wsku[(k0+t)*72   + mb*16 + g];
        unsigned a1 = wsku[(k0+t)*72   + mb*16 + 8 + g];
        unsigned a2 = wsku[(k0+t+4)*72 + mb*16 + g];
        unsigned a3 = wsku[(k0+t+4)*72 + mb*16 + 8 + g];
        #pragma unroll
        for (int nt = 0; nt < 16; nt++){
            int n0 = nh*128 + nt*8;
            unsigned b0 = hsu[(k0+t)*264   + n0 + g];
            unsigned b1 = hsu[(k0+t+4)*264 + n0 + g];
            MMA_TF32(acc[nt], a0, a1, a2, a3, b0, b1);
        }
    }
    #pragma unroll
    for (int ks = 0; ks < 2; ks++){
        int k0 = ks*8;
        int kr = k0 + t, kr4 = k0 + t + 4;
        unsigned a0 = Gxu[kr*72  + mb*16 + g];
        unsigned a1 = Gxu[kr*72  + mb*16 + 8 + g];
        unsigned a2 = Gxu[kr4*72 + mb*16 + g];
        unsigned a3 = Gxu[kr4*72 + mb*16 + 8 + g];
        int ky0 = kr & 7,  p0 = kr >> 3;
        int ky4 = kr4 & 7, p4 = kr4 >> 3;
        int i0 = (ky0*(nh*128 + g)) & 255;
        int i4 = (ky4*(nh*128 + g)) & 255;
        int s0 = (ky0*8) & 255, s4 = (ky4*8) & 255;
        #pragma unroll
        for (int nt = 0; nt < 16; nt++){
            unsigned b0 = twu[i0*2 + p0];
            unsigned b1 = twu[i4*2 + p4];
            i0 = (i0 + s0) & 255; i4 = (i4 + s4) & 255;
            MMA_TF32(acc[nt], a0, a1, a2, a3, b0, b1);
        }
    }
    __syncthreads();
    #pragma unroll
    for (int nt = 0; nt < 16; nt++){
        int n0 = nh*128 + nt*8 + 2*t;
        *(float2*)&hs[(mb*16 + g)*264     + n0] = make_float2(gelu_f(acc[nt][0]), gelu_f(acc[nt][1]));
        *(float2*)&hs[(mb*16 + 8 + g)*264 + n0] = make_float2(gelu_f(acc[nt][2]), gelu_f(acc[nt][3]));
    }
    __syncthreads();

    // ---- phase 2: m = gelu(W1 t + b1), M=32
    int mb2 = w & 1, nq = w >> 1;
    float am[8][4];
    {
        float bl = b1s[mb2*16 + g], bh = b1s[mb2*16 + 8 + g];
        #pragma unroll
        for (int nt = 0; nt < 8; nt++){
            am[nt][0] = bl; am[nt][1] = bl;
            am[nt][2] = bh; am[nt][3] = bh;
        }
    }
    #pragma unroll 2
    for (int ks = 0; ks < 8; ks++){
        int k0 = ks*8;
        unsigned a0 = w1u[(k0+t)*40   + mb2*16 + g];
        unsigned a1 = w1u[(k0+t)*40   + mb2*16 + 8 + g];
        unsigned a2 = w1u[(k0+t+4)*40 + mb2*16 + g];
        unsigned a3 = w1u[(k0+t+4)*40 + mb2*16 + 8 + g];
        #pragma unroll
        for (int nt = 0; nt < 8; nt++){
            int n0 = nq*64 + nt*8;
            unsigned b0 = hsu[(k0+t)*264   + n0 + g];
            unsigned b1 = hsu[(k0+t+4)*264 + n0 + g];
            MMA_TF32(am[nt], a0, a1, a2, a3, b0, b1);
        }
    }
    __syncthreads();
    #pragma unroll
    for (int nt = 0; nt < 8; nt++){
        int n0 = nq*64 + nt*8 + 2*t;
        *(float2*)&hs[(mb2*16 + g)*264     + n0] = make_float2(gelu_f(am[nt][0]), gelu_f(am[nt][1]));
        *(float2*)&hs[(mb2*16 + 8 + g)*264 + n0] = make_float2(gelu_f(am[nt][2]), gelu_f(am[nt][3]));
    }
    float out[16][4];
    #pragma unroll
    for (int nt = 0; nt < 16; nt++){
        int n0 = nh*128 + nt*8 + 2*t;
        int r0 = mb*16 + g, r1 = r0 + 8;
        float2 ha = *(const float2*)&row[r0*256 + n0];
        float2 hb = *(const float2*)&row[r1*256 + n0];
        out[nt][0] = fmaf(gw[r0], ha.x, b2s[r0]);
        out[nt][1] = fmaf(gw[r0], ha.y, b2s[r0]);
        out[nt][2] = fmaf(gw[r1], hb.x, b2s[r1]);
        out[nt][3] = fmaf(gw[r1], hb.y, b2s[r1]);
    }
    __syncthreads();

    // ---- phase 3: out += W2 m  (K=32)
    #pragma unroll
    for (int ks = 0; ks < 4; ks++){
        int k0 = ks*8;
        unsigned a0 = w2u[(k0+t)*72   + mb*16 + g];
        unsigned a1 = w2u[(k0+t)*72   + mb*16 + 8 + g];
        unsigned a2 = w2u[(k0+t+4)*72 + mb*16 + g];
        unsigned a3 = w2u[(k0+t+4)*72 + mb*16 + 8 + g];
        #pragma unroll
        for (int nt = 0; nt < 16; nt++){
            int n0 = nh*128 + nt*8;
            unsigned b0 = hsu[(k0+t)*264   + n0 + g];
            unsigned b1 = hsu[(k0+t+4)*264 + n0 + g];
            MMA_TF32(out[nt], a0, a1, a2, a3, b0, b1);
        }
    }
    __syncthreads();

    bool dog = (l < 3);
    #pragma unroll
    for (int nt = 0; nt < 16; nt++){
        int n0 = nh*128 + nt*8 + 2*t;
        int r0 = mb*16 + g, r1 = r0 + 8;
        float v0a = out[nt][0], v1a = out[nt][1];
        float v0b = out[nt][2], v1b = out[nt][3];
        if (dog){
            v0a = gelu_f(v0a); v1a = gelu_f(v1a);
            v0b = gelu_f(v0b); v1b = gelu_f(v1b);
        }
        float2 ra = make_float2(v0a, v1a);
        float2 rb = make_float2(v0b, v1b);
        *(float2*)&hs[r0*264 + n0] = ra;
        *(float2*)&hs[r1*264 + n0] = rb;
        *(float2*)&row[r0*256 + n0] = ra;
        *(float2*)&row[r1*256 + n0] = rb;
    }

    // ---- epilogue: stage-1 DFT of h_new via tf32 MMA ------------------------
    if (do_dft){
        __syncthreads();   // hs complete; wsk/Gext/w1/w2 regions now dead
        #pragma unroll
        for (int r = 0; r < 16; r++){
            int e = tid + r*256;
            int v = e >> 4, slot = e & 15;
            int ky = slot & 7;
            twT[v*24 + slot] = twi[((ky*v)&255)*2 + (slot>>3)];
        }
        __syncthreads();
        const unsigned* twu2 = (const unsigned*)twT;
        float accd[4] = {0.f, 0.f, 0.f, 0.f};
        int m0 = mb*16, n0 = nh*8;
        #pragma unroll 4
        for (int ks = 0; ks < 32; ks++){
            int k0 = ks*8;
            unsigned a0 = hsu[(m0+g)*264   + k0+t];
            unsigned a1 = hsu[(m0+8+g)*264 + k0+t];
            unsigned a2 = hsu[(m0+g)*264   + k0+t+4];
            unsigned a3 = hsu[(m0+8+g)*264 + k0+t+4];
            unsigned b0 = twu2[(k0+t)*24   + n0 + g];
            unsigned b1 = twu2[(k0+t+4)*24 + n0 + g];
            MMA_TF32(accd, a0, a1, a2, a3, b0, b1);
        }
        redd[(m0+g)*16   + n0 + 2*t]     = accd[0];
        redd[(m0+g)*16   + n0 + 2*t + 1] = accd[1];
        redd[(m0+8+g)*16 + n0 + 2*t]     = accd[2];
        redd[(m0+8+g)*16 + n0 + 2*t + 1] = accd[3];
        __syncthreads();
        const float scale = 1.0f/65536.0f;
        #pragma unroll
        for (int rep = 0; rep < 2; rep++){
            int idx = tid + rep*256;
            int ky = idx >> 6, cc = idx & 63;
            float* o = g_Y + (size_t)(((b*8+ky)*256+u)*64 + cc)*2;
            o[0] =  redd[cc*16 + ky]*scale;
            o[1] = -redd[cc*16 + 8 + ky]*scale;   // e^{-i}: conjugate
        }
    }
}

// ---------------- projection via tf32 MMA (unchanged from R16) ---------------
__global__ __launch_bounds__(256,2) void k_proj(const float* __restrict__ x,
                      const float* __restrict__ b1g, const float* __restrict__ w2g,
                      const float* __restrict__ b2g, float* __restrict__ out){
    extern __shared__ float sm[];
    float* hsp = sm;            // 64*72 = 4608  (tf32 bits, [k=c][px])
    float* w1s = hsp + 4608;    // 64*136 = 8704 (tf32 bits, [k][o])
    float* t2  = w1s + 8704;    // 128*66 = 8448
    float* b1s = t2 + 8448;     // 128   -> total 21888 floats = 87552 B
    int tid = threadIdx.x;
    int blk = blockIdx.x;
    int q = blk & 3, u = (blk>>2) & 255, b = blk >> 10;
    int lane = tid & 31, w = tid >> 5;
    int g = lane >> 2, t = lane & 3;
    int mb = w;   // 0..7

    const float* row = g_h + (size_t)(b*256+u)*64*256 + q*64;
    for (int i = tid; i < 1024; i += 256){
        int c = i>>4, v4 = i&15;
        float4 hv = *(const float4*)&row[c*256 + v4*4];
        uint4 hb;
        hb.x = tf32_rna(hv.x); hb.y = tf32_rna(hv.y);
        hb.z = tf32_rna(hv.z); hb.w = tf32_rna(hv.w);
        *(uint4*)&hsp[c*72 + v4*4] = hb;
    }
    for (int i = tid; i < 2048; i += 256){
        int k = i>>5, o4 = i&31;
        *(uint4*)&w1s[k*136 + o4*4] = ((const uint4*)g_Wp1)[i];
    }
    if (tid < 128) b1s[tid] = b1g[tid];
    __syncthreads();

    const unsigned* hu = (const unsigned*)hsp;
    const unsigned* wu = (const unsigned*)w1s;
    float acc[8][4];
    {
        float bl = b1s[mb*16 + g], bh = b1s[mb*16 + 8 + g];
        #pragma unroll
        for (int nt = 0; nt < 8; nt++){
            acc[nt][0] = bl; acc[nt][1] = bl;
            acc[nt][2] = bh; acc[nt][3] = bh;
        }
    }
    #pragma unroll 2
    for (int ks = 0; ks < 8; ks++){
        int k0 = ks*8;
        unsigned a0 = wu[(k0+t)*136   + mb*16 + g];
        unsigned a1 = wu[(k0+t)*136   + mb*16 + 8 + g];
        unsigned a2 = wu[(k0+t+4)*136 + mb*16 + g];
        unsigned a3 = wu[(k0+t+4)*136 + mb*16 + 8 + g];
        #pragma unroll
        for (int nt = 0; nt < 8; nt++){
            int n0 = nt*8;
            unsigned b0 = hu[(k0+t)*72   + n0 + g];
            unsigned b1 = hu[(k0+t+4)*72 + n0 + g];
            MMA_TF32(acc[nt], a0, a1, a2, a3, b0, b1);
        }
    }
    #pragma unroll
    for (int nt = 0; nt < 8; nt++){
        int n0 = nt*8 + 2*t;
        t2[(mb*16 + g)*66 + n0]       = gelu_f(acc[nt][0]);
        t2[(mb*16 + g)*66 + n0 + 1]   = gelu_f(acc[nt][1]);
        t2[(mb*16 + 8 + g)*66 + n0]     = gelu_f(acc[nt][2]);
        t2[(mb*16 + 8 + g)*66 + n0 + 1] = gelu_f(acc[nt][3]);
    }
    __syncthreads();
    if (tid < 192){
        int c = tid >> 6, vv = tid & 63;
        float a = b2g[c];
        #pragma unroll 4
        for (int j = 0; j < 128; j++)
            a = fmaf(t2[j*66+vv], w2g[c*128+j], a);
        size_t gi = (size_t)((b*3+c)*256+u)*256 + q*64 + vv;
        out[gi] = a + x[gi];
    }
}

// ---------------- host launch ------------------------------------------------
extern "C" void kernel_launch(void* const* d_in, const int* in_sizes, int n_in,
                              void* d_out, int out_size){
    (void)in_sizes; (void)n_in; (void)out_size;
    const float* x       = (const float*)d_in[0];
    const float* lift_w1 = (const float*)d_in[1];
    const float* lift_b1 = (const float*)d_in[2];
    const float* lift_w2 = (const float*)d_in[3];
    const float* lift_b2 = (const float*)d_in[4];
    const float* swr1    = (const float*)d_in[5];
    const float* swi1    = (const float*)d_in[6];
    const float* swr2    = (const float*)d_in[7];
    const float* swi2    = (const float*)d_in[8];
    const float* spec_b  = (const float*)d_in[9];
    const float* skw     = (const float*)d_in[10];
    const float* gate    = (const float*)d_in[11];
    const float* mw1     = (const float*)d_in[12];
    const float* mb1     = (const float*)d_in[13];
    const float* mw2     = (const float*)d_in[14];
    const float* mb2     = (const float*)d_in[15];
    const float* pw1     = (const float*)d_in[16];
    const float* pb1     = (const float*)d_in[17];
    const float* pw2     = (const float*)d_in[18];
    const float* pb2     = (const float*)d_in[19];
    float* out = (float*)d_out;

    const int SM_LIFT = 28096 * 4;                                    // 112384
    const int SM_DFT1 = (16640 + 512 + 6144 + 1024) * 4;              // 97280
    const int SM_FUSE = 28256 * 4;                                    // 113024
    const int SM_PROJ = 21888 * 4;                                    // 87552

    cudaFuncSetAttribute(k_lift, cudaFuncAttributeMaxDynamicSharedMemorySize, SM_LIFT);
    cudaFuncSetAttribute(k_dft1, cudaFuncAttributeMaxDynamicSharedMemorySize, SM_DFT1);
    cudaFuncSetAttribute(k_fuse, cudaFuncAttributeMaxDynamicSharedMemorySize, SM_FUSE);
    cudaFuncSetAttribute(k_proj, cudaFuncAttributeMaxDynamicSharedMemorySize, SM_PROJ);

    k_reorder<<<224, 256>>>(lift_w2, pw1, skw, mw1, mw2);
    k_lift<<<BB*HH*2, 256, SM_LIFT>>>(x, lift_w1, lift_b1, lift_b2);
    k_dft1<<<BB*HH, 256, SM_DFT1>>>();           // once, after lift
    for (int l = 0; l < 4; l++){
        k_dft2 <<<BB*NKY*NKX, 256>>>();
        k_mix  <<<NKX*NKY, 256>>>(l, swr1, swi1, swr2, swi2);
        k_idft1<<<BB*NKY*8, 256>>>();
        k_fuse <<<BB*HH, 256, SM_FUSE>>>(l, (l < 3) ? 1 : 0,
                                         gate, spec_b, mb1, mb2);
    }
    k_proj<<<BB*HH*4, 256, SM_PROJ>>>(x, pb1, pw2, pb2, out);
}